// round 6
// baseline (speedup 1.0000x reference)
#include <cuda_runtime.h>
#include <math.h>
#include <stdint.h>

#define HEADS   16
#define DH      64
#define BLK     16
#define SEQ     2048
#define NB      128
#define BATCH   2
#define DIM     1024
#define N3      3072
#define MROWS   (BATCH * SEQ)   // 4096

// ---------------------------------------------------------------------------
// Scratch (device globals — no allocations anywhere)
// ---------------------------------------------------------------------------
__device__ float g_qkv[(size_t)MROWS * N3];    // 4096 x 3072
__device__ float g_att[(size_t)MROWS * DIM];   // 4096 x 1024 (tf32-rounded at write)
__device__ float g_xr[(size_t)MROWS * DIM];    // 4096 x 1024 (tf32-rounded x)
__device__ float g_wqkvT[(size_t)N3 * DIM];    // 3072 x 1024 (K-major, tf32-rounded)
__device__ float g_woutT[(size_t)DIM * DIM];   // 1024 x 1024

__device__ __forceinline__ float to_tf32(float x) {
    uint32_t u;
    asm("cvt.rna.tf32.f32 %0, %1;" : "=r"(u) : "f"(x));
    return __uint_as_float(u);
}

// mma.sync m16n8k8 tf32: D = A*B + D  (fp32 accum)
__device__ __forceinline__ void mma_tf32(float* c, const uint32_t* a, const uint32_t* b) {
    asm volatile(
        "mma.sync.aligned.m16n8k8.row.col.f32.tf32.tf32.f32 "
        "{%0,%1,%2,%3}, {%4,%5,%6,%7}, {%8,%9}, {%0,%1,%2,%3};"
        : "+f"(c[0]), "+f"(c[1]), "+f"(c[2]), "+f"(c[3])
        : "r"(a[0]), "r"(a[1]), "r"(a[2]), "r"(a[3]), "r"(b[0]), "r"(b[1]));
}

__device__ __forceinline__ uint32_t smem_u32(const void* p) {
    uint32_t a;
    asm("{ .reg .u64 t; cvta.to.shared.u64 t, %1; cvt.u32.u64 %0, t; }" : "=r"(a) : "l"(p));
    return a;
}
__device__ __forceinline__ void cpa16(uint32_t s, const void* g) {
    asm volatile("cp.async.cg.shared.global [%0], [%1], 16;" :: "r"(s), "l"(g));
}
#define CP_COMMIT() asm volatile("cp.async.commit_group;" ::: "memory")
#define CP_WAIT1()  asm volatile("cp.async.wait_group 1;" ::: "memory")

// ---------------------------------------------------------------------------
// Elementwise tf32 round (for x)
// ---------------------------------------------------------------------------
__global__ void __launch_bounds__(256)
round_tf32(const float* __restrict__ src, float* __restrict__ dst, int n4)
{
    int i = blockIdx.x * 256 + threadIdx.x;
    if (i < n4) {
        float4 v = ((const float4*)src)[i];
        v.x = to_tf32(v.x); v.y = to_tf32(v.y);
        v.z = to_tf32(v.z); v.w = to_tf32(v.w);
        ((float4*)dst)[i] = v;
    }
}

// ---------------------------------------------------------------------------
// Transpose + tf32 round: dst[C x R] = tf32(src[R x C])^T
// ---------------------------------------------------------------------------
__global__ void __launch_bounds__(256)
transpose_tf32(const float* __restrict__ src, float* __restrict__ dst, int R, int C)
{
    __shared__ float t[32][33];
    int c0 = blockIdx.x * 32, r0 = blockIdx.y * 32;
    int x = threadIdx.x, y = threadIdx.y;  // block (32, 8)
    #pragma unroll
    for (int i = 0; i < 32; i += 8)
        t[y + i][x] = to_tf32(src[(size_t)(r0 + y + i) * C + c0 + x]);
    __syncthreads();
    #pragma unroll
    for (int i = 0; i < 32; i += 8)
        dst[(size_t)(c0 + y + i) * R + r0 + x] = t[x][y + i];
}

// ---------------------------------------------------------------------------
// cp.async-pipelined mma.sync tf32 GEMM: C = A @ Bt^T (+bias).
// A, Bt MUST be pre-rounded to tf32. 128x128 tile, BK=32, 3 stages.
// Fragment-ordered smem (direct cp.async, zero shuffling):
//   A stage: [mt(8)][ks(4)][reg(4)][lane(32)]  = 4096 floats (16 KB)
//   B stage: [nt(16)][ks(4)][reg(2)][lane(32)] = 4096 floats (16 KB)
// A k-contiguous global float4 maps to 4 consecutive lanes, one reg -> 16B.
// ---------------------------------------------------------------------------
#define STAGES 3
#define GEMM_SMEM (STAGES * 32768)

template<bool BIAS>
__global__ void __launch_bounds__(256, 2)
gemm_cp(const float* __restrict__ A, const float* __restrict__ Bt,
        const float* __restrict__ bias, float* __restrict__ C, int N, int K)
{
    extern __shared__ float sm[];   // [stage][A 4096 | B 4096]
    const uint32_t smb = smem_u32(sm);

    const int tid = threadIdx.x;
    const int wid = tid >> 5;
    const int lid = tid & 31;
    const int wr  = wid >> 2;       // 0..1
    const int wc  = wid & 3;        // 0..3

    const int nchunk = K >> 5;      // 32

    const float* Ab = A  + (size_t)(blockIdx.y * 128) * K;
    const float* Bb = Bt + (size_t)(blockIdx.x * 128) * K;

    // Per-thread copy slots: 4 for A, 4 for B. t = tid + i*256 -> (row, kq)
    uint32_t adst[4], bdst[4];      // smem float-offsets within a stage
    const float* agsrc[4];
    const float* bgsrc[4];
    #pragma unroll
    for (int i = 0; i < 4; i++) {
        int t   = tid + i * 256;
        int row = t >> 3;           // 0..127
        int kq  = t & 7;            // k-quad (4 floats)
        int ks  = kq >> 1;
        // A: reg = rowhalf | khalf<<1
        int regA = ((row >> 3) & 1) | ((kq & 1) << 1);
        int mt   = row >> 4;
        adst[i]  = (((mt * 4 + ks) * 4 + regA) * 32 + (row & 7) * 4);
        agsrc[i] = Ab + (size_t)row * K + kq * 4;
        // B: reg = khalf
        int regB = kq & 1;
        int nt   = row >> 3;        // n index = row (0..127), nt = n>>3
        bdst[i]  = 4096 + (((nt * 4 + ks) * 2 + regB) * 32 + (row & 7) * 4);
        bgsrc[i] = Bb + (size_t)row * K + kq * 4;
    }

    auto issue = [&](int c, int s) {
        uint32_t sb = smb + s * 32768;
        #pragma unroll
        for (int i = 0; i < 4; i++) {
            cpa16(sb + adst[i] * 4, agsrc[i] + c * 32);
            cpa16(sb + bdst[i] * 4, bgsrc[i] + c * 32);
        }
    };

    float acc[4][4][4];
    #pragma unroll
    for (int i = 0; i < 4; i++)
        #pragma unroll
        for (int j = 0; j < 4; j++)
            #pragma unroll
            for (int r = 0; r < 4; r++) acc[i][j][r] = 0.0f;

    // Prologue: stages 0, 1
    issue(0, 0); CP_COMMIT();
    issue(1, 1); CP_COMMIT();

    for (int c = 0; c < nchunk; c++) {
        const int s = c % STAGES;
        CP_WAIT1();
        __syncthreads();

        const int cn = c + STAGES - 1;
        if (cn < nchunk) issue(cn, cn % STAGES);
        CP_COMMIT();

        const float* sA = sm + s * 8192;
        const float* sB = sA + 4096;
        #pragma unroll
        for (int ks = 0; ks < 4; ks++) {
            uint32_t afr[4][4];
            uint32_t bfr[4][2];
            #pragma unroll
            for (int mt = 0; mt < 4; mt++)
                #pragma unroll
                for (int r = 0; r < 4; r++)
                    afr[mt][r] = __float_as_uint(
                        sA[(((wr * 4 + mt) * 4 + ks) * 4 + r) * 32 + lid]);
            #pragma unroll
            for (int nt = 0; nt < 4; nt++)
                #pragma unroll
                for (int r = 0; r < 2; r++)
                    bfr[nt][r] = __float_as_uint(
                        sB[(((wc * 4 + nt) * 4 + ks) * 2 + r) * 32 + lid]);
            #pragma unroll
            for (int mt = 0; mt < 4; mt++)
                #pragma unroll
                for (int nt = 0; nt < 4; nt++)
                    mma_tf32(acc[mt][nt], afr[mt], bfr[nt]);
        }
    }

    const int r0 = blockIdx.y * 128 + wr * 64 + (lid >> 2);
    const int c0 = blockIdx.x * 128 + wc * 32 + (lid & 3) * 2;
    #pragma unroll
    for (int mt = 0; mt < 4; mt++) {
        #pragma unroll
        for (int nt = 0; nt < 4; nt++) {
            int row = r0 + mt * 16;
            int col = c0 + nt * 8;
            float2 v0 = make_float2(acc[mt][nt][0], acc[mt][nt][1]);
            float2 v1 = make_float2(acc[mt][nt][2], acc[mt][nt][3]);
            if (BIAS) {
                float b0 = bias[col], b1 = bias[col + 1];
                v0.x += b0; v0.y += b1;
                v1.x += b0; v1.y += b1;
            }
            *(float2*)(C + (size_t)row * N + col)       = v0;
            *(float2*)(C + (size_t)(row + 8) * N + col) = v1;
        }
    }
}

// ---------------------------------------------------------------------------
// mma.sync flash attention, warp-split-K (round-4 proven; output tf32-rounded)
// ---------------------------------------------------------------------------
__global__ void __launch_bounds__(128)
attn_mma(const float* __restrict__ qkv, const void* __restrict__ layout,
         float* __restrict__ att)
{
    __shared__ __align__(16) float wbuf[4][2464];
    __shared__ int list[NB];
    __shared__ int wcnt[4];

    const int qb = blockIdx.x, h = blockIdx.y, bz = blockIdx.z;
    const int tid = threadIdx.x;
    const int wid = tid >> 5;
    const int lid = tid & 31;
    const int r4  = lid >> 2;
    const int c4  = lid & 3;

    const int probe = __ldg(&((const int*)layout)[32]);
    const bool u8 = (probe == 257);
    const int kb0 = wid * 32 + lid;
    bool ok = (kb0 <= qb) &&
              (u8 ? (((const unsigned char*)layout)[qb * NB + kb0] != 0)
                  : (((const int*)layout)[qb * NB + kb0] != 0));
    unsigned bmask = __ballot_sync(0xffffffffu, ok);
    if (lid == 0) wcnt[wid] = __popc(bmask);
    __syncthreads();
    int pre = 0;
    #pragma unroll
    for (int w = 0; w < 4; w++) pre += (w < wid) ? wcnt[w] : 0;
    const int total = wcnt[0] + wcnt[1] + wcnt[2] + wcnt[3];
    if (ok) list[pre + __popc(bmask & ((1u << lid) - 1u))] = kb0;
    __syncthreads();

    const float scale = 0.125f;
    const float* qp = qkv + (size_t)(bz * SEQ + qb * 16) * N3 + h * 64;
    uint32_t qa[8][4];
    #pragma unroll
    for (int ks = 0; ks < 8; ks++) {
        qa[ks][0] = __float_as_uint(to_tf32(qp[(size_t)r4 * N3       + ks * 8 + c4]     * scale));
        qa[ks][1] = __float_as_uint(to_tf32(qp[(size_t)(r4 + 8) * N3 + ks * 8 + c4]     * scale));
        qa[ks][2] = __float_as_uint(to_tf32(qp[(size_t)r4 * N3       + ks * 8 + c4 + 4] * scale));
        qa[ks][3] = __float_as_uint(to_tf32(qp[(size_t)(r4 + 8) * N3 + ks * 8 + c4 + 4] * scale));
    }

    float o[8][4];
    #pragma unroll
    for (int nt = 0; nt < 8; nt++)
        #pragma unroll
        for (int r = 0; r < 4; r++) o[nt][r] = 0.0f;
    float m_lo = -INFINITY, m_hi = -INFINITY, l_lo = 0.0f, l_hi = 0.0f;

    float* Ks = wbuf[wid];
    float* Vs = Ks + 1088;
    float* Ps = Ks + 2176;

    for (int it = wid; it < total; it += 4) {
        const int kb = list[it];
        const float* kvb = qkv + (size_t)(bz * SEQ + kb * 16) * N3 + h * 64;

        #pragma unroll
        for (int j = 0; j < 8; j++) {
            int f = lid + j * 32;
            int row = f >> 4, c16 = f & 15;
            float4 k4 = *(const float4*)(kvb + (size_t)row * N3 + 1024 + c16 * 4);
            float* kd = Ks + row * 68 + c16 * 4;
            kd[0] = to_tf32(k4.x); kd[1] = to_tf32(k4.y);
            kd[2] = to_tf32(k4.z); kd[3] = to_tf32(k4.w);
            float4 v4 = *(const float4*)(kvb + (size_t)row * N3 + 2048 + c16 * 4);
            float* vd = Vs + row * 68 + c16 * 4;
            vd[0] = to_tf32(v4.x); vd[1] = to_tf32(v4.y);
            vd[2] = to_tf32(v4.z); vd[3] = to_tf32(v4.w);
        }
        __syncwarp();

        float s0[4] = {0.f, 0.f, 0.f, 0.f};
        float s1[4] = {0.f, 0.f, 0.f, 0.f};
        #pragma unroll
        for (int ks = 0; ks < 8; ks++) {
            uint32_t b0[2], b1[2];
            b0[0] = __float_as_uint(Ks[r4 * 68 + ks * 8 + c4]);
            b0[1] = __float_as_uint(Ks[r4 * 68 + ks * 8 + c4 + 4]);
            b1[0] = __float_as_uint(Ks[(8 + r4) * 68 + ks * 8 + c4]);
            b1[1] = __float_as_uint(Ks[(8 + r4) * 68 + ks * 8 + c4 + 4]);
            mma_tf32(s0, qa[ks], b0);
            mma_tf32(s1, qa[ks], b1);
        }

        if (kb == qb) {
            const int cA = 2 * c4, cB = 2 * c4 + 1;
            if (cA > r4)     s0[0] = -1e30f;
            if (cB > r4)     s0[1] = -1e30f;
            if (cA > r4 + 8) s0[2] = -1e30f;
            if (cB > r4 + 8) s0[3] = -1e30f;
            if (cA + 8 > r4)     s1[0] = -1e30f;
            if (cB + 8 > r4)     s1[1] = -1e30f;
            if (cA + 8 > r4 + 8) s1[2] = -1e30f;
            if (cB + 8 > r4 + 8) s1[3] = -1e30f;
        }

        float lo = fmaxf(fmaxf(s0[0], s0[1]), fmaxf(s1[0], s1[1]));
        float hi = fmaxf(fmaxf(s0[2], s0[3]), fmaxf(s1[2], s1[3]));
        lo = fmaxf(lo, __shfl_xor_sync(0xffffffffu, lo, 1));
        lo = fmaxf(lo, __shfl_xor_sync(0xffffffffu, lo, 2));
        hi = fmaxf(hi, __shfl_xor_sync(0xffffffffu, hi, 1));
        hi = fmaxf(hi, __shfl_xor_sync(0xffffffffu, hi, 2));

        const float mlo = fmaxf(m_lo, lo);
        const float mhi = fmaxf(m_hi, hi);
        const float alo = __expf(m_lo - mlo);
        const float ahi = __expf(m_hi - mhi);

        float p00 = __expf(s0[0] - mlo), p01 = __expf(s0[1] - mlo);
        float p10 = __expf(s1[0] - mlo), p11 = __expf(s1[1] - mlo);
        float p02 = __expf(s0[2] - mhi), p03 = __expf(s0[3] - mhi);
        float p12 = __expf(s1[2] - mhi), p13 = __expf(s1[3] - mhi);

        float slo = p00 + p01 + p10 + p11;
        float shi = p02 + p03 + p12 + p13;
        slo += __shfl_xor_sync(0xffffffffu, slo, 1);
        slo += __shfl_xor_sync(0xffffffffu, slo, 2);
        shi += __shfl_xor_sync(0xffffffffu, shi, 1);
        shi += __shfl_xor_sync(0xffffffffu, shi, 2);

        l_lo = l_lo * alo + slo;
        l_hi = l_hi * ahi + shi;
        m_lo = mlo; m_hi = mhi;

        #pragma unroll
        for (int nt = 0; nt < 8; nt++) {
            o[nt][0] *= alo; o[nt][1] *= alo;
            o[nt][2] *= ahi; o[nt][3] *= ahi;
        }

        *(float2*)&Ps[r4 * 18 + 2 * c4]           = make_float2(to_tf32(p00), to_tf32(p01));
        *(float2*)&Ps[r4 * 18 + 8 + 2 * c4]       = make_float2(to_tf32(p10), to_tf32(p11));
        *(float2*)&Ps[(r4 + 8) * 18 + 2 * c4]     = make_float2(to_tf32(p02), to_tf32(p03));
        *(float2*)&Ps[(r4 + 8) * 18 + 8 + 2 * c4] = make_float2(to_tf32(p12), to_tf32(p13));
        __syncwarp();

        uint32_t pa0[4], pa1[4];
        pa0[0] = __float_as_uint(Ps[r4 * 18 + c4]);
        pa0[1] = __float_as_uint(Ps[(r4 + 8) * 18 + c4]);
        pa0[2] = __float_as_uint(Ps[r4 * 18 + c4 + 4]);
        pa0[3] = __float_as_uint(Ps[(r4 + 8) * 18 + c4 + 4]);
        pa1[0] = __float_as_uint(Ps[r4 * 18 + 8 + c4]);
        pa1[1] = __float_as_uint(Ps[(r4 + 8) * 18 + 8 + c4]);
        pa1[2] = __float_as_uint(Ps[r4 * 18 + 8 + c4 + 4]);
        pa1[3] = __float_as_uint(Ps[(r4 + 8) * 18 + 8 + c4 + 4]);

        #pragma unroll
        for (int nt = 0; nt < 8; nt++) {
            uint32_t b0[2], b1[2];
            b0[0] = __float_as_uint(Vs[c4 * 68 + nt * 8 + r4]);
            b0[1] = __float_as_uint(Vs[(c4 + 4) * 68 + nt * 8 + r4]);
            mma_tf32(o[nt], pa0, b0);
            b1[0] = __float_as_uint(Vs[(8 + c4) * 68 + nt * 8 + r4]);
            b1[1] = __float_as_uint(Vs[(12 + c4) * 68 + nt * 8 + r4]);
            mma_tf32(o[nt], pa1, b1);
        }
        __syncwarp();
    }

    float* Os = wbuf[wid];
    #pragma unroll
    for (int nt = 0; nt < 8; nt++) {
        *(float2*)&Os[r4 * 66 + nt * 8 + 2 * c4]       = make_float2(o[nt][0], o[nt][1]);
        *(float2*)&Os[(r4 + 8) * 66 + nt * 8 + 2 * c4] = make_float2(o[nt][2], o[nt][3]);
    }
    if (c4 == 0) {
        Os[1056 + r4]     = m_lo;
        Os[1056 + 8 + r4] = m_hi;
        Os[1072 + r4]     = l_lo;
        Os[1072 + 8 + r4] = l_hi;
    }
    __syncthreads();

    {
        const int row = tid >> 3;
        const int d0  = (tid & 7) * 8;
        float mw[4], lw[4];
        float M = -INFINITY;
        #pragma unroll
        for (int w = 0; w < 4; w++) {
            mw[w] = wbuf[w][1056 + row];
            lw[w] = wbuf[w][1072 + row];
            M = fmaxf(M, mw[w]);
        }
        float L = 0.0f, wgt[4];
        #pragma unroll
        for (int w = 0; w < 4; w++) {
            wgt[w] = __expf(mw[w] - M);
            L += wgt[w] * lw[w];
        }
        const float inv = 1.0f / L;
        float out[8];
        #pragma unroll
        for (int j = 0; j < 8; j++) out[j] = 0.0f;
        #pragma unroll
        for (int w = 0; w < 4; w++) {
            const float g = wgt[w];
            const float* op = &wbuf[w][row * 66 + d0];
            #pragma unroll
            for (int j = 0; j < 8; j++) out[j] += g * op[j];
        }
        float* ap = att + (size_t)(bz * SEQ + qb * 16 + row) * DIM + h * 64 + d0;
        // tf32-round so the out-projection (cp.async path) sees RNA-rounded A
        float4 v0 = make_float4(to_tf32(out[0] * inv), to_tf32(out[1] * inv),
                                to_tf32(out[2] * inv), to_tf32(out[3] * inv));
        float4 v1 = make_float4(to_tf32(out[4] * inv), to_tf32(out[5] * inv),
                                to_tf32(out[6] * inv), to_tf32(out[7] * inv));
        *(float4*)(ap)     = v0;
        *(float4*)(ap + 4) = v1;
    }
}

// ---------------------------------------------------------------------------
extern "C" void kernel_launch(void* const* d_in, const int* in_sizes, int n_in,
                              void* d_out, int out_size)
{
    const float* x      = (const float*)d_in[0];
    const float* w_qkv  = (const float*)d_in[1];
    const float* w_out  = (const float*)d_in[2];
    const float* b_out  = (const float*)d_in[3];
    const void*  layout = d_in[4];
    float* out = (float*)d_out;

    void* p;
    cudaGetSymbolAddress(&p, g_qkv);   float* qkv   = (float*)p;
    cudaGetSymbolAddress(&p, g_att);   float* att   = (float*)p;
    cudaGetSymbolAddress(&p, g_xr);    float* xr    = (float*)p;
    cudaGetSymbolAddress(&p, g_wqkvT); float* wqkvT = (float*)p;
    cudaGetSymbolAddress(&p, g_woutT); float* woutT = (float*)p;

    cudaFuncSetAttribute(gemm_cp<false>,
                         cudaFuncAttributeMaxDynamicSharedMemorySize, GEMM_SMEM);
    cudaFuncSetAttribute(gemm_cp<true>,
                         cudaFuncAttributeMaxDynamicSharedMemorySize, GEMM_SMEM);

    // 0) Preprocess: round x; transpose+round weights
    round_tf32<<<(MROWS * DIM / 4 + 255) / 256, 256>>>(x, xr, MROWS * DIM / 4);
    transpose_tf32<<<dim3(N3 / 32, DIM / 32), dim3(32, 8)>>>(w_qkv, wqkvT, DIM, N3);
    transpose_tf32<<<dim3(DIM / 32, DIM / 32), dim3(32, 8)>>>(w_out, woutT, DIM, DIM);

    // 1) QKV projection: [4096,1024] @ [1024,3072]
    gemm_cp<false><<<dim3(N3 / 128, MROWS / 128), 256, GEMM_SMEM>>>(
        xr, wqkvT, nullptr, qkv, N3, DIM);

    // 2) Block-sparse flash attention (mma.sync)
    attn_mma<<<dim3(NB, HEADS, BATCH), 128>>>(qkv, layout, att);

    // 3) Output projection + bias
    gemm_cp<true><<<dim3(DIM / 128, MROWS / 128), 256, GEMM_SMEM>>>(
        att, woutT, b_out, out, DIM, DIM);
}

// round 9
// speedup vs baseline: 1.3520x; 1.3520x over previous
#include <cuda_runtime.h>
#include <math.h>
#include <stdint.h>

#define HEADS   16
#define DH      64
#define BLK     16
#define SEQ     2048
#define NB      128
#define BATCH   2
#define DIM     1024
#define N3      3072
#define MROWS   (BATCH * SEQ)   // 4096

// ---------------------------------------------------------------------------
// Scratch (device globals — no allocations anywhere)
// ---------------------------------------------------------------------------
__device__ float g_qkv[(size_t)MROWS * N3];    // 4096 x 3072
__device__ float g_att[(size_t)MROWS * DIM];   // 4096 x 1024 (tf32-rounded at write)
__device__ float g_xr[(size_t)MROWS * DIM];    // 4096 x 1024 (tf32-rounded x)
__device__ float g_wqkvT[(size_t)N3 * DIM];    // 3072 x 1024 (K-major, tf32-rounded)
__device__ float g_woutT[(size_t)DIM * DIM];   // 1024 x 1024

__device__ __forceinline__ float to_tf32(float x) {
    uint32_t u;
    asm("cvt.rna.tf32.f32 %0, %1;" : "=r"(u) : "f"(x));
    return __uint_as_float(u);
}

// mma.sync m16n8k8 tf32: D = A*B + D  (fp32 accum)
__device__ __forceinline__ void mma_tf32(float* c, const uint32_t* a, const uint32_t* b) {
    asm volatile(
        "mma.sync.aligned.m16n8k8.row.col.f32.tf32.tf32.f32 "
        "{%0,%1,%2,%3}, {%4,%5,%6,%7}, {%8,%9}, {%0,%1,%2,%3};"
        : "+f"(c[0]), "+f"(c[1]), "+f"(c[2]), "+f"(c[3])
        : "r"(a[0]), "r"(a[1]), "r"(a[2]), "r"(a[3]), "r"(b[0]), "r"(b[1]));
}

__device__ __forceinline__ uint32_t smem_u32(const void* p) {
    uint32_t a;
    asm("{ .reg .u64 t; cvta.to.shared.u64 t, %1; cvt.u32.u64 %0, t; }" : "=r"(a) : "l"(p));
    return a;
}
__device__ __forceinline__ void cpa16(uint32_t s, const void* g) {
    asm volatile("cp.async.cg.shared.global [%0], [%1], 16;" :: "r"(s), "l"(g));
}
#define CP_COMMIT() asm volatile("cp.async.commit_group;" ::: "memory")
#define CP_WAIT1()  asm volatile("cp.async.wait_group 1;" ::: "memory")

__device__ __forceinline__ void ldsm_x4(uint32_t* r, uint32_t a) {
    asm volatile("ldmatrix.sync.aligned.m8n8.x4.shared.b16 {%0,%1,%2,%3}, [%4];"
                 : "=r"(r[0]), "=r"(r[1]), "=r"(r[2]), "=r"(r[3]) : "r"(a));
}

// ---------------------------------------------------------------------------
// Elementwise tf32 round (for x)
// ---------------------------------------------------------------------------
__global__ void __launch_bounds__(256)
round_tf32(const float* __restrict__ src, float* __restrict__ dst, int n4)
{
    int i = blockIdx.x * 256 + threadIdx.x;
    if (i < n4) {
        float4 v = ((const float4*)src)[i];
        v.x = to_tf32(v.x); v.y = to_tf32(v.y);
        v.z = to_tf32(v.z); v.w = to_tf32(v.w);
        ((float4*)dst)[i] = v;
    }
}

// ---------------------------------------------------------------------------
// Transpose + tf32 round: dst[C x R] = tf32(src[R x C])^T
// ---------------------------------------------------------------------------
__global__ void __launch_bounds__(256)
transpose_tf32(const float* __restrict__ src, float* __restrict__ dst, int R, int C)
{
    __shared__ float t[32][33];
    int c0 = blockIdx.x * 32, r0 = blockIdx.y * 32;
    int x = threadIdx.x, y = threadIdx.y;  // block (32, 8)
    #pragma unroll
    for (int i = 0; i < 32; i += 8)
        t[y + i][x] = to_tf32(src[(size_t)(r0 + y + i) * C + c0 + x]);
    __syncthreads();
    #pragma unroll
    for (int i = 0; i < 32; i += 8)
        dst[(size_t)(c0 + y + i) * R + r0 + x] = t[x][y + i];
}

// ---------------------------------------------------------------------------
// cp.async + ldmatrix tf32 GEMM: C = A @ Bt^T (+bias). A, Bt pre-rounded tf32.
// 128x128 tile, BK=32, 3 stages. Smem per stage: A 16 KB + B 16 KB,
// row-major [row(128)][kq(8)] of 16B quads with XOR swizzle kq ^= row&7.
// Fragments via ldmatrix.x4.b16 (exact tf32 m16n8k8 layout), k-step
// register double-buffered so LDSM latency hides under MMAs.
// ---------------------------------------------------------------------------
#define STAGES 3
#define GEMM_SMEM (STAGES * 32768)

template<bool BIAS>
__global__ void __launch_bounds__(256, 2)
gemm_lds(const float* __restrict__ A, const float* __restrict__ Bt,
         const float* __restrict__ bias, float* __restrict__ C, int N, int K)
{
    extern __shared__ float sm[];
    const uint32_t smb = smem_u32(sm);

    const int tid = threadIdx.x;
    const int wid = tid >> 5;
    const int lid = tid & 31;
    const int wr  = wid >> 2;       // 0..1
    const int wc  = wid & 3;        // 0..3

    const int nchunk = K >> 5;      // 32

    // ---- copy mapping: thread -> (row = tid>>1, kq = (tid&1)*4 + j) ----
    const int crow = tid >> 1;
    const int ckq0 = (tid & 1) * 4;
    const float* agp = A  + (size_t)(blockIdx.y * 128 + crow) * K + ckq0 * 4;
    const float* bgp = Bt + (size_t)(blockIdx.x * 128 + crow) * K + ckq0 * 4;
    const uint32_t crow_off = (uint32_t)crow * 128;   // bytes (32 floats/row)
    const uint32_t csw = (uint32_t)(crow & 7);

    auto issue = [&](int c, int s) {
        const uint32_t ab = smb + s * 32768 + crow_off;
        const uint32_t bb = ab + 16384;
        #pragma unroll
        for (int j = 0; j < 4; j++) {
            uint32_t off = (uint32_t)((ckq0 + j) ^ csw) << 4;
            cpa16(ab + off, agp + c * 32 + j * 4);
            cpa16(bb + off, bgp + c * 32 + j * 4);
        }
    };

    // ---- ldmatrix address components ----
    const uint32_t a_row  = (uint32_t)(lid & 15);
    const uint32_t a_kqb  = (uint32_t)(lid >> 4);
    const uint32_t b_row  = (uint32_t)(wc * 32 + (lid & 7) + ((lid >> 4) << 3));
    const uint32_t b_kqb  = (uint32_t)((lid >> 3) & 1);
    const uint32_t a_sw   = (uint32_t)(lid & 7);      // row&7 for both A and B rows

    float acc[4][4][4];
    #pragma unroll
    for (int i = 0; i < 4; i++)
        #pragma unroll
        for (int j = 0; j < 4; j++)
            #pragma unroll
            for (int r = 0; r < 4; r++) acc[i][j][r] = 0.0f;

    issue(0, 0); CP_COMMIT();
    issue(1, 1); CP_COMMIT();

    uint32_t afr[2][4][4];
    uint32_t bfr[2][2][4];

    for (int c = 0; c < nchunk; c++) {
        const int s = c % STAGES;
        CP_WAIT1();
        __syncthreads();

        const int cn = c + STAGES - 1;
        if (cn < nchunk) issue(cn, cn % STAGES);
        CP_COMMIT();

        const uint32_t abase = smb + s * 32768 + (wr * 64 + a_row) * 128;
        const uint32_t bbase = abase - (wr * 64 + a_row) * 128 + 16384 + b_row * 128;

        // load ks=0 fragments into buffer 0
        #pragma unroll
        for (int mt = 0; mt < 4; mt++)
            ldsm_x4(afr[0][mt], abase + mt * 2048 + (((a_kqb) ^ a_sw) << 4));
        #pragma unroll
        for (int np = 0; np < 2; np++)
            ldsm_x4(bfr[0][np], bbase + np * 2048 + (((b_kqb) ^ a_sw) << 4));

        #pragma unroll
        for (int ks = 0; ks < 4; ks++) {
            const int cur = ks & 1, nxt = cur ^ 1;
            if (ks < 3) {
                const uint32_t kq_a = (uint32_t)(2 * (ks + 1)) + a_kqb;
                const uint32_t kq_b = (uint32_t)(2 * (ks + 1)) + b_kqb;
                #pragma unroll
                for (int mt = 0; mt < 4; mt++)
                    ldsm_x4(afr[nxt][mt], abase + mt * 2048 + ((kq_a ^ a_sw) << 4));
                #pragma unroll
                for (int np = 0; np < 2; np++)
                    ldsm_x4(bfr[nxt][np], bbase + np * 2048 + ((kq_b ^ a_sw) << 4));
            }
            #pragma unroll
            for (int mt = 0; mt < 4; mt++)
                #pragma unroll
                for (int nt = 0; nt < 4; nt++)
                    mma_tf32(acc[mt][nt], afr[cur][mt], &bfr[cur][nt >> 1][(nt & 1) * 2]);
        }
    }

    const int r0 = blockIdx.y * 128 + wr * 64 + (lid >> 2);
    const int c0 = blockIdx.x * 128 + wc * 32 + (lid & 3) * 2;
    #pragma unroll
    for (int mt = 0; mt < 4; mt++) {
        #pragma unroll
        for (int nt = 0; nt < 4; nt++) {
            int row = r0 + mt * 16;
            int col = c0 + nt * 8;
            float2 v0 = make_float2(acc[mt][nt][0], acc[mt][nt][1]);
            float2 v1 = make_float2(acc[mt][nt][2], acc[mt][nt][3]);
            if (BIAS) {
                float b0 = bias[col], b1 = bias[col + 1];
                v0.x += b0; v0.y += b1;
                v1.x += b0; v1.y += b1;
            }
            *(float2*)(C + (size_t)row * N + col)       = v0;
            *(float2*)(C + (size_t)(row + 8) * N + col) = v1;
        }
    }
}

// ---------------------------------------------------------------------------
// mma.sync flash attention, warp-split-K (round-4 proven; output tf32-rounded)
// ---------------------------------------------------------------------------
__global__ void __launch_bounds__(128)
attn_mma(const float* __restrict__ qkv, const void* __restrict__ layout,
         float* __restrict__ att)
{
    __shared__ __align__(16) float wbuf[4][2464];
    __shared__ int list[NB];
    __shared__ int wcnt[4];

    const int qb = blockIdx.x, h = blockIdx.y, bz = blockIdx.z;
    const int tid = threadIdx.x;
    const int wid = tid >> 5;
    const int lid = tid & 31;
    const int r4  = lid >> 2;
    const int c4  = lid & 3;

    const int probe = __ldg(&((const int*)layout)[32]);
    const bool u8 = (probe == 257);
    const int kb0 = wid * 32 + lid;
    bool ok = (kb0 <= qb) &&
              (u8 ? (((const unsigned char*)layout)[qb * NB + kb0] != 0)
                  : (((const int*)layout)[qb * NB + kb0] != 0));
    unsigned bmask = __ballot_sync(0xffffffffu, ok);
    if (lid == 0) wcnt[wid] = __popc(bmask);
    __syncthreads();
    int pre = 0;
    #pragma unroll
    for (int w = 0; w < 4; w++) pre += (w < wid) ? wcnt[w] : 0;
    const int total = wcnt[0] + wcnt[1] + wcnt[2] + wcnt[3];
    if (ok) list[pre + __popc(bmask & ((1u << lid) - 1u))] = kb0;
    __syncthreads();

    const float scale = 0.125f;
    const float* qp = qkv + (size_t)(bz * SEQ + qb * 16) * N3 + h * 64;
    uint32_t qa[8][4];
    #pragma unroll
    for (int ks = 0; ks < 8; ks++) {
        qa[ks][0] = __float_as_uint(to_tf32(qp[(size_t)r4 * N3       + ks * 8 + c4]     * scale));
        qa[ks][1] = __float_as_uint(to_tf32(qp[(size_t)(r4 + 8) * N3 + ks * 8 + c4]     * scale));
        qa[ks][2] = __float_as_uint(to_tf32(qp[(size_t)r4 * N3       + ks * 8 + c4 + 4] * scale));
        qa[ks][3] = __float_as_uint(to_tf32(qp[(size_t)(r4 + 8) * N3 + ks * 8 + c4 + 4] * scale));
    }

    float o[8][4];
    #pragma unroll
    for (int nt = 0; nt < 8; nt++)
        #pragma unroll
        for (int r = 0; r < 4; r++) o[nt][r] = 0.0f;
    float m_lo = -INFINITY, m_hi = -INFINITY, l_lo = 0.0f, l_hi = 0.0f;

    float* Ks = wbuf[wid];
    float* Vs = Ks + 1088;
    float* Ps = Ks + 2176;

    for (int it = wid; it < total; it += 4) {
        const int kb = list[it];
        const float* kvb = qkv + (size_t)(bz * SEQ + kb * 16) * N3 + h * 64;

        #pragma unroll
        for (int j = 0; j < 8; j++) {
            int f = lid + j * 32;
            int row = f >> 4, c16 = f & 15;
            float4 k4 = *(const float4*)(kvb + (size_t)row * N3 + 1024 + c16 * 4);
            float* kd = Ks + row * 68 + c16 * 4;
            kd[0] = to_tf32(k4.x); kd[1] = to_tf32(k4.y);
            kd[2] = to_tf32(k4.z); kd[3] = to_tf32(k4.w);
            float4 v4 = *(const float4*)(kvb + (size_t)row * N3 + 2048 + c16 * 4);
            float* vd = Vs + row * 68 + c16 * 4;
            vd[0] = to_tf32(v4.x); vd[1] = to_tf32(v4.y);
            vd[2] = to_tf32(v4.z); vd[3] = to_tf32(v4.w);
        }
        __syncwarp();

        float s0[4] = {0.f, 0.f, 0.f, 0.f};
        float s1[4] = {0.f, 0.f, 0.f, 0.f};
        #pragma unroll
        for (int ks = 0; ks < 8; ks++) {
            uint32_t b0[2], b1[2];
            b0[0] = __float_as_uint(Ks[r4 * 68 + ks * 8 + c4]);
            b0[1] = __float_as_uint(Ks[r4 * 68 + ks * 8 + c4 + 4]);
            b1[0] = __float_as_uint(Ks[(8 + r4) * 68 + ks * 8 + c4]);
            b1[1] = __float_as_uint(Ks[(8 + r4) * 68 + ks * 8 + c4 + 4]);
            mma_tf32(s0, qa[ks], b0);
            mma_tf32(s1, qa[ks], b1);
        }

        if (kb == qb) {
            const int cA = 2 * c4, cB = 2 * c4 + 1;
            if (cA > r4)     s0[0] = -1e30f;
            if (cB > r4)     s0[1] = -1e30f;
            if (cA > r4 + 8) s0[2] = -1e30f;
            if (cB > r4 + 8) s0[3] = -1e30f;
            if (cA + 8 > r4)     s1[0] = -1e30f;
            if (cB + 8 > r4)     s1[1] = -1e30f;
            if (cA + 8 > r4 + 8) s1[2] = -1e30f;
            if (cB + 8 > r4 + 8) s1[3] = -1e30f;
        }

        float lo = fmaxf(fmaxf(s0[0], s0[1]), fmaxf(s1[0], s1[1]));
        float hi = fmaxf(fmaxf(s0[2], s0[3]), fmaxf(s1[2], s1[3]));
        lo = fmaxf(lo, __shfl_xor_sync(0xffffffffu, lo, 1));
        lo = fmaxf(lo, __shfl_xor_sync(0xffffffffu, lo, 2));
        hi = fmaxf(hi, __shfl_xor_sync(0xffffffffu, hi, 1));
        hi = fmaxf(hi, __shfl_xor_sync(0xffffffffu, hi, 2));

        const float mlo = fmaxf(m_lo, lo);
        const float mhi = fmaxf(m_hi, hi);
        const float alo = __expf(m_lo - mlo);
        const float ahi = __expf(m_hi - mhi);

        float p00 = __expf(s0[0] - mlo), p01 = __expf(s0[1] - mlo);
        float p10 = __expf(s1[0] - mlo), p11 = __expf(s1[1] - mlo);
        float p02 = __expf(s0[2] - mhi), p03 = __expf(s0[3] - mhi);
        float p12 = __expf(s1[2] - mhi), p13 = __expf(s1[3] - mhi);

        float slo = p00 + p01 + p10 + p11;
        float shi = p02 + p03 + p12 + p13;
        slo += __shfl_xor_sync(0xffffffffu, slo, 1);
        slo += __shfl_xor_sync(0xffffffffu, slo, 2);
        shi += __shfl_xor_sync(0xffffffffu, shi, 1);
        shi += __shfl_xor_sync(0xffffffffu, shi, 2);

        l_lo = l_lo * alo + slo;
        l_hi = l_hi * ahi + shi;
        m_lo = mlo; m_hi = mhi;

        #pragma unroll
        for (int nt = 0; nt < 8; nt++) {
            o[nt][0] *= alo; o[nt][1] *= alo;
            o[nt][2] *= ahi; o[nt][3] *= ahi;
        }

        *(float2*)&Ps[r4 * 18 + 2 * c4]           = make_float2(to_tf32(p00), to_tf32(p01));
        *(float2*)&Ps[r4 * 18 + 8 + 2 * c4]       = make_float2(to_tf32(p10), to_tf32(p11));
        *(float2*)&Ps[(r4 + 8) * 18 + 2 * c4]     = make_float2(to_tf32(p02), to_tf32(p03));
        *(float2*)&Ps[(r4 + 8) * 18 + 8 + 2 * c4] = make_float2(to_tf32(p12), to_tf32(p13));
        __syncwarp();

        uint32_t pa0[4], pa1[4];
        pa0[0] = __float_as_uint(Ps[r4 * 18 + c4]);
        pa0[1] = __float_as_uint(Ps[(r4 + 8) * 18 + c4]);
        pa0[2] = __float_as_uint(Ps[r4 * 18 + c4 + 4]);
        pa0[3] = __float_as_uint(Ps[(r4 + 8) * 18 + c4 + 4]);
        pa1[0] = __float_as_uint(Ps[r4 * 18 + 8 + c4]);
        pa1[1] = __float_as_uint(Ps[(r4 + 8) * 18 + 8 + c4]);
        pa1[2] = __float_as_uint(Ps[r4 * 18 + 8 + c4 + 4]);
        pa1[3] = __float_as_uint(Ps[(r4 + 8) * 18 + 8 + c4 + 4]);

        #pragma unroll
        for (int nt = 0; nt < 8; nt++) {
            uint32_t b0[2], b1[2];
            b0[0] = __float_as_uint(Vs[c4 * 68 + nt * 8 + r4]);
            b0[1] = __float_as_uint(Vs[(c4 + 4) * 68 + nt * 8 + r4]);
            mma_tf32(o[nt], pa0, b0);
            b1[0] = __float_as_uint(Vs[(8 + c4) * 68 + nt * 8 + r4]);
            b1[1] = __float_as_uint(Vs[(12 + c4) * 68 + nt * 8 + r4]);
            mma_tf32(o[nt], pa1, b1);
        }
        __syncwarp();
    }

    float* Os = wbuf[wid];
    #pragma unroll
    for (int nt = 0; nt < 8; nt++) {
        *(float2*)&Os[r4 * 66 + nt * 8 + 2 * c4]       = make_float2(o[nt][0], o[nt][1]);
        *(float2*)&Os[(r4 + 8) * 66 + nt * 8 + 2 * c4] = make_float2(o[nt][2], o[nt][3]);
    }
    if (c4 == 0) {
        Os[1056 + r4]     = m_lo;
        Os[1056 + 8 + r4] = m_hi;
        Os[1072 + r4]     = l_lo;
        Os[1072 + 8 + r4] = l_hi;
    }
    __syncthreads();

    {
        const int row = tid >> 3;
        const int d0  = (tid & 7) * 8;
        float mw[4], lw[4];
        float M = -INFINITY;
        #pragma unroll
        for (int w = 0; w < 4; w++) {
            mw[w] = wbuf[w][1056 + row];
            lw[w] = wbuf[w][1072 + row];
            M = fmaxf(M, mw[w]);
        }
        float L = 0.0f, wgt[4];
        #pragma unroll
        for (int w = 0; w < 4; w++) {
            wgt[w] = __expf(mw[w] - M);
            L += wgt[w] * lw[w];
        }
        const float inv = 1.0f / L;
        float out[8];
        #pragma unroll
        for (int j = 0; j < 8; j++) out[j] = 0.0f;
        #pragma unroll
        for (int w = 0; w < 4; w++) {
            const float g = wgt[w];
            const float* op = &wbuf[w][row * 66 + d0];
            #pragma unroll
            for (int j = 0; j < 8; j++) out[j] += g * op[j];
        }
        float* ap = att + (size_t)(bz * SEQ + qb * 16 + row) * DIM + h * 64 + d0;
        float4 v0 = make_float4(to_tf32(out[0] * inv), to_tf32(out[1] * inv),
                                to_tf32(out[2] * inv), to_tf32(out[3] * inv));
        float4 v1 = make_float4(to_tf32(out[4] * inv), to_tf32(out[5] * inv),
                                to_tf32(out[6] * inv), to_tf32(out[7] * inv));
        *(float4*)(ap)     = v0;
        *(float4*)(ap + 4) = v1;
    }
}

// ---------------------------------------------------------------------------
extern "C" void kernel_launch(void* const* d_in, const int* in_sizes, int n_in,
                              void* d_out, int out_size)
{
    const float* x      = (const float*)d_in[0];
    const float* w_qkv  = (const float*)d_in[1];
    const float* w_out  = (const float*)d_in[2];
    const float* b_out  = (const float*)d_in[3];
    const void*  layout = d_in[4];
    float* out = (float*)d_out;

    void* p;
    cudaGetSymbolAddress(&p, g_qkv);   float* qkv   = (float*)p;
    cudaGetSymbolAddress(&p, g_att);   float* att   = (float*)p;
    cudaGetSymbolAddress(&p, g_xr);    float* xr    = (float*)p;
    cudaGetSymbolAddress(&p, g_wqkvT); float* wqkvT = (float*)p;
    cudaGetSymbolAddress(&p, g_woutT); float* woutT = (float*)p;

    cudaFuncSetAttribute(gemm_lds<false>,
                         cudaFuncAttributeMaxDynamicSharedMemorySize, GEMM_SMEM);
    cudaFuncSetAttribute(gemm_lds<true>,
                         cudaFuncAttributeMaxDynamicSharedMemorySize, GEMM_SMEM);

    // 0) Preprocess: round x; transpose+round weights
    round_tf32<<<(MROWS * DIM / 4 + 255) / 256, 256>>>(x, xr, MROWS * DIM / 4);
    transpose_tf32<<<dim3(N3 / 32, DIM / 32), dim3(32, 8)>>>(w_qkv, wqkvT, DIM, N3);
    transpose_tf32<<<dim3(DIM / 32, DIM / 32), dim3(32, 8)>>>(w_out, woutT, DIM, DIM);

    // 1) QKV projection: [4096,1024] @ [1024,3072]
    gemm_lds<false><<<dim3(N3 / 128, MROWS / 128), 256, GEMM_SMEM>>>(
        xr, wqkvT, nullptr, qkv, N3, DIM);

    // 2) Block-sparse flash attention (mma.sync)
    attn_mma<<<dim3(NB, HEADS, BATCH), 128>>>(qkv, layout, att);

    // 3) Output projection + bias
    gemm_lds<true><<<dim3(DIM / 128, MROWS / 128), 256, GEMM_SMEM>>>(
        att, woutT, b_out, out, DIM, DIM);
}

// round 10
// speedup vs baseline: 1.7178x; 1.2705x over previous
#include <cuda_runtime.h>
#include <math.h>
#include <stdint.h>

#define HEADS   16
#define DH      64
#define BLK     16
#define SEQ     2048
#define NB      128
#define BATCH   2
#define DIM     1024
#define N3      3072
#define MROWS   (BATCH * SEQ)   // 4096

// ---------------------------------------------------------------------------
// Scratch (device globals — no allocations anywhere)
// ---------------------------------------------------------------------------
__device__ float g_qkv[(size_t)MROWS * N3];    // 4096 x 3072
__device__ float g_att[(size_t)MROWS * DIM];   // 4096 x 1024 (tf32-rounded at write)
__device__ float g_xr[(size_t)MROWS * DIM];    // 4096 x 1024 (tf32-rounded x)
__device__ float g_wqkvT[(size_t)N3 * DIM];    // 3072 x 1024 (K-major, tf32-rounded)
__device__ float g_woutT[(size_t)DIM * DIM];   // 1024 x 1024

__device__ __forceinline__ float to_tf32(float x) {
    uint32_t u;
    asm("cvt.rna.tf32.f32 %0, %1;" : "=r"(u) : "f"(x));
    return __uint_as_float(u);
}

// mma.sync m16n8k8 tf32: D = A*B + D  (fp32 accum)
__device__ __forceinline__ void mma_tf32(float* c, const uint32_t* a, const uint32_t* b) {
    asm volatile(
        "mma.sync.aligned.m16n8k8.row.col.f32.tf32.tf32.f32 "
        "{%0,%1,%2,%3}, {%4,%5,%6,%7}, {%8,%9}, {%0,%1,%2,%3};"
        : "+f"(c[0]), "+f"(c[1]), "+f"(c[2]), "+f"(c[3])
        : "r"(a[0]), "r"(a[1]), "r"(a[2]), "r"(a[3]), "r"(b[0]), "r"(b[1]));
}

__device__ __forceinline__ uint32_t smem_u32(const void* p) {
    uint32_t a;
    asm("{ .reg .u64 t; cvta.to.shared.u64 t, %1; cvt.u32.u64 %0, t; }" : "=r"(a) : "l"(p));
    return a;
}
__device__ __forceinline__ void cpa16(uint32_t s, const void* g) {
    asm volatile("cp.async.cg.shared.global [%0], [%1], 16;" :: "r"(s), "l"(g));
}
#define CP_COMMIT() asm volatile("cp.async.commit_group;" ::: "memory")
#define CP_WAIT1()  asm volatile("cp.async.wait_group 1;" ::: "memory")

__device__ __forceinline__ void ldsm_x4(uint32_t* r, uint32_t a) {
    asm volatile("ldmatrix.sync.aligned.m8n8.x4.shared.b16 {%0,%1,%2,%3}, [%4];"
                 : "=r"(r[0]), "=r"(r[1]), "=r"(r[2]), "=r"(r[3]) : "r"(a));
}

// ---------------------------------------------------------------------------
// Elementwise tf32 round (for x)
// ---------------------------------------------------------------------------
__global__ void __launch_bounds__(256)
round_tf32(const float* __restrict__ src, float* __restrict__ dst, int n4)
{
    int i = blockIdx.x * 256 + threadIdx.x;
    if (i < n4) {
        float4 v = ((const float4*)src)[i];
        v.x = to_tf32(v.x); v.y = to_tf32(v.y);
        v.z = to_tf32(v.z); v.w = to_tf32(v.w);
        ((float4*)dst)[i] = v;
    }
}

// ---------------------------------------------------------------------------
// Transpose + tf32 round: dst[C x R] = tf32(src[R x C])^T
// ---------------------------------------------------------------------------
__global__ void __launch_bounds__(256)
transpose_tf32(const float* __restrict__ src, float* __restrict__ dst, int R, int C)
{
    __shared__ float t[32][33];
    int c0 = blockIdx.x * 32, r0 = blockIdx.y * 32;
    int x = threadIdx.x, y = threadIdx.y;  // block (32, 8)
    #pragma unroll
    for (int i = 0; i < 32; i += 8)
        t[y + i][x] = to_tf32(src[(size_t)(r0 + y + i) * C + c0 + x]);
    __syncthreads();
    #pragma unroll
    for (int i = 0; i < 32; i += 8)
        dst[(size_t)(c0 + y + i) * R + r0 + x] = t[x][y + i];
}

// ---------------------------------------------------------------------------
// cp.async + ldmatrix tf32 GEMM: C = A @ Bt^T (+bias). A, Bt pre-rounded tf32.
// 128x128 CTA tile, 128 threads = 4 warps, WARP TILE 64x64 (square -> half the
// per-MMA smem fragment traffic vs 64x32). BK=32, 3 stages.
// Smem per stage: A 16 KB + B 16 KB, row-major [row(128)][kq(8)] 16B quads,
// XOR swizzle kq ^= row&7. ldmatrix.x4.b16 fragments, k-step double-buffered.
// ---------------------------------------------------------------------------
#define STAGES 3
#define GEMM_SMEM (STAGES * 32768)

template<bool BIAS>
__global__ void __launch_bounds__(128)
gemm_sq(const float* __restrict__ A, const float* __restrict__ Bt,
        const float* __restrict__ bias, float* __restrict__ C, int N, int K)
{
    extern __shared__ float sm[];
    const uint32_t smb = smem_u32(sm);

    const int tid = threadIdx.x;
    const int wid = tid >> 5;
    const int lid = tid & 31;
    const int wr  = wid >> 1;       // 0..1 (M half)
    const int wc  = wid & 1;        // 0..1 (N half)

    const int nchunk = K >> 5;      // 32

    // ---- copy mapping: thread t covers quads q = t + i*128, i=0..7 ----
    //   row = (t>>3) + 16*i   (row&7 == (t>>3)&7, constant across i)
    //   kq  = t&7             (constant)
    const int r0c = tid >> 3;             // 0..15
    const int kqc = tid & 7;
    const uint32_t csw = (uint32_t)(r0c & 7);
    const uint32_t cq_off = (uint32_t)((kqc ^ csw) << 4);   // swizzled quad byte off
    const float* Abase = A  + (size_t)(blockIdx.y * 128 + r0c) * K + kqc * 4;
    const float* Bbase = Bt + (size_t)(blockIdx.x * 128 + r0c) * K + kqc * 4;

    auto issue = [&](int c, int s) {
        const uint32_t ab = smb + s * 32768 + r0c * 128 + cq_off;
        #pragma unroll
        for (int i = 0; i < 8; i++) {
            cpa16(ab + i * 2048,         Abase + (size_t)(16 * i) * K + c * 32);
            cpa16(ab + 16384 + i * 2048, Bbase + (size_t)(16 * i) * K + c * 32);
        }
    };

    // ---- ldmatrix address components ----
    // A (per mt): rows wr*64 + mt*16 + (lid&15), kq = 2ks + (lid>>4)
    const uint32_t a_row = (uint32_t)(wr * 64 + (lid & 15));
    const uint32_t a_kqb = (uint32_t)(lid >> 4);
    // B (per np): rows wc*64 + np*16 + (lid&7) + ((lid>>4)<<3), kq = 2ks + ((lid>>3)&1)
    const uint32_t b_row = (uint32_t)(wc * 64 + (lid & 7) + ((lid >> 4) << 3));
    const uint32_t b_kqb = (uint32_t)((lid >> 3) & 1);
    const uint32_t l_sw  = (uint32_t)(lid & 7);     // row&7 for A and B rows

    float acc[4][8][4];
    #pragma unroll
    for (int i = 0; i < 4; i++)
        #pragma unroll
        for (int j = 0; j < 8; j++)
            #pragma unroll
            for (int r = 0; r < 4; r++) acc[i][j][r] = 0.0f;

    issue(0, 0); CP_COMMIT();
    issue(1, 1); CP_COMMIT();

    uint32_t afr[2][4][4];
    uint32_t bfr[2][4][4];

    for (int c = 0; c < nchunk; c++) {
        const int s = c % STAGES;
        CP_WAIT1();
        __syncthreads();

        const int cn = c + STAGES - 1;
        if (cn < nchunk) issue(cn, cn % STAGES);
        CP_COMMIT();

        const uint32_t abase = smb + s * 32768 + a_row * 128;
        const uint32_t bbase = smb + s * 32768 + 16384 + b_row * 128;

        // ks = 0 into buffer 0
        #pragma unroll
        for (int mt = 0; mt < 4; mt++)
            ldsm_x4(afr[0][mt], abase + mt * 2048 + ((a_kqb ^ l_sw) << 4));
        #pragma unroll
        for (int np = 0; np < 4; np++)
            ldsm_x4(bfr[0][np], bbase + np * 2048 + ((b_kqb ^ l_sw) << 4));

        #pragma unroll
        for (int ks = 0; ks < 4; ks++) {
            const int cur = ks & 1, nxt = cur ^ 1;
            if (ks < 3) {
                const uint32_t kq_a = (uint32_t)(2 * (ks + 1)) + a_kqb;
                const uint32_t kq_b = (uint32_t)(2 * (ks + 1)) + b_kqb;
                #pragma unroll
                for (int mt = 0; mt < 4; mt++)
                    ldsm_x4(afr[nxt][mt], abase + mt * 2048 + ((kq_a ^ l_sw) << 4));
                #pragma unroll
                for (int np = 0; np < 4; np++)
                    ldsm_x4(bfr[nxt][np], bbase + np * 2048 + ((kq_b ^ l_sw) << 4));
            }
            #pragma unroll
            for (int mt = 0; mt < 4; mt++)
                #pragma unroll
                for (int nt = 0; nt < 8; nt++)
                    mma_tf32(acc[mt][nt], afr[cur][mt], &bfr[cur][nt >> 1][(nt & 1) * 2]);
        }
    }

    const int r0 = blockIdx.y * 128 + wr * 64 + (lid >> 2);
    const int c0 = blockIdx.x * 128 + wc * 64 + (lid & 3) * 2;
    #pragma unroll
    for (int mt = 0; mt < 4; mt++) {
        #pragma unroll
        for (int nt = 0; nt < 8; nt++) {
            int row = r0 + mt * 16;
            int col = c0 + nt * 8;
            float2 v0 = make_float2(acc[mt][nt][0], acc[mt][nt][1]);
            float2 v1 = make_float2(acc[mt][nt][2], acc[mt][nt][3]);
            if (BIAS) {
                float b0 = bias[col], b1 = bias[col + 1];
                v0.x += b0; v0.y += b1;
                v1.x += b0; v1.y += b1;
            }
            *(float2*)(C + (size_t)row * N + col)       = v0;
            *(float2*)(C + (size_t)(row + 8) * N + col) = v1;
        }
    }
}

// ---------------------------------------------------------------------------
// mma.sync flash attention, warp-split-K (round-4 proven; output tf32-rounded)
// ---------------------------------------------------------------------------
__global__ void __launch_bounds__(128)
attn_mma(const float* __restrict__ qkv, const void* __restrict__ layout,
         float* __restrict__ att)
{
    __shared__ __align__(16) float wbuf[4][2464];
    __shared__ int list[NB];
    __shared__ int wcnt[4];

    const int qb = blockIdx.x, h = blockIdx.y, bz = blockIdx.z;
    const int tid = threadIdx.x;
    const int wid = tid >> 5;
    const int lid = tid & 31;
    const int r4  = lid >> 2;
    const int c4  = lid & 3;

    const int probe = __ldg(&((const int*)layout)[32]);
    const bool u8 = (probe == 257);
    const int kb0 = wid * 32 + lid;
    bool ok = (kb0 <= qb) &&
              (u8 ? (((const unsigned char*)layout)[qb * NB + kb0] != 0)
                  : (((const int*)layout)[qb * NB + kb0] != 0));
    unsigned bmask = __ballot_sync(0xffffffffu, ok);
    if (lid == 0) wcnt[wid] = __popc(bmask);
    __syncthreads();
    int pre = 0;
    #pragma unroll
    for (int w = 0; w < 4; w++) pre += (w < wid) ? wcnt[w] : 0;
    const int total = wcnt[0] + wcnt[1] + wcnt[2] + wcnt[3];
    if (ok) list[pre + __popc(bmask & ((1u << lid) - 1u))] = kb0;
    __syncthreads();

    const float scale = 0.125f;
    const float* qp = qkv + (size_t)(bz * SEQ + qb * 16) * N3 + h * 64;
    uint32_t qa[8][4];
    #pragma unroll
    for (int ks = 0; ks < 8; ks++) {
        qa[ks][0] = __float_as_uint(to_tf32(qp[(size_t)r4 * N3       + ks * 8 + c4]     * scale));
        qa[ks][1] = __float_as_uint(to_tf32(qp[(size_t)(r4 + 8) * N3 + ks * 8 + c4]     * scale));
        qa[ks][2] = __float_as_uint(to_tf32(qp[(size_t)r4 * N3       + ks * 8 + c4 + 4] * scale));
        qa[ks][3] = __float_as_uint(to_tf32(qp[(size_t)(r4 + 8) * N3 + ks * 8 + c4 + 4] * scale));
    }

    float o[8][4];
    #pragma unroll
    for (int nt = 0; nt < 8; nt++)
        #pragma unroll
        for (int r = 0; r < 4; r++) o[nt][r] = 0.0f;
    float m_lo = -INFINITY, m_hi = -INFINITY, l_lo = 0.0f, l_hi = 0.0f;

    float* Ks = wbuf[wid];
    float* Vs = Ks + 1088;
    float* Ps = Ks + 2176;

    for (int it = wid; it < total; it += 4) {
        const int kb = list[it];
        const float* kvb = qkv + (size_t)(bz * SEQ + kb * 16) * N3 + h * 64;

        #pragma unroll
        for (int j = 0; j < 8; j++) {
            int f = lid + j * 32;
            int row = f >> 4, c16 = f & 15;
            float4 k4 = *(const float4*)(kvb + (size_t)row * N3 + 1024 + c16 * 4);
            float* kd = Ks + row * 68 + c16 * 4;
            kd[0] = to_tf32(k4.x); kd[1] = to_tf32(k4.y);
            kd[2] = to_tf32(k4.z); kd[3] = to_tf32(k4.w);
            float4 v4 = *(const float4*)(kvb + (size_t)row * N3 + 2048 + c16 * 4);
            float* vd = Vs + row * 68 + c16 * 4;
            vd[0] = to_tf32(v4.x); vd[1] = to_tf32(v4.y);
            vd[2] = to_tf32(v4.z); vd[3] = to_tf32(v4.w);
        }
        __syncwarp();

        float s0[4] = {0.f, 0.f, 0.f, 0.f};
        float s1[4] = {0.f, 0.f, 0.f, 0.f};
        #pragma unroll
        for (int ks = 0; ks < 8; ks++) {
            uint32_t b0[2], b1[2];
            b0[0] = __float_as_uint(Ks[r4 * 68 + ks * 8 + c4]);
            b0[1] = __float_as_uint(Ks[r4 * 68 + ks * 8 + c4 + 4]);
            b1[0] = __float_as_uint(Ks[(8 + r4) * 68 + ks * 8 + c4]);
            b1[1] = __float_as_uint(Ks[(8 + r4) * 68 + ks * 8 + c4 + 4]);
            mma_tf32(s0, qa[ks], b0);
            mma_tf32(s1, qa[ks], b1);
        }

        if (kb == qb) {
            const int cA = 2 * c4, cB = 2 * c4 + 1;
            if (cA > r4)     s0[0] = -1e30f;
            if (cB > r4)     s0[1] = -1e30f;
            if (cA > r4 + 8) s0[2] = -1e30f;
            if (cB > r4 + 8) s0[3] = -1e30f;
            if (cA + 8 > r4)     s1[0] = -1e30f;
            if (cB + 8 > r4)     s1[1] = -1e30f;
            if (cA + 8 > r4 + 8) s1[2] = -1e30f;
            if (cB + 8 > r4 + 8) s1[3] = -1e30f;
        }

        float lo = fmaxf(fmaxf(s0[0], s0[1]), fmaxf(s1[0], s1[1]));
        float hi = fmaxf(fmaxf(s0[2], s0[3]), fmaxf(s1[2], s1[3]));
        lo = fmaxf(lo, __shfl_xor_sync(0xffffffffu, lo, 1));
        lo = fmaxf(lo, __shfl_xor_sync(0xffffffffu, lo, 2));
        hi = fmaxf(hi, __shfl_xor_sync(0xffffffffu, hi, 1));
        hi = fmaxf(hi, __shfl_xor_sync(0xffffffffu, hi, 2));

        const float mlo = fmaxf(m_lo, lo);
        const float mhi = fmaxf(m_hi, hi);
        const float alo = __expf(m_lo - mlo);
        const float ahi = __expf(m_hi - mhi);

        float p00 = __expf(s0[0] - mlo), p01 = __expf(s0[1] - mlo);
        float p10 = __expf(s1[0] - mlo), p11 = __expf(s1[1] - mlo);
        float p02 = __expf(s0[2] - mhi), p03 = __expf(s0[3] - mhi);
        float p12 = __expf(s1[2] - mhi), p13 = __expf(s1[3] - mhi);

        float slo = p00 + p01 + p10 + p11;
        float shi = p02 + p03 + p12 + p13;
        slo += __shfl_xor_sync(0xffffffffu, slo, 1);
        slo += __shfl_xor_sync(0xffffffffu, slo, 2);
        shi += __shfl_xor_sync(0xffffffffu, shi, 1);
        shi += __shfl_xor_sync(0xffffffffu, shi, 2);

        l_lo = l_lo * alo + slo;
        l_hi = l_hi * ahi + shi;
        m_lo = mlo; m_hi = mhi;

        #pragma unroll
        for (int nt = 0; nt < 8; nt++) {
            o[nt][0] *= alo; o[nt][1] *= alo;
            o[nt][2] *= ahi; o[nt][3] *= ahi;
        }

        *(float2*)&Ps[r4 * 18 + 2 * c4]           = make_float2(to_tf32(p00), to_tf32(p01));
        *(float2*)&Ps[r4 * 18 + 8 + 2 * c4]       = make_float2(to_tf32(p10), to_tf32(p11));
        *(float2*)&Ps[(r4 + 8) * 18 + 2 * c4]     = make_float2(to_tf32(p02), to_tf32(p03));
        *(float2*)&Ps[(r4 + 8) * 18 + 8 + 2 * c4] = make_float2(to_tf32(p12), to_tf32(p13));
        __syncwarp();

        uint32_t pa0[4], pa1[4];
        pa0[0] = __float_as_uint(Ps[r4 * 18 + c4]);
        pa0[1] = __float_as_uint(Ps[(r4 + 8) * 18 + c4]);
        pa0[2] = __float_as_uint(Ps[r4 * 18 + c4 + 4]);
        pa0[3] = __float_as_uint(Ps[(r4 + 8) * 18 + c4 + 4]);
        pa1[0] = __float_as_uint(Ps[r4 * 18 + 8 + c4]);
        pa1[1] = __float_as_uint(Ps[(r4 + 8) * 18 + 8 + c4]);
        pa1[2] = __float_as_uint(Ps[r4 * 18 + 8 + c4 + 4]);
        pa1[3] = __float_as_uint(Ps[(r4 + 8) * 18 + 8 + c4 + 4]);

        #pragma unroll
        for (int nt = 0; nt < 8; nt++) {
            uint32_t b0[2], b1[2];
            b0[0] = __float_as_uint(Vs[c4 * 68 + nt * 8 + r4]);
            b0[1] = __float_as_uint(Vs[(c4 + 4) * 68 + nt * 8 + r4]);
            mma_tf32(o[nt], pa0, b0);
            b1[0] = __float_as_uint(Vs[(8 + c4) * 68 + nt * 8 + r4]);
            b1[1] = __float_as_uint(Vs[(12 + c4) * 68 + nt * 8 + r4]);
            mma_tf32(o[nt], pa1, b1);
        }
        __syncwarp();
    }

    float* Os = wbuf[wid];
    #pragma unroll
    for (int nt = 0; nt < 8; nt++) {
        *(float2*)&Os[r4 * 66 + nt * 8 + 2 * c4]       = make_float2(o[nt][0], o[nt][1]);
        *(float2*)&Os[(r4 + 8) * 66 + nt * 8 + 2 * c4] = make_float2(o[nt][2], o[nt][3]);
    }
    if (c4 == 0) {
        Os[1056 + r4]     = m_lo;
        Os[1056 + 8 + r4] = m_hi;
        Os[1072 + r4]     = l_lo;
        Os[1072 + 8 + r4] = l_hi;
    }
    __syncthreads();

    {
        const int row = tid >> 3;
        const int d0  = (tid & 7) * 8;
        float mw[4], lw[4];
        float M = -INFINITY;
        #pragma unroll
        for (int w = 0; w < 4; w++) {
            mw[w] = wbuf[w][1056 + row];
            lw[w] = wbuf[w][1072 + row];
            M = fmaxf(M, mw[w]);
        }
        float L = 0.0f, wgt[4];
        #pragma unroll
        for (int w = 0; w < 4; w++) {
            wgt[w] = __expf(mw[w] - M);
            L += wgt[w] * lw[w];
        }
        const float inv = 1.0f / L;
        float out[8];
        #pragma unroll
        for (int j = 0; j < 8; j++) out[j] = 0.0f;
        #pragma unroll
        for (int w = 0; w < 4; w++) {
            const float g = wgt[w];
            const float* op = &wbuf[w][row * 66 + d0];
            #pragma unroll
            for (int j = 0; j < 8; j++) out[j] += g * op[j];
        }
        float* ap = att + (size_t)(bz * SEQ + qb * 16 + row) * DIM + h * 64 + d0;
        float4 v0 = make_float4(to_tf32(out[0] * inv), to_tf32(out[1] * inv),
                                to_tf32(out[2] * inv), to_tf32(out[3] * inv));
        float4 v1 = make_float4(to_tf32(out[4] * inv), to_tf32(out[5] * inv),
                                to_tf32(out[6] * inv), to_tf32(out[7] * inv));
        *(float4*)(ap)     = v0;
        *(float4*)(ap + 4) = v1;
    }
}

// ---------------------------------------------------------------------------
extern "C" void kernel_launch(void* const* d_in, const int* in_sizes, int n_in,
                              void* d_out, int out_size)
{
    const float* x      = (const float*)d_in[0];
    const float* w_qkv  = (const float*)d_in[1];
    const float* w_out  = (const float*)d_in[2];
    const float* b_out  = (const float*)d_in[3];
    const void*  layout = d_in[4];
    float* out = (float*)d_out;

    void* p;
    cudaGetSymbolAddress(&p, g_qkv);   float* qkv   = (float*)p;
    cudaGetSymbolAddress(&p, g_att);   float* att   = (float*)p;
    cudaGetSymbolAddress(&p, g_xr);    float* xr    = (float*)p;
    cudaGetSymbolAddress(&p, g_wqkvT); float* wqkvT = (float*)p;
    cudaGetSymbolAddress(&p, g_woutT); float* woutT = (float*)p;

    cudaFuncSetAttribute(gemm_sq<false>,
                         cudaFuncAttributeMaxDynamicSharedMemorySize, GEMM_SMEM);
    cudaFuncSetAttribute(gemm_sq<true>,
                         cudaFuncAttributeMaxDynamicSharedMemorySize, GEMM_SMEM);

    // 0) Preprocess: round x; transpose+round weights
    round_tf32<<<(MROWS * DIM / 4 + 255) / 256, 256>>>(x, xr, MROWS * DIM / 4);
    transpose_tf32<<<dim3(N3 / 32, DIM / 32), dim3(32, 8)>>>(w_qkv, wqkvT, DIM, N3);
    transpose_tf32<<<dim3(DIM / 32, DIM / 32), dim3(32, 8)>>>(w_out, woutT, DIM, DIM);

    // 1) QKV projection: [4096,1024] @ [1024,3072]
    gemm_sq<false><<<dim3(N3 / 128, MROWS / 128), 128, GEMM_SMEM>>>(
        xr, wqkvT, nullptr, qkv, N3, DIM);

    // 2) Block-sparse flash attention (mma.sync)
    attn_mma<<<dim3(NB, HEADS, BATCH), 128>>>(qkv, layout, att);

    // 3) Output projection + bias
    gemm_sq<true><<<dim3(DIM / 128, MROWS / 128), 128, GEMM_SMEM>>>(
        att, woutT, b_out, out, DIM, DIM);
}

// round 11
// speedup vs baseline: 1.8891x; 1.0997x over previous
#include <cuda_runtime.h>
#include <math.h>
#include <stdint.h>

#define HEADS   16
#define DH      64
#define BLK     16
#define SEQ     2048
#define NB      128
#define BATCH   2
#define DIM     1024
#define N3      3072
#define MROWS   (BATCH * SEQ)   // 4096

// ---------------------------------------------------------------------------
// Scratch (device globals — no allocations anywhere)
// ---------------------------------------------------------------------------
__device__ float g_qkv[(size_t)MROWS * N3];    // 4096 x 3072
__device__ float g_att[(size_t)MROWS * DIM];   // 4096 x 1024 (tf32-rounded at write)
__device__ float g_xr[(size_t)MROWS * DIM];    // 4096 x 1024 (tf32-rounded x)
__device__ float g_wqkvT[(size_t)N3 * DIM];    // 3072 x 1024 (K-major, tf32-rounded)
__device__ float g_woutT[(size_t)DIM * DIM];   // 1024 x 1024

__device__ __forceinline__ float to_tf32(float x) {
    uint32_t u;
    asm("cvt.rna.tf32.f32 %0, %1;" : "=r"(u) : "f"(x));
    return __uint_as_float(u);
}

// mma.sync m16n8k8 tf32: D = A*B + D  (fp32 accum)
__device__ __forceinline__ void mma_tf32(float* c, const uint32_t* a, const uint32_t* b) {
    asm volatile(
        "mma.sync.aligned.m16n8k8.row.col.f32.tf32.tf32.f32 "
        "{%0,%1,%2,%3}, {%4,%5,%6,%7}, {%8,%9}, {%0,%1,%2,%3};"
        : "+f"(c[0]), "+f"(c[1]), "+f"(c[2]), "+f"(c[3])
        : "r"(a[0]), "r"(a[1]), "r"(a[2]), "r"(a[3]), "r"(b[0]), "r"(b[1]));
}

__device__ __forceinline__ uint32_t smem_u32(const void* p) {
    uint32_t a;
    asm("{ .reg .u64 t; cvta.to.shared.u64 t, %1; cvt.u32.u64 %0, t; }" : "=r"(a) : "l"(p));
    return a;
}
__device__ __forceinline__ void cpa16(uint32_t s, const void* g) {
    asm volatile("cp.async.cg.shared.global [%0], [%1], 16;" :: "r"(s), "l"(g));
}
#define CP_COMMIT() asm volatile("cp.async.commit_group;" ::: "memory")
#define CP_WAIT1()  asm volatile("cp.async.wait_group 1;" ::: "memory")

__device__ __forceinline__ void ldsm_x4(uint32_t* r, uint32_t a) {
    asm volatile("ldmatrix.sync.aligned.m8n8.x4.shared.b16 {%0,%1,%2,%3}, [%4];"
                 : "=r"(r[0]), "=r"(r[1]), "=r"(r[2]), "=r"(r[3]) : "r"(a));
}

// ---------------------------------------------------------------------------
// Elementwise tf32 round (for x)
// ---------------------------------------------------------------------------
__global__ void __launch_bounds__(256)
round_tf32(const float* __restrict__ src, float* __restrict__ dst, int n4)
{
    int i = blockIdx.x * 256 + threadIdx.x;
    if (i < n4) {
        float4 v = ((const float4*)src)[i];
        v.x = to_tf32(v.x); v.y = to_tf32(v.y);
        v.z = to_tf32(v.z); v.w = to_tf32(v.w);
        ((float4*)dst)[i] = v;
    }
}

// ---------------------------------------------------------------------------
// Transpose + tf32 round: dst[C x R] = tf32(src[R x C])^T
// ---------------------------------------------------------------------------
__global__ void __launch_bounds__(256)
transpose_tf32(const float* __restrict__ src, float* __restrict__ dst, int R, int C)
{
    __shared__ float t[32][33];
    int c0 = blockIdx.x * 32, r0 = blockIdx.y * 32;
    int x = threadIdx.x, y = threadIdx.y;  // block (32, 8)
    #pragma unroll
    for (int i = 0; i < 32; i += 8)
        t[y + i][x] = to_tf32(src[(size_t)(r0 + y + i) * C + c0 + x]);
    __syncthreads();
    #pragma unroll
    for (int i = 0; i < 32; i += 8)
        dst[(size_t)(c0 + y + i) * R + r0 + x] = t[x][y + i];
}

// ---------------------------------------------------------------------------
// cp.async + ldmatrix tf32 GEMM (round-10 proven: 64x64 warp tiles)
// ---------------------------------------------------------------------------
#define STAGES 3
#define GEMM_SMEM (STAGES * 32768)

template<bool BIAS>
__global__ void __launch_bounds__(128)
gemm_sq(const float* __restrict__ A, const float* __restrict__ Bt,
        const float* __restrict__ bias, float* __restrict__ C, int N, int K)
{
    extern __shared__ float sm[];
    const uint32_t smb = smem_u32(sm);

    const int tid = threadIdx.x;
    const int wid = tid >> 5;
    const int lid = tid & 31;
    const int wr  = wid >> 1;
    const int wc  = wid & 1;

    const int nchunk = K >> 5;

    const int r0c = tid >> 3;
    const int kqc = tid & 7;
    const uint32_t csw = (uint32_t)(r0c & 7);
    const uint32_t cq_off = (uint32_t)((kqc ^ csw) << 4);
    const float* Abase = A  + (size_t)(blockIdx.y * 128 + r0c) * K + kqc * 4;
    const float* Bbase = Bt + (size_t)(blockIdx.x * 128 + r0c) * K + kqc * 4;

    auto issue = [&](int c, int s) {
        const uint32_t ab = smb + s * 32768 + r0c * 128 + cq_off;
        #pragma unroll
        for (int i = 0; i < 8; i++) {
            cpa16(ab + i * 2048,         Abase + (size_t)(16 * i) * K + c * 32);
            cpa16(ab + 16384 + i * 2048, Bbase + (size_t)(16 * i) * K + c * 32);
        }
    };

    const uint32_t a_row = (uint32_t)(wr * 64 + (lid & 15));
    const uint32_t a_kqb = (uint32_t)(lid >> 4);
    const uint32_t b_row = (uint32_t)(wc * 64 + (lid & 7) + ((lid >> 4) << 3));
    const uint32_t b_kqb = (uint32_t)((lid >> 3) & 1);
    const uint32_t l_sw  = (uint32_t)(lid & 7);

    float acc[4][8][4];
    #pragma unroll
    for (int i = 0; i < 4; i++)
        #pragma unroll
        for (int j = 0; j < 8; j++)
            #pragma unroll
            for (int r = 0; r < 4; r++) acc[i][j][r] = 0.0f;

    issue(0, 0); CP_COMMIT();
    issue(1, 1); CP_COMMIT();

    uint32_t afr[2][4][4];
    uint32_t bfr[2][4][4];

    for (int c = 0; c < nchunk; c++) {
        const int s = c % STAGES;
        CP_WAIT1();
        __syncthreads();

        const int cn = c + STAGES - 1;
        if (cn < nchunk) issue(cn, cn % STAGES);
        CP_COMMIT();

        const uint32_t abase = smb + s * 32768 + a_row * 128;
        const uint32_t bbase = smb + s * 32768 + 16384 + b_row * 128;

        #pragma unroll
        for (int mt = 0; mt < 4; mt++)
            ldsm_x4(afr[0][mt], abase + mt * 2048 + ((a_kqb ^ l_sw) << 4));
        #pragma unroll
        for (int np = 0; np < 4; np++)
            ldsm_x4(bfr[0][np], bbase + np * 2048 + ((b_kqb ^ l_sw) << 4));

        #pragma unroll
        for (int ks = 0; ks < 4; ks++) {
            const int cur = ks & 1, nxt = cur ^ 1;
            if (ks < 3) {
                const uint32_t kq_a = (uint32_t)(2 * (ks + 1)) + a_kqb;
                const uint32_t kq_b = (uint32_t)(2 * (ks + 1)) + b_kqb;
                #pragma unroll
                for (int mt = 0; mt < 4; mt++)
                    ldsm_x4(afr[nxt][mt], abase + mt * 2048 + ((kq_a ^ l_sw) << 4));
                #pragma unroll
                for (int np = 0; np < 4; np++)
                    ldsm_x4(bfr[nxt][np], bbase + np * 2048 + ((kq_b ^ l_sw) << 4));
            }
            #pragma unroll
            for (int mt = 0; mt < 4; mt++)
                #pragma unroll
                for (int nt = 0; nt < 8; nt++)
                    mma_tf32(acc[mt][nt], afr[cur][mt], &bfr[cur][nt >> 1][(nt & 1) * 2]);
        }
    }

    const int r0 = blockIdx.y * 128 + wr * 64 + (lid >> 2);
    const int c0 = blockIdx.x * 128 + wc * 64 + (lid & 3) * 2;
    #pragma unroll
    for (int mt = 0; mt < 4; mt++) {
        #pragma unroll
        for (int nt = 0; nt < 8; nt++) {
            int row = r0 + mt * 16;
            int col = c0 + nt * 8;
            float2 v0 = make_float2(acc[mt][nt][0], acc[mt][nt][1]);
            float2 v1 = make_float2(acc[mt][nt][2], acc[mt][nt][3]);
            if (BIAS) {
                float b0 = bias[col], b1 = bias[col + 1];
                v0.x += b0; v0.y += b1;
                v1.x += b0; v1.y += b1;
            }
            *(float2*)(C + (size_t)row * N + col)       = v0;
            *(float2*)(C + (size_t)(row + 8) * N + col) = v1;
        }
    }
}

// ---------------------------------------------------------------------------
// mma.sync flash attention, warp-split-K, cp.async double-buffered K/V.
// Dynamic smem (floats):
//   warp w: [w*4640, w*4640+4640)
//     KV stage s (s=0,1): +s*2176  (K 16x68 @ +0, V 16x68 @ +1088)
//     P tile:              +4352   (16 x 18)
//     epilogue (reuse stage0): O 16x66 @ +0, m @ +1056, l @ +1072
//   list[NB] ints at float-offset 18560, wcnt[4] at 18688
// Total = 74768 bytes.
// ---------------------------------------------------------------------------
#define ATTN_SMEM 74768

__global__ void __launch_bounds__(128)
attn_mma(const float* __restrict__ qkv, const void* __restrict__ layout,
         float* __restrict__ att)
{
    extern __shared__ float asm_[];
    int* list = (int*)(asm_ + 18560);
    int* wcnt = (int*)(asm_ + 18688);

    const int qb = blockIdx.x, h = blockIdx.y, bz = blockIdx.z;
    const int tid = threadIdx.x;
    const int wid = tid >> 5;
    const int lid = tid & 31;
    const int r4  = lid >> 2;
    const int c4  = lid & 3;

    // ---- build allowed-block list (ballot compaction) ----
    const int probe = __ldg(&((const int*)layout)[32]);
    const bool u8 = (probe == 257);
    const int kb0 = wid * 32 + lid;
    bool ok = (kb0 <= qb) &&
              (u8 ? (((const unsigned char*)layout)[qb * NB + kb0] != 0)
                  : (((const int*)layout)[qb * NB + kb0] != 0));
    unsigned bmask = __ballot_sync(0xffffffffu, ok);
    if (lid == 0) wcnt[wid] = __popc(bmask);
    __syncthreads();
    int pre = 0;
    #pragma unroll
    for (int w = 0; w < 4; w++) pre += (w < wid) ? wcnt[w] : 0;
    const int total = wcnt[0] + wcnt[1] + wcnt[2] + wcnt[3];
    if (ok) list[pre + __popc(bmask & ((1u << lid) - 1u))] = kb0;
    __syncthreads();

    // ---- Q fragments (loaded once, pre-scaled, RNA tf32) ----
    const float scale = 0.125f;
    const float* qp = qkv + (size_t)(bz * SEQ + qb * 16) * N3 + h * 64;
    uint32_t qa[8][4];
    #pragma unroll
    for (int ks = 0; ks < 8; ks++) {
        qa[ks][0] = __float_as_uint(to_tf32(qp[(size_t)r4 * N3       + ks * 8 + c4]     * scale));
        qa[ks][1] = __float_as_uint(to_tf32(qp[(size_t)(r4 + 8) * N3 + ks * 8 + c4]     * scale));
        qa[ks][2] = __float_as_uint(to_tf32(qp[(size_t)r4 * N3       + ks * 8 + c4 + 4] * scale));
        qa[ks][3] = __float_as_uint(to_tf32(qp[(size_t)(r4 + 8) * N3 + ks * 8 + c4 + 4] * scale));
    }

    float o[8][4];
    #pragma unroll
    for (int nt = 0; nt < 8; nt++)
        #pragma unroll
        for (int r = 0; r < 4; r++) o[nt][r] = 0.0f;
    float m_lo = -INFINITY, m_hi = -INFINITY, l_lo = 0.0f, l_hi = 0.0f;

    float* wbase = asm_ + wid * 4640;
    const uint32_t wbase_u = smem_u32(wbase);
    float* Ps = wbase + 4352;

    const float* qkv_bz = qkv + (size_t)(bz * SEQ) * N3 + h * 64;

    // cp.async stage of block list[it]'s K/V into stage s (raw fp32)
    auto stage_kv = [&](int it, int s) {
        if (it >= total) return;                     // empty group OK
        const int kb = list[it];
        const float* kvb = qkv_bz + (size_t)(kb * 16) * N3;
        const uint32_t base = wbase_u + (uint32_t)(s * 2176) * 4;
        #pragma unroll
        for (int j = 0; j < 8; j++) {
            int f = lid + j * 32;                    // 0..255
            int row = f >> 4, c16 = f & 15;
            uint32_t off = (uint32_t)(row * 68 + c16 * 4) * 4;   // 16B-aligned (272B rows)
            cpa16(base + off,            kvb + (size_t)row * N3 + 1024 + c16 * 4);
            cpa16(base + 1088 * 4 + off, kvb + (size_t)row * N3 + 2048 + c16 * 4);
        }
    };

    int buf = 0;
    stage_kv(wid, buf); CP_COMMIT();

    for (int it = wid; it < total; it += 4) {
        stage_kv(it + 4, buf ^ 1); CP_COMMIT();
        CP_WAIT1();
        __syncwarp();

        const int kb = list[it];
        float* Ks = wbase + buf * 2176;
        float* Vs = Ks + 1088;

        // S = Q @ K^T  (RNA tf32 applied at fragment load)
        float s0[4] = {0.f, 0.f, 0.f, 0.f};
        float s1[4] = {0.f, 0.f, 0.f, 0.f};
        #pragma unroll
        for (int ks = 0; ks < 8; ks++) {
            uint32_t b0[2], b1[2];
            b0[0] = __float_as_uint(to_tf32(Ks[r4 * 68 + ks * 8 + c4]));
            b0[1] = __float_as_uint(to_tf32(Ks[r4 * 68 + ks * 8 + c4 + 4]));
            b1[0] = __float_as_uint(to_tf32(Ks[(8 + r4) * 68 + ks * 8 + c4]));
            b1[1] = __float_as_uint(to_tf32(Ks[(8 + r4) * 68 + ks * 8 + c4 + 4]));
            mma_tf32(s0, qa[ks], b0);
            mma_tf32(s1, qa[ks], b1);
        }

        if (kb == qb) {
            const int cA = 2 * c4, cB = 2 * c4 + 1;
            if (cA > r4)     s0[0] = -1e30f;
            if (cB > r4)     s0[1] = -1e30f;
            if (cA > r4 + 8) s0[2] = -1e30f;
            if (cB > r4 + 8) s0[3] = -1e30f;
            if (cA + 8 > r4)     s1[0] = -1e30f;
            if (cB + 8 > r4)     s1[1] = -1e30f;
            if (cA + 8 > r4 + 8) s1[2] = -1e30f;
            if (cB + 8 > r4 + 8) s1[3] = -1e30f;
        }

        float lo = fmaxf(fmaxf(s0[0], s0[1]), fmaxf(s1[0], s1[1]));
        float hi = fmaxf(fmaxf(s0[2], s0[3]), fmaxf(s1[2], s1[3]));
        lo = fmaxf(lo, __shfl_xor_sync(0xffffffffu, lo, 1));
        lo = fmaxf(lo, __shfl_xor_sync(0xffffffffu, lo, 2));
        hi = fmaxf(hi, __shfl_xor_sync(0xffffffffu, hi, 1));
        hi = fmaxf(hi, __shfl_xor_sync(0xffffffffu, hi, 2));

        const float mlo = fmaxf(m_lo, lo);
        const float mhi = fmaxf(m_hi, hi);
        const float alo = __expf(m_lo - mlo);
        const float ahi = __expf(m_hi - mhi);

        float p00 = __expf(s0[0] - mlo), p01 = __expf(s0[1] - mlo);
        float p10 = __expf(s1[0] - mlo), p11 = __expf(s1[1] - mlo);
        float p02 = __expf(s0[2] - mhi), p03 = __expf(s0[3] - mhi);
        float p12 = __expf(s1[2] - mhi), p13 = __expf(s1[3] - mhi);

        float slo = p00 + p01 + p10 + p11;
        float shi = p02 + p03 + p12 + p13;
        slo += __shfl_xor_sync(0xffffffffu, slo, 1);
        slo += __shfl_xor_sync(0xffffffffu, slo, 2);
        shi += __shfl_xor_sync(0xffffffffu, shi, 1);
        shi += __shfl_xor_sync(0xffffffffu, shi, 2);

        l_lo = l_lo * alo + slo;
        l_hi = l_hi * ahi + shi;
        m_lo = mlo; m_hi = mhi;

        #pragma unroll
        for (int nt = 0; nt < 8; nt++) {
            o[nt][0] *= alo; o[nt][1] *= alo;
            o[nt][2] *= ahi; o[nt][3] *= ahi;
        }

        *(float2*)&Ps[r4 * 18 + 2 * c4]           = make_float2(to_tf32(p00), to_tf32(p01));
        *(float2*)&Ps[r4 * 18 + 8 + 2 * c4]       = make_float2(to_tf32(p10), to_tf32(p11));
        *(float2*)&Ps[(r4 + 8) * 18 + 2 * c4]     = make_float2(to_tf32(p02), to_tf32(p03));
        *(float2*)&Ps[(r4 + 8) * 18 + 8 + 2 * c4] = make_float2(to_tf32(p12), to_tf32(p13));
        __syncwarp();

        uint32_t pa0[4], pa1[4];
        pa0[0] = __float_as_uint(Ps[r4 * 18 + c4]);
        pa0[1] = __float_as_uint(Ps[(r4 + 8) * 18 + c4]);
        pa0[2] = __float_as_uint(Ps[r4 * 18 + c4 + 4]);
        pa0[3] = __float_as_uint(Ps[(r4 + 8) * 18 + c4 + 4]);
        pa1[0] = __float_as_uint(Ps[r4 * 18 + 8 + c4]);
        pa1[1] = __float_as_uint(Ps[(r4 + 8) * 18 + 8 + c4]);
        pa1[2] = __float_as_uint(Ps[r4 * 18 + 8 + c4 + 4]);
        pa1[3] = __float_as_uint(Ps[(r4 + 8) * 18 + 8 + c4 + 4]);

        #pragma unroll
        for (int nt = 0; nt < 8; nt++) {
            uint32_t b0[2], b1[2];
            b0[0] = __float_as_uint(to_tf32(Vs[c4 * 68 + nt * 8 + r4]));
            b0[1] = __float_as_uint(to_tf32(Vs[(c4 + 4) * 68 + nt * 8 + r4]));
            mma_tf32(o[nt], pa0, b0);
            b1[0] = __float_as_uint(to_tf32(Vs[(8 + c4) * 68 + nt * 8 + r4]));
            b1[1] = __float_as_uint(to_tf32(Vs[(12 + c4) * 68 + nt * 8 + r4]));
            mma_tf32(o[nt], pa1, b1);
        }
        __syncwarp();
        buf ^= 1;
    }

    // ---- write per-warp partials (reuse stage-0 region) ----
    float* Os = wbase;
    #pragma unroll
    for (int nt = 0; nt < 8; nt++) {
        *(float2*)&Os[r4 * 66 + nt * 8 + 2 * c4]       = make_float2(o[nt][0], o[nt][1]);
        *(float2*)&Os[(r4 + 8) * 66 + nt * 8 + 2 * c4] = make_float2(o[nt][2], o[nt][3]);
    }
    if (c4 == 0) {
        Os[1056 + r4]     = m_lo;
        Os[1056 + 8 + r4] = m_hi;
        Os[1072 + r4]     = l_lo;
        Os[1072 + 8 + r4] = l_hi;
    }
    __syncthreads();

    // ---- split-K combine ----
    {
        const int row = tid >> 3;
        const int d0  = (tid & 7) * 8;
        float mw[4], lw[4];
        float M = -INFINITY;
        #pragma unroll
        for (int w = 0; w < 4; w++) {
            mw[w] = asm_[w * 4640 + 1056 + row];
            lw[w] = asm_[w * 4640 + 1072 + row];
            M = fmaxf(M, mw[w]);
        }
        float L = 0.0f, wgt[4];
        #pragma unroll
        for (int w = 0; w < 4; w++) {
            wgt[w] = __expf(mw[w] - M);
            L += wgt[w] * lw[w];
        }
        const float inv = 1.0f / L;
        float out[8];
        #pragma unroll
        for (int j = 0; j < 8; j++) out[j] = 0.0f;
        #pragma unroll
        for (int w = 0; w < 4; w++) {
            const float g = wgt[w];
            const float* op = asm_ + w * 4640 + row * 66 + d0;
            #pragma unroll
            for (int j = 0; j < 8; j++) out[j] += g * op[j];
        }
        float* ap = att + (size_t)(bz * SEQ + qb * 16 + row) * DIM + h * 64 + d0;
        float4 v0 = make_float4(to_tf32(out[0] * inv), to_tf32(out[1] * inv),
                                to_tf32(out[2] * inv), to_tf32(out[3] * inv));
        float4 v1 = make_float4(to_tf32(out[4] * inv), to_tf32(out[5] * inv),
                                to_tf32(out[6] * inv), to_tf32(out[7] * inv));
        *(float4*)(ap)     = v0;
        *(float4*)(ap + 4) = v1;
    }
}

// ---------------------------------------------------------------------------
extern "C" void kernel_launch(void* const* d_in, const int* in_sizes, int n_in,
                              void* d_out, int out_size)
{
    const float* x      = (const float*)d_in[0];
    const float* w_qkv  = (const float*)d_in[1];
    const float* w_out  = (const float*)d_in[2];
    const float* b_out  = (const float*)d_in[3];
    const void*  layout = d_in[4];
    float* out = (float*)d_out;

    void* p;
    cudaGetSymbolAddress(&p, g_qkv);   float* qkv   = (float*)p;
    cudaGetSymbolAddress(&p, g_att);   float* att   = (float*)p;
    cudaGetSymbolAddress(&p, g_xr);    float* xr    = (float*)p;
    cudaGetSymbolAddress(&p, g_wqkvT); float* wqkvT = (float*)p;
    cudaGetSymbolAddress(&p, g_woutT); float* woutT = (float*)p;

    cudaFuncSetAttribute(gemm_sq<false>,
                         cudaFuncAttributeMaxDynamicSharedMemorySize, GEMM_SMEM);
    cudaFuncSetAttribute(gemm_sq<true>,
                         cudaFuncAttributeMaxDynamicSharedMemorySize, GEMM_SMEM);
    cudaFuncSetAttribute(attn_mma,
                         cudaFuncAttributeMaxDynamicSharedMemorySize, ATTN_SMEM);

    // 0) Preprocess: round x; transpose+round weights
    round_tf32<<<(MROWS * DIM / 4 + 255) / 256, 256>>>(x, xr, MROWS * DIM / 4);
    transpose_tf32<<<dim3(N3 / 32, DIM / 32), dim3(32, 8)>>>(w_qkv, wqkvT, DIM, N3);
    transpose_tf32<<<dim3(DIM / 32, DIM / 32), dim3(32, 8)>>>(w_out, woutT, DIM, DIM);

    // 1) QKV projection: [4096,1024] @ [1024,3072]
    gemm_sq<false><<<dim3(N3 / 128, MROWS / 128), 128, GEMM_SMEM>>>(
        xr, wqkvT, nullptr, qkv, N3, DIM);

    // 2) Block-sparse flash attention (cp.async double-buffered)
    attn_mma<<<dim3(NB, HEADS, BATCH), 128, ATTN_SMEM>>>(qkv, layout, att);

    // 3) Output projection + bias
    gemm_sq<true><<<dim3(DIM / 128, MROWS / 128), 128, GEMM_SMEM>>>(
        att, woutT, b_out, out, DIM, DIM);
}

// round 12
// speedup vs baseline: 1.9173x; 1.0150x over previous
#include <cuda_runtime.h>
#include <math.h>
#include <stdint.h>

#define HEADS   16
#define DH      64
#define BLK     16
#define SEQ     2048
#define NB      128
#define BATCH   2
#define DIM     1024
#define N3      3072
#define MROWS   (BATCH * SEQ)   // 4096

// ---------------------------------------------------------------------------
// Scratch (device globals — no allocations anywhere)
// ---------------------------------------------------------------------------
__device__ float g_qkv[(size_t)MROWS * N3];    // 4096 x 3072 (tf32-rounded at write)
__device__ float g_att[(size_t)MROWS * DIM];   // 4096 x 1024 (tf32-rounded at write)
__device__ float g_xr[(size_t)MROWS * DIM];    // 4096 x 1024 (tf32-rounded x)
__device__ float g_wqkvT[(size_t)N3 * DIM];    // 3072 x 1024 (K-major, tf32-rounded)
__device__ float g_woutT[(size_t)DIM * DIM];   // 1024 x 1024

__device__ __forceinline__ float to_tf32(float x) {
    uint32_t u;
    asm("cvt.rna.tf32.f32 %0, %1;" : "=r"(u) : "f"(x));
    return __uint_as_float(u);
}

// mma.sync m16n8k8 tf32: D = A*B + D  (fp32 accum)
__device__ __forceinline__ void mma_tf32(float* c, const uint32_t* a, const uint32_t* b) {
    asm volatile(
        "mma.sync.aligned.m16n8k8.row.col.f32.tf32.tf32.f32 "
        "{%0,%1,%2,%3}, {%4,%5,%6,%7}, {%8,%9}, {%0,%1,%2,%3};"
        : "+f"(c[0]), "+f"(c[1]), "+f"(c[2]), "+f"(c[3])
        : "r"(a[0]), "r"(a[1]), "r"(a[2]), "r"(a[3]), "r"(b[0]), "r"(b[1]));
}

__device__ __forceinline__ uint32_t smem_u32(const void* p) {
    uint32_t a;
    asm("{ .reg .u64 t; cvta.to.shared.u64 t, %1; cvt.u32.u64 %0, t; }" : "=r"(a) : "l"(p));
    return a;
}
__device__ __forceinline__ void cpa16(uint32_t s, const void* g) {
    asm volatile("cp.async.cg.shared.global [%0], [%1], 16;" :: "r"(s), "l"(g));
}
#define CP_COMMIT() asm volatile("cp.async.commit_group;" ::: "memory")
#define CP_WAIT1()  asm volatile("cp.async.wait_group 1;" ::: "memory")

__device__ __forceinline__ void ldsm_x4(uint32_t* r, uint32_t a) {
    asm volatile("ldmatrix.sync.aligned.m8n8.x4.shared.b16 {%0,%1,%2,%3}, [%4];"
                 : "=r"(r[0]), "=r"(r[1]), "=r"(r[2]), "=r"(r[3]) : "r"(a));
}

// ---------------------------------------------------------------------------
// Elementwise tf32 round (for x)
// ---------------------------------------------------------------------------
__global__ void __launch_bounds__(256)
round_tf32(const float* __restrict__ src, float* __restrict__ dst, int n4)
{
    int i = blockIdx.x * 256 + threadIdx.x;
    if (i < n4) {
        float4 v = ((const float4*)src)[i];
        v.x = to_tf32(v.x); v.y = to_tf32(v.y);
        v.z = to_tf32(v.z); v.w = to_tf32(v.w);
        ((float4*)dst)[i] = v;
    }
}

// ---------------------------------------------------------------------------
// Transpose + tf32 round: dst[C x R] = tf32(src[R x C])^T
// ---------------------------------------------------------------------------
__global__ void __launch_bounds__(256)
transpose_tf32(const float* __restrict__ src, float* __restrict__ dst, int R, int C)
{
    __shared__ float t[32][33];
    int c0 = blockIdx.x * 32, r0 = blockIdx.y * 32;
    int x = threadIdx.x, y = threadIdx.y;  // block (32, 8)
    #pragma unroll
    for (int i = 0; i < 32; i += 8)
        t[y + i][x] = to_tf32(src[(size_t)(r0 + y + i) * C + c0 + x]);
    __syncthreads();
    #pragma unroll
    for (int i = 0; i < 32; i += 8)
        dst[(size_t)(c0 + y + i) * R + r0 + x] = t[x][y + i];
}

// ---------------------------------------------------------------------------
// cp.async + ldmatrix tf32 GEMM (round-10 proven: 64x64 warp tiles).
// BIAS=false instance (QKV) tf32-rounds its output so attention needs no CVTs.
// ---------------------------------------------------------------------------
#define STAGES 3
#define GEMM_SMEM (STAGES * 32768)

template<bool BIAS>
__global__ void __launch_bounds__(128)
gemm_sq(const float* __restrict__ A, const float* __restrict__ Bt,
        const float* __restrict__ bias, float* __restrict__ C, int N, int K)
{
    extern __shared__ float sm[];
    const uint32_t smb = smem_u32(sm);

    const int tid = threadIdx.x;
    const int wid = tid >> 5;
    const int lid = tid & 31;
    const int wr  = wid >> 1;
    const int wc  = wid & 1;

    const int nchunk = K >> 5;

    const int r0c = tid >> 3;
    const int kqc = tid & 7;
    const uint32_t csw = (uint32_t)(r0c & 7);
    const uint32_t cq_off = (uint32_t)((kqc ^ csw) << 4);
    const float* Abase = A  + (size_t)(blockIdx.y * 128 + r0c) * K + kqc * 4;
    const float* Bbase = Bt + (size_t)(blockIdx.x * 128 + r0c) * K + kqc * 4;

    auto issue = [&](int c, int s) {
        const uint32_t ab = smb + s * 32768 + r0c * 128 + cq_off;
        #pragma unroll
        for (int i = 0; i < 8; i++) {
            cpa16(ab + i * 2048,         Abase + (size_t)(16 * i) * K + c * 32);
            cpa16(ab + 16384 + i * 2048, Bbase + (size_t)(16 * i) * K + c * 32);
        }
    };

    const uint32_t a_row = (uint32_t)(wr * 64 + (lid & 15));
    const uint32_t a_kqb = (uint32_t)(lid >> 4);
    const uint32_t b_row = (uint32_t)(wc * 64 + (lid & 7) + ((lid >> 4) << 3));
    const uint32_t b_kqb = (uint32_t)((lid >> 3) & 1);
    const uint32_t l_sw  = (uint32_t)(lid & 7);

    float acc[4][8][4];
    #pragma unroll
    for (int i = 0; i < 4; i++)
        #pragma unroll
        for (int j = 0; j < 8; j++)
            #pragma unroll
            for (int r = 0; r < 4; r++) acc[i][j][r] = 0.0f;

    issue(0, 0); CP_COMMIT();
    issue(1, 1); CP_COMMIT();

    uint32_t afr[2][4][4];
    uint32_t bfr[2][4][4];

    for (int c = 0; c < nchunk; c++) {
        const int s = c % STAGES;
        CP_WAIT1();
        __syncthreads();

        const int cn = c + STAGES - 1;
        if (cn < nchunk) issue(cn, cn % STAGES);
        CP_COMMIT();

        const uint32_t abase = smb + s * 32768 + a_row * 128;
        const uint32_t bbase = smb + s * 32768 + 16384 + b_row * 128;

        #pragma unroll
        for (int mt = 0; mt < 4; mt++)
            ldsm_x4(afr[0][mt], abase + mt * 2048 + ((a_kqb ^ l_sw) << 4));
        #pragma unroll
        for (int np = 0; np < 4; np++)
            ldsm_x4(bfr[0][np], bbase + np * 2048 + ((b_kqb ^ l_sw) << 4));

        #pragma unroll
        for (int ks = 0; ks < 4; ks++) {
            const int cur = ks & 1, nxt = cur ^ 1;
            if (ks < 3) {
                const uint32_t kq_a = (uint32_t)(2 * (ks + 1)) + a_kqb;
                const uint32_t kq_b = (uint32_t)(2 * (ks + 1)) + b_kqb;
                #pragma unroll
                for (int mt = 0; mt < 4; mt++)
                    ldsm_x4(afr[nxt][mt], abase + mt * 2048 + ((kq_a ^ l_sw) << 4));
                #pragma unroll
                for (int np = 0; np < 4; np++)
                    ldsm_x4(bfr[nxt][np], bbase + np * 2048 + ((kq_b ^ l_sw) << 4));
            }
            #pragma unroll
            for (int mt = 0; mt < 4; mt++)
                #pragma unroll
                for (int nt = 0; nt < 8; nt++)
                    mma_tf32(acc[mt][nt], afr[cur][mt], &bfr[cur][nt >> 1][(nt & 1) * 2]);
        }
    }

    const int r0 = blockIdx.y * 128 + wr * 64 + (lid >> 2);
    const int c0 = blockIdx.x * 128 + wc * 64 + (lid & 3) * 2;
    #pragma unroll
    for (int mt = 0; mt < 4; mt++) {
        #pragma unroll
        for (int nt = 0; nt < 8; nt++) {
            int row = r0 + mt * 16;
            int col = c0 + nt * 8;
            float2 v0, v1;
            if (BIAS) {
                float b0 = bias[col], b1 = bias[col + 1];
                v0 = make_float2(acc[mt][nt][0] + b0, acc[mt][nt][1] + b1);
                v1 = make_float2(acc[mt][nt][2] + b0, acc[mt][nt][3] + b1);
            } else {
                // qkv path: pre-round so attention consumes tf32 directly
                v0 = make_float2(to_tf32(acc[mt][nt][0]), to_tf32(acc[mt][nt][1]));
                v1 = make_float2(to_tf32(acc[mt][nt][2]), to_tf32(acc[mt][nt][3]));
            }
            *(float2*)(C + (size_t)row * N + col)       = v0;
            *(float2*)(C + (size_t)(row + 8) * N + col) = v1;
        }
    }
}

// ---------------------------------------------------------------------------
// mma.sync flash attention, warp-split-K, cp.async double-buffered K/V.
// K and P fragments via ldmatrix (qkv is pre-rounded tf32 -> no CVTs).
// Dynamic smem (floats): warp w at [w*4672, +4672):
//   KV stage s (s=0,1): +s*2176  (K 16x68 @ +0, V 16x68 @ +1088)
//   P tile:              +4352   (16 rows x stride 20 = 320)
//   epilogue reuse of stage0: O 16x66 @ +0, m @ +1056, l @ +1072
// list[NB] ints at float-offset 18688, wcnt[4] at 18816. Total 75280 bytes.
// ---------------------------------------------------------------------------
#define ATTN_SMEM 75280

__global__ void __launch_bounds__(128)
attn_mma(const float* __restrict__ qkv, const void* __restrict__ layout,
         float* __restrict__ att)
{
    extern __shared__ float asm_[];
    int* list = (int*)(asm_ + 18688);
    int* wcnt = (int*)(asm_ + 18816);

    const int qb = blockIdx.x, h = blockIdx.y, bz = blockIdx.z;
    const int tid = threadIdx.x;
    const int wid = tid >> 5;
    const int lid = tid & 31;
    const int r4  = lid >> 2;
    const int c4  = lid & 3;

    // ---- build allowed-block list (ballot compaction) ----
    const int probe = __ldg(&((const int*)layout)[32]);
    const bool u8 = (probe == 257);
    const int kb0 = wid * 32 + lid;
    bool ok = (kb0 <= qb) &&
              (u8 ? (((const unsigned char*)layout)[qb * NB + kb0] != 0)
                  : (((const int*)layout)[qb * NB + kb0] != 0));
    unsigned bmask = __ballot_sync(0xffffffffu, ok);
    if (lid == 0) wcnt[wid] = __popc(bmask);
    __syncthreads();
    int pre = 0;
    #pragma unroll
    for (int w = 0; w < 4; w++) pre += (w < wid) ? wcnt[w] : 0;
    const int total = wcnt[0] + wcnt[1] + wcnt[2] + wcnt[3];
    if (ok) list[pre + __popc(bmask & ((1u << lid) - 1u))] = kb0;
    __syncthreads();

    // ---- Q fragments (qkv pre-rounded tf32; scale 2^-3 is exact) ----
    const float scale = 0.125f;
    const float* qp = qkv + (size_t)(bz * SEQ + qb * 16) * N3 + h * 64;
    uint32_t qa[8][4];
    #pragma unroll
    for (int ks = 0; ks < 8; ks++) {
        qa[ks][0] = __float_as_uint(qp[(size_t)r4 * N3       + ks * 8 + c4]     * scale);
        qa[ks][1] = __float_as_uint(qp[(size_t)(r4 + 8) * N3 + ks * 8 + c4]     * scale);
        qa[ks][2] = __float_as_uint(qp[(size_t)r4 * N3       + ks * 8 + c4 + 4] * scale);
        qa[ks][3] = __float_as_uint(qp[(size_t)(r4 + 8) * N3 + ks * 8 + c4 + 4] * scale);
    }

    float o[8][4];
    #pragma unroll
    for (int nt = 0; nt < 8; nt++)
        #pragma unroll
        for (int r = 0; r < 4; r++) o[nt][r] = 0.0f;
    float m_lo = -INFINITY, m_hi = -INFINITY, l_lo = 0.0f, l_hi = 0.0f;

    float* wbase = asm_ + wid * 4672;
    const uint32_t wbase_u = smem_u32(wbase);
    float* Ps = wbase + 4352;
    const uint32_t ps_u = wbase_u + 4352 * 4;

    // ldmatrix address components
    const uint32_t kb_off = (uint32_t)((lid & 7) + ((lid >> 4) << 3)) * 272
                          + (uint32_t)((lid >> 3) & 1) * 16;        // K as B-frags
    const uint32_t p_off  = (uint32_t)(lid & 15) * 80
                          + (uint32_t)(lid >> 4) * 16;              // P as A-frags

    const float* qkv_bz = qkv + (size_t)(bz * SEQ) * N3 + h * 64;

    auto stage_kv = [&](int it, int s) {
        if (it >= total) return;
        const int kb = list[it];
        const float* kvb = qkv_bz + (size_t)(kb * 16) * N3;
        const uint32_t base = wbase_u + (uint32_t)(s * 2176) * 4;
        #pragma unroll
        for (int j = 0; j < 8; j++) {
            int f = lid + j * 32;
            int row = f >> 4, c16 = f & 15;
            uint32_t off = (uint32_t)(row * 68 + c16 * 4) * 4;
            cpa16(base + off,            kvb + (size_t)row * N3 + 1024 + c16 * 4);
            cpa16(base + 1088 * 4 + off, kvb + (size_t)row * N3 + 2048 + c16 * 4);
        }
    };

    int buf = 0;
    stage_kv(wid, buf); CP_COMMIT();

    for (int it = wid; it < total; it += 4) {
        stage_kv(it + 4, buf ^ 1); CP_COMMIT();
        CP_WAIT1();
        __syncwarp();

        const int kb = list[it];
        const uint32_t kst = wbase_u + (uint32_t)(buf * 2176) * 4;
        float* Vs = wbase + buf * 2176 + 1088;

        // S = Q @ K^T : K B-fragments via ldmatrix (8 LDSM)
        float s0[4] = {0.f, 0.f, 0.f, 0.f};
        float s1[4] = {0.f, 0.f, 0.f, 0.f};
        #pragma unroll
        for (int ks = 0; ks < 8; ks++) {
            uint32_t kfr[4];
            ldsm_x4(kfr, kst + kb_off + ks * 32);
            mma_tf32(s0, qa[ks], &kfr[0]);
            mma_tf32(s1, qa[ks], &kfr[2]);
        }

        if (kb == qb) {
            const int cA = 2 * c4, cB = 2 * c4 + 1;
            if (cA > r4)     s0[0] = -1e30f;
            if (cB > r4)     s0[1] = -1e30f;
            if (cA > r4 + 8) s0[2] = -1e30f;
            if (cB > r4 + 8) s0[3] = -1e30f;
            if (cA + 8 > r4)     s1[0] = -1e30f;
            if (cB + 8 > r4)     s1[1] = -1e30f;
            if (cA + 8 > r4 + 8) s1[2] = -1e30f;
            if (cB + 8 > r4 + 8) s1[3] = -1e30f;
        }

        float lo = fmaxf(fmaxf(s0[0], s0[1]), fmaxf(s1[0], s1[1]));
        float hi = fmaxf(fmaxf(s0[2], s0[3]), fmaxf(s1[2], s1[3]));
        lo = fmaxf(lo, __shfl_xor_sync(0xffffffffu, lo, 1));
        lo = fmaxf(lo, __shfl_xor_sync(0xffffffffu, lo, 2));
        hi = fmaxf(hi, __shfl_xor_sync(0xffffffffu, hi, 1));
        hi = fmaxf(hi, __shfl_xor_sync(0xffffffffu, hi, 2));

        const float mlo = fmaxf(m_lo, lo);
        const float mhi = fmaxf(m_hi, hi);
        const float alo = __expf(m_lo - mlo);
        const float ahi = __expf(m_hi - mhi);

        float p00 = __expf(s0[0] - mlo), p01 = __expf(s0[1] - mlo);
        float p10 = __expf(s1[0] - mlo), p11 = __expf(s1[1] - mlo);
        float p02 = __expf(s0[2] - mhi), p03 = __expf(s0[3] - mhi);
        float p12 = __expf(s1[2] - mhi), p13 = __expf(s1[3] - mhi);

        float slo = p00 + p01 + p10 + p11;
        float shi = p02 + p03 + p12 + p13;
        slo += __shfl_xor_sync(0xffffffffu, slo, 1);
        slo += __shfl_xor_sync(0xffffffffu, slo, 2);
        shi += __shfl_xor_sync(0xffffffffu, shi, 1);
        shi += __shfl_xor_sync(0xffffffffu, shi, 2);

        l_lo = l_lo * alo + slo;
        l_hi = l_hi * ahi + shi;
        m_lo = mlo; m_hi = mhi;

        #pragma unroll
        for (int nt = 0; nt < 8; nt++) {
            o[nt][0] *= alo; o[nt][1] *= alo;
            o[nt][2] *= ahi; o[nt][3] *= ahi;
        }

        // store P row-major (stride 20 floats), tf32-rounded
        *(float2*)&Ps[r4 * 20 + 2 * c4]           = make_float2(to_tf32(p00), to_tf32(p01));
        *(float2*)&Ps[r4 * 20 + 8 + 2 * c4]       = make_float2(to_tf32(p10), to_tf32(p11));
        *(float2*)&Ps[(r4 + 8) * 20 + 2 * c4]     = make_float2(to_tf32(p02), to_tf32(p03));
        *(float2*)&Ps[(r4 + 8) * 20 + 8 + 2 * c4] = make_float2(to_tf32(p12), to_tf32(p13));
        __syncwarp();

        // P A-fragments via ldmatrix (2 LDSM)
        uint32_t pa0[4], pa1[4];
        ldsm_x4(pa0, ps_u + p_off);
        ldsm_x4(pa1, ps_u + p_off + 32);

        #pragma unroll
        for (int nt = 0; nt < 8; nt++) {
            uint32_t b0[2], b1[2];
            b0[0] = __float_as_uint(Vs[c4 * 68 + nt * 8 + r4]);
            b0[1] = __float_as_uint(Vs[(c4 + 4) * 68 + nt * 8 + r4]);
            mma_tf32(o[nt], pa0, b0);
            b1[0] = __float_as_uint(Vs[(8 + c4) * 68 + nt * 8 + r4]);
            b1[1] = __float_as_uint(Vs[(12 + c4) * 68 + nt * 8 + r4]);
            mma_tf32(o[nt], pa1, b1);
        }
        __syncwarp();
        buf ^= 1;
    }

    // ---- write per-warp partials (reuse stage-0 region) ----
    float* Os = wbase;
    #pragma unroll
    for (int nt = 0; nt < 8; nt++) {
        *(float2*)&Os[r4 * 66 + nt * 8 + 2 * c4]       = make_float2(o[nt][0], o[nt][1]);
        *(float2*)&Os[(r4 + 8) * 66 + nt * 8 + 2 * c4] = make_float2(o[nt][2], o[nt][3]);
    }
    if (c4 == 0) {
        Os[1056 + r4]     = m_lo;
        Os[1056 + 8 + r4] = m_hi;
        Os[1072 + r4]     = l_lo;
        Os[1072 + 8 + r4] = l_hi;
    }
    __syncthreads();

    // ---- split-K combine ----
    {
        const int row = tid >> 3;
        const int d0  = (tid & 7) * 8;
        float mw[4], lw[4];
        float M = -INFINITY;
        #pragma unroll
        for (int w = 0; w < 4; w++) {
            mw[w] = asm_[w * 4672 + 1056 + row];
            lw[w] = asm_[w * 4672 + 1072 + row];
            M = fmaxf(M, mw[w]);
        }
        float L = 0.0f, wgt[4];
        #pragma unroll
        for (int w = 0; w < 4; w++) {
            wgt[w] = __expf(mw[w] - M);
            L += wgt[w] * lw[w];
        }
        const float inv = 1.0f / L;
        float out[8];
        #pragma unroll
        for (int j = 0; j < 8; j++) out[j] = 0.0f;
        #pragma unroll
        for (int w = 0; w < 4; w++) {
            const float g = wgt[w];
            const float* op = asm_ + w * 4672 + row * 66 + d0;
            #pragma unroll
            for (int j = 0; j < 8; j++) out[j] += g * op[j];
        }
        float* ap = att + (size_t)(bz * SEQ + qb * 16 + row) * DIM + h * 64 + d0;
        float4 v0 = make_float4(to_tf32(out[0] * inv), to_tf32(out[1] * inv),
                                to_tf32(out[2] * inv), to_tf32(out[3] * inv));
        float4 v1 = make_float4(to_tf32(out[4] * inv), to_tf32(out[5] * inv),
                                to_tf32(out[6] * inv), to_tf32(out[7] * inv));
        *(float4*)(ap)     = v0;
        *(float4*)(ap + 4) = v1;
    }
}

// ---------------------------------------------------------------------------
extern "C" void kernel_launch(void* const* d_in, const int* in_sizes, int n_in,
                              void* d_out, int out_size)
{
    const float* x      = (const float*)d_in[0];
    const float* w_qkv  = (const float*)d_in[1];
    const float* w_out  = (const float*)d_in[2];
    const float* b_out  = (const float*)d_in[3];
    const void*  layout = d_in[4];
    float* out = (float*)d_out;

    void* p;
    cudaGetSymbolAddress(&p, g_qkv);   float* qkv   = (float*)p;
    cudaGetSymbolAddress(&p, g_att);   float* att   = (float*)p;
    cudaGetSymbolAddress(&p, g_xr);    float* xr    = (float*)p;
    cudaGetSymbolAddress(&p, g_wqkvT); float* wqkvT = (float*)p;
    cudaGetSymbolAddress(&p, g_woutT); float* woutT = (float*)p;

    cudaFuncSetAttribute(gemm_sq<false>,
                         cudaFuncAttributeMaxDynamicSharedMemorySize, GEMM_SMEM);
    cudaFuncSetAttribute(gemm_sq<true>,
                         cudaFuncAttributeMaxDynamicSharedMemorySize, GEMM_SMEM);
    cudaFuncSetAttribute(attn_mma,
                         cudaFuncAttributeMaxDynamicSharedMemorySize, ATTN_SMEM);

    // 0) Preprocess: round x; transpose+round weights
    round_tf32<<<(MROWS * DIM / 4 + 255) / 256, 256>>>(x, xr, MROWS * DIM / 4);
    transpose_tf32<<<dim3(N3 / 32, DIM / 32), dim3(32, 8)>>>(w_qkv, wqkvT, DIM, N3);
    transpose_tf32<<<dim3(DIM / 32, DIM / 32), dim3(32, 8)>>>(w_out, woutT, DIM, DIM);

    // 1) QKV projection (output tf32-rounded)
    gemm_sq<false><<<dim3(N3 / 128, MROWS / 128), 128, GEMM_SMEM>>>(
        xr, wqkvT, nullptr, qkv, N3, DIM);

    // 2) Block-sparse flash attention (cp.async + ldmatrix)
    attn_mma<<<dim3(NB, HEADS, BATCH), 128, ATTN_SMEM>>>(qkv, layout, att);

    // 3) Output projection + bias
    gemm_sq<true><<<dim3(DIM / 128, MROWS / 128), 128, GEMM_SMEM>>>(
        att, woutT, b_out, out, DIM, DIM);
}

// round 13
// speedup vs baseline: 1.9658x; 1.0253x over previous
#include <cuda_runtime.h>
#include <math.h>
#include <stdint.h>

#define HEADS   16
#define DH      64
#define BLK     16
#define SEQ     2048
#define NB      128
#define BATCH   2
#define DIM     1024
#define N3      3072
#define MROWS   (BATCH * SEQ)   // 4096

// ---------------------------------------------------------------------------
// Scratch (device globals — no allocations anywhere)
// ---------------------------------------------------------------------------
__device__ float g_qkv[(size_t)MROWS * N3];    // 4096 x 3072 (tf32-rounded at write)
__device__ float g_att[(size_t)MROWS * DIM];   // 4096 x 1024 (tf32-rounded at write)
__device__ float g_xr[(size_t)MROWS * DIM];    // 4096 x 1024 (tf32-rounded x)
__device__ float g_wqkvT[(size_t)N3 * DIM];    // 3072 x 1024 (K-major, tf32-rounded)
__device__ float g_woutT[(size_t)DIM * DIM];   // 1024 x 1024

__device__ __forceinline__ float to_tf32(float x) {
    uint32_t u;
    asm("cvt.rna.tf32.f32 %0, %1;" : "=r"(u) : "f"(x));
    return __uint_as_float(u);
}

// mma.sync m16n8k8 tf32: D = A*B + D  (fp32 accum)
__device__ __forceinline__ void mma_tf32(float* c, const uint32_t* a, const uint32_t* b) {
    asm volatile(
        "mma.sync.aligned.m16n8k8.row.col.f32.tf32.tf32.f32 "
        "{%0,%1,%2,%3}, {%4,%5,%6,%7}, {%8,%9}, {%0,%1,%2,%3};"
        : "+f"(c[0]), "+f"(c[1]), "+f"(c[2]), "+f"(c[3])
        : "r"(a[0]), "r"(a[1]), "r"(a[2]), "r"(a[3]), "r"(b[0]), "r"(b[1]));
}

__device__ __forceinline__ uint32_t smem_u32(const void* p) {
    uint32_t a;
    asm("{ .reg .u64 t; cvta.to.shared.u64 t, %1; cvt.u32.u64 %0, t; }" : "=r"(a) : "l"(p));
    return a;
}
__device__ __forceinline__ void cpa16(uint32_t s, const void* g) {
    asm volatile("cp.async.cg.shared.global [%0], [%1], 16;" :: "r"(s), "l"(g));
}
#define CP_COMMIT() asm volatile("cp.async.commit_group;" ::: "memory")
#define CP_WAIT1()  asm volatile("cp.async.wait_group 1;" ::: "memory")

__device__ __forceinline__ void ldsm_x4(uint32_t* r, uint32_t a) {
    asm volatile("ldmatrix.sync.aligned.m8n8.x4.shared.b16 {%0,%1,%2,%3}, [%4];"
                 : "=r"(r[0]), "=r"(r[1]), "=r"(r[2]), "=r"(r[3]) : "r"(a));
}

// ---------------------------------------------------------------------------
// Elementwise tf32 round (for x)
// ---------------------------------------------------------------------------
__global__ void __launch_bounds__(256)
round_tf32(const float* __restrict__ src, float* __restrict__ dst, int n4)
{
    int i = blockIdx.x * 256 + threadIdx.x;
    if (i < n4) {
        float4 v = ((const float4*)src)[i];
        v.x = to_tf32(v.x); v.y = to_tf32(v.y);
        v.z = to_tf32(v.z); v.w = to_tf32(v.w);
        ((float4*)dst)[i] = v;
    }
}

// ---------------------------------------------------------------------------
// Transpose + tf32 round: dst[C x R] = tf32(src[R x C])^T
// ---------------------------------------------------------------------------
__global__ void __launch_bounds__(256)
transpose_tf32(const float* __restrict__ src, float* __restrict__ dst, int R, int C)
{
    __shared__ float t[32][33];
    int c0 = blockIdx.x * 32, r0 = blockIdx.y * 32;
    int x = threadIdx.x, y = threadIdx.y;  // block (32, 8)
    #pragma unroll
    for (int i = 0; i < 32; i += 8)
        t[y + i][x] = to_tf32(src[(size_t)(r0 + y + i) * C + c0 + x]);
    __syncthreads();
    #pragma unroll
    for (int i = 0; i < 32; i += 8)
        dst[(size_t)(c0 + y + i) * R + r0 + x] = t[x][y + i];
}

// ---------------------------------------------------------------------------
// cp.async + ldmatrix tf32 GEMM (round-10 proven: 64x64 warp tiles).
// BIAS=false instance (QKV) tf32-rounds its output so attention needs no CVTs.
// ---------------------------------------------------------------------------
#define STAGES 3
#define GEMM_SMEM (STAGES * 32768)

template<bool BIAS>
__global__ void __launch_bounds__(128)
gemm_sq(const float* __restrict__ A, const float* __restrict__ Bt,
        const float* __restrict__ bias, float* __restrict__ C, int N, int K)
{
    extern __shared__ float sm[];
    const uint32_t smb = smem_u32(sm);

    const int tid = threadIdx.x;
    const int wid = tid >> 5;
    const int lid = tid & 31;
    const int wr  = wid >> 1;
    const int wc  = wid & 1;

    const int nchunk = K >> 5;

    const int r0c = tid >> 3;
    const int kqc = tid & 7;
    const uint32_t csw = (uint32_t)(r0c & 7);
    const uint32_t cq_off = (uint32_t)((kqc ^ csw) << 4);
    const float* Abase = A  + (size_t)(blockIdx.y * 128 + r0c) * K + kqc * 4;
    const float* Bbase = Bt + (size_t)(blockIdx.x * 128 + r0c) * K + kqc * 4;

    auto issue = [&](int c, int s) {
        const uint32_t ab = smb + s * 32768 + r0c * 128 + cq_off;
        #pragma unroll
        for (int i = 0; i < 8; i++) {
            cpa16(ab + i * 2048,         Abase + (size_t)(16 * i) * K + c * 32);
            cpa16(ab + 16384 + i * 2048, Bbase + (size_t)(16 * i) * K + c * 32);
        }
    };

    const uint32_t a_row = (uint32_t)(wr * 64 + (lid & 15));
    const uint32_t a_kqb = (uint32_t)(lid >> 4);
    const uint32_t b_row = (uint32_t)(wc * 64 + (lid & 7) + ((lid >> 4) << 3));
    const uint32_t b_kqb = (uint32_t)((lid >> 3) & 1);
    const uint32_t l_sw  = (uint32_t)(lid & 7);

    float acc[4][8][4];
    #pragma unroll
    for (int i = 0; i < 4; i++)
        #pragma unroll
        for (int j = 0; j < 8; j++)
            #pragma unroll
            for (int r = 0; r < 4; r++) acc[i][j][r] = 0.0f;

    issue(0, 0); CP_COMMIT();
    issue(1, 1); CP_COMMIT();

    uint32_t afr[2][4][4];
    uint32_t bfr[2][4][4];

    for (int c = 0; c < nchunk; c++) {
        const int s = c % STAGES;
        CP_WAIT1();
        __syncthreads();

        const int cn = c + STAGES - 1;
        if (cn < nchunk) issue(cn, cn % STAGES);
        CP_COMMIT();

        const uint32_t abase = smb + s * 32768 + a_row * 128;
        const uint32_t bbase = smb + s * 32768 + 16384 + b_row * 128;

        #pragma unroll
        for (int mt = 0; mt < 4; mt++)
            ldsm_x4(afr[0][mt], abase + mt * 2048 + ((a_kqb ^ l_sw) << 4));
        #pragma unroll
        for (int np = 0; np < 4; np++)
            ldsm_x4(bfr[0][np], bbase + np * 2048 + ((b_kqb ^ l_sw) << 4));

        #pragma unroll
        for (int ks = 0; ks < 4; ks++) {
            const int cur = ks & 1, nxt = cur ^ 1;
            if (ks < 3) {
                const uint32_t kq_a = (uint32_t)(2 * (ks + 1)) + a_kqb;
                const uint32_t kq_b = (uint32_t)(2 * (ks + 1)) + b_kqb;
                #pragma unroll
                for (int mt = 0; mt < 4; mt++)
                    ldsm_x4(afr[nxt][mt], abase + mt * 2048 + ((kq_a ^ l_sw) << 4));
                #pragma unroll
                for (int np = 0; np < 4; np++)
                    ldsm_x4(bfr[nxt][np], bbase + np * 2048 + ((kq_b ^ l_sw) << 4));
            }
            #pragma unroll
            for (int mt = 0; mt < 4; mt++)
                #pragma unroll
                for (int nt = 0; nt < 8; nt++)
                    mma_tf32(acc[mt][nt], afr[cur][mt], &bfr[cur][nt >> 1][(nt & 1) * 2]);
        }
    }

    const int r0 = blockIdx.y * 128 + wr * 64 + (lid >> 2);
    const int c0 = blockIdx.x * 128 + wc * 64 + (lid & 3) * 2;
    #pragma unroll
    for (int mt = 0; mt < 4; mt++) {
        #pragma unroll
        for (int nt = 0; nt < 8; nt++) {
            int row = r0 + mt * 16;
            int col = c0 + nt * 8;
            float2 v0, v1;
            if (BIAS) {
                float b0 = bias[col], b1 = bias[col + 1];
                v0 = make_float2(acc[mt][nt][0] + b0, acc[mt][nt][1] + b1);
                v1 = make_float2(acc[mt][nt][2] + b0, acc[mt][nt][3] + b1);
            } else {
                v0 = make_float2(to_tf32(acc[mt][nt][0]), to_tf32(acc[mt][nt][1]));
                v1 = make_float2(to_tf32(acc[mt][nt][2]), to_tf32(acc[mt][nt][3]));
            }
            *(float2*)(C + (size_t)row * N + col)       = v0;
            *(float2*)(C + (size_t)(row + 8) * N + col) = v1;
        }
    }
}

// ---------------------------------------------------------------------------
// mma.sync flash attention, warp-split-K, cp.async double-buffered K/V.
// Q staged via cp.async + ldmatrix; QK accumulation split into even/odd
// chains (dependency depth 8 -> 4).
// Dynamic smem (floats): warp w at [w*4672, +4672):
//   KV stage s (s=0,1): +s*2176  (K 16x68 @ +0, V 16x68 @ +1088)
//   P tile:              +4352   (16 rows x stride 20)
//   epilogue reuse of stage0: O 16x66 @ +0, m @ +1056, l @ +1072
// list[NB] ints at float-offset 18688, wcnt[4] at 18816. Total 75280 bytes.
// ---------------------------------------------------------------------------
#define ATTN_SMEM 75280

__global__ void __launch_bounds__(128)
attn_mma(const float* __restrict__ qkv, const void* __restrict__ layout,
         float* __restrict__ att)
{
    extern __shared__ float asm_[];
    int* list = (int*)(asm_ + 18688);
    int* wcnt = (int*)(asm_ + 18816);

    const int qb = blockIdx.x, h = blockIdx.y, bz = blockIdx.z;
    const int tid = threadIdx.x;
    const int wid = tid >> 5;
    const int lid = tid & 31;
    const int r4  = lid >> 2;
    const int c4  = lid & 3;

    float* wbase = asm_ + wid * 4672;
    const uint32_t wbase_u = smem_u32(wbase);
    float* Ps = wbase + 4352;
    const uint32_t ps_u = wbase_u + 4352 * 4;

    const float* qkv_bz = qkv + (size_t)(bz * SEQ) * N3 + h * 64;

    // ---- stage Q into stage-1 K area (free until first prefetch) ----
    {
        const float* qg = qkv_bz + (size_t)(qb * 16) * N3;
        const uint32_t base = wbase_u + (uint32_t)2176 * 4;
        #pragma unroll
        for (int j = 0; j < 8; j++) {
            int f = lid + j * 32;
            int row = f >> 4, c16 = f & 15;
            cpa16(base + (uint32_t)(row * 68 + c16 * 4) * 4,
                  qg + (size_t)row * N3 + c16 * 4);
        }
    }
    CP_COMMIT();                       // group Q

    // ---- build allowed-block list (overlaps Q fetch) ----
    const int probe = __ldg(&((const int*)layout)[32]);
    const bool u8 = (probe == 257);
    const int kb0 = wid * 32 + lid;
    bool ok = (kb0 <= qb) &&
              (u8 ? (((const unsigned char*)layout)[qb * NB + kb0] != 0)
                  : (((const int*)layout)[qb * NB + kb0] != 0));
    unsigned bmask = __ballot_sync(0xffffffffu, ok);
    if (lid == 0) wcnt[wid] = __popc(bmask);
    __syncthreads();
    int pre = 0;
    #pragma unroll
    for (int w = 0; w < 4; w++) pre += (w < wid) ? wcnt[w] : 0;
    const int total = wcnt[0] + wcnt[1] + wcnt[2] + wcnt[3];
    if (ok) list[pre + __popc(bmask & ((1u << lid) - 1u))] = kb0;
    __syncthreads();

    // cp.async stage of block list[it]'s K/V into stage s (pre-rounded tf32)
    auto stage_kv = [&](int it, int s) {
        if (it >= total) return;
        const int kb = list[it];
        const float* kvb = qkv_bz + (size_t)(kb * 16) * N3;
        const uint32_t base = wbase_u + (uint32_t)(s * 2176) * 4;
        #pragma unroll
        for (int j = 0; j < 8; j++) {
            int f = lid + j * 32;
            int row = f >> 4, c16 = f & 15;
            uint32_t off = (uint32_t)(row * 68 + c16 * 4) * 4;
            cpa16(base + off,            kvb + (size_t)row * N3 + 1024 + c16 * 4);
            cpa16(base + 1088 * 4 + off, kvb + (size_t)row * N3 + 2048 + c16 * 4);
        }
    };

    stage_kv(wid, 0); CP_COMMIT();     // group KV0
    CP_WAIT1();                        // group Q complete
    __syncwarp();

    // ---- Q A-fragments via ldmatrix, scaled by exact 2^-3 ----
    const uint32_t q_off = (uint32_t)(lid & 15) * 272 + (uint32_t)(lid >> 4) * 16;
    uint32_t qa[8][4];
    #pragma unroll
    for (int ks = 0; ks < 8; ks++) {
        ldsm_x4(qa[ks], wbase_u + 2176u * 4 + q_off + ks * 32);
        #pragma unroll
        for (int r = 0; r < 4; r++)
            qa[ks][r] = __float_as_uint(__uint_as_float(qa[ks][r]) * 0.125f);
    }

    float o[8][4];
    #pragma unroll
    for (int nt = 0; nt < 8; nt++)
        #pragma unroll
        for (int r = 0; r < 4; r++) o[nt][r] = 0.0f;
    float m_lo = -INFINITY, m_hi = -INFINITY, l_lo = 0.0f, l_hi = 0.0f;

    // ldmatrix address components
    const uint32_t kb_off = (uint32_t)((lid & 7) + ((lid >> 4) << 3)) * 272
                          + (uint32_t)((lid >> 3) & 1) * 16;        // K as B-frags
    const uint32_t p_off  = (uint32_t)(lid & 15) * 80
                          + (uint32_t)(lid >> 4) * 16;              // P as A-frags

    int buf = 0;
    for (int it = wid; it < total; it += 4) {
        stage_kv(it + 4, buf ^ 1); CP_COMMIT();
        CP_WAIT1();
        __syncwarp();

        const int kb = list[it];
        const uint32_t kst = wbase_u + (uint32_t)(buf * 2176) * 4;
        float* Vs = wbase + buf * 2176 + 1088;

        // S = Q @ K^T : even/odd split accumulators (dep depth 4)
        float s0e[4] = {0.f, 0.f, 0.f, 0.f};
        float s0o[4] = {0.f, 0.f, 0.f, 0.f};
        float s1e[4] = {0.f, 0.f, 0.f, 0.f};
        float s1o[4] = {0.f, 0.f, 0.f, 0.f};
        #pragma unroll
        for (int ks = 0; ks < 8; ks += 2) {
            uint32_t kfr0[4], kfr1[4];
            ldsm_x4(kfr0, kst + kb_off + ks * 32);
            ldsm_x4(kfr1, kst + kb_off + (ks + 1) * 32);
            mma_tf32(s0e, qa[ks],     &kfr0[0]);
            mma_tf32(s1e, qa[ks],     &kfr0[2]);
            mma_tf32(s0o, qa[ks + 1], &kfr1[0]);
            mma_tf32(s1o, qa[ks + 1], &kfr1[2]);
        }
        float s0[4], s1[4];
        #pragma unroll
        for (int r = 0; r < 4; r++) {
            s0[r] = s0e[r] + s0o[r];
            s1[r] = s1e[r] + s1o[r];
        }

        if (kb == qb) {
            const int cA = 2 * c4, cB = 2 * c4 + 1;
            if (cA > r4)     s0[0] = -1e30f;
            if (cB > r4)     s0[1] = -1e30f;
            if (cA > r4 + 8) s0[2] = -1e30f;
            if (cB > r4 + 8) s0[3] = -1e30f;
            if (cA + 8 > r4)     s1[0] = -1e30f;
            if (cB + 8 > r4)     s1[1] = -1e30f;
            if (cA + 8 > r4 + 8) s1[2] = -1e30f;
            if (cB + 8 > r4 + 8) s1[3] = -1e30f;
        }

        float lo = fmaxf(fmaxf(s0[0], s0[1]), fmaxf(s1[0], s1[1]));
        float hi = fmaxf(fmaxf(s0[2], s0[3]), fmaxf(s1[2], s1[3]));
        lo = fmaxf(lo, __shfl_xor_sync(0xffffffffu, lo, 1));
        lo = fmaxf(lo, __shfl_xor_sync(0xffffffffu, lo, 2));
        hi = fmaxf(hi, __shfl_xor_sync(0xffffffffu, hi, 1));
        hi = fmaxf(hi, __shfl_xor_sync(0xffffffffu, hi, 2));

        const float mlo = fmaxf(m_lo, lo);
        const float mhi = fmaxf(m_hi, hi);
        const float alo = __expf(m_lo - mlo);
        const float ahi = __expf(m_hi - mhi);

        float p00 = __expf(s0[0] - mlo), p01 = __expf(s0[1] - mlo);
        float p10 = __expf(s1[0] - mlo), p11 = __expf(s1[1] - mlo);
        float p02 = __expf(s0[2] - mhi), p03 = __expf(s0[3] - mhi);
        float p12 = __expf(s1[2] - mhi), p13 = __expf(s1[3] - mhi);

        float slo = p00 + p01 + p10 + p11;
        float shi = p02 + p03 + p12 + p13;
        slo += __shfl_xor_sync(0xffffffffu, slo, 1);
        slo += __shfl_xor_sync(0xffffffffu, slo, 2);
        shi += __shfl_xor_sync(0xffffffffu, shi, 1);
        shi += __shfl_xor_sync(0xffffffffu, shi, 2);

        l_lo = l_lo * alo + slo;
        l_hi = l_hi * ahi + shi;
        m_lo = mlo; m_hi = mhi;

        #pragma unroll
        for (int nt = 0; nt < 8; nt++) {
            o[nt][0] *= alo; o[nt][1] *= alo;
            o[nt][2] *= ahi; o[nt][3] *= ahi;
        }

        *(float2*)&Ps[r4 * 20 + 2 * c4]           = make_float2(to_tf32(p00), to_tf32(p01));
        *(float2*)&Ps[r4 * 20 + 8 + 2 * c4]       = make_float2(to_tf32(p10), to_tf32(p11));
        *(float2*)&Ps[(r4 + 8) * 20 + 2 * c4]     = make_float2(to_tf32(p02), to_tf32(p03));
        *(float2*)&Ps[(r4 + 8) * 20 + 8 + 2 * c4] = make_float2(to_tf32(p12), to_tf32(p13));
        __syncwarp();

        uint32_t pa0[4], pa1[4];
        ldsm_x4(pa0, ps_u + p_off);
        ldsm_x4(pa1, ps_u + p_off + 32);

        #pragma unroll
        for (int nt = 0; nt < 8; nt++) {
            uint32_t b0[2], b1[2];
            b0[0] = __float_as_uint(Vs[c4 * 68 + nt * 8 + r4]);
            b0[1] = __float_as_uint(Vs[(c4 + 4) * 68 + nt * 8 + r4]);
            mma_tf32(o[nt], pa0, b0);
            b1[0] = __float_as_uint(Vs[(8 + c4) * 68 + nt * 8 + r4]);
            b1[1] = __float_as_uint(Vs[(12 + c4) * 68 + nt * 8 + r4]);
            mma_tf32(o[nt], pa1, b1);
        }
        __syncwarp();
        buf ^= 1;
    }

    // ---- write per-warp partials (reuse stage-0 region) ----
    float* Os = wbase;
    #pragma unroll
    for (int nt = 0; nt < 8; nt++) {
        *(float2*)&Os[r4 * 66 + nt * 8 + 2 * c4]       = make_float2(o[nt][0], o[nt][1]);
        *(float2*)&Os[(r4 + 8) * 66 + nt * 8 + 2 * c4] = make_float2(o[nt][2], o[nt][3]);
    }
    if (c4 == 0) {
        Os[1056 + r4]     = m_lo;
        Os[1056 + 8 + r4] = m_hi;
        Os[1072 + r4]     = l_lo;
        Os[1072 + 8 + r4] = l_hi;
    }
    __syncthreads();

    // ---- split-K combine ----
    {
        const int row = tid >> 3;
        const int d0  = (tid & 7) * 8;
        float mw[4], lw[4];
        float M = -INFINITY;
        #pragma unroll
        for (int w = 0; w < 4; w++) {
            mw[w] = asm_[w * 4672 + 1056 + row];
            lw[w] = asm_[w * 4672 + 1072 + row];
            M = fmaxf(M, mw[w]);
        }
        float L = 0.0f, wgt[4];
        #pragma unroll
        for (int w = 0; w < 4; w++) {
            wgt[w] = __expf(mw[w] - M);
            L += wgt[w] * lw[w];
        }
        const float inv = 1.0f / L;
        float out[8];
        #pragma unroll
        for (int j = 0; j < 8; j++) out[j] = 0.0f;
        #pragma unroll
        for (int w = 0; w < 4; w++) {
            const float g = wgt[w];
            const float* op = asm_ + w * 4672 + row * 66 + d0;
            #pragma unroll
            for (int j = 0; j < 8; j++) out[j] += g * op[j];
        }
        float* ap = att + (size_t)(bz * SEQ + qb * 16 + row) * DIM + h * 64 + d0;
        float4 v0 = make_float4(to_tf32(out[0] * inv), to_tf32(out[1] * inv),
                                to_tf32(out[2] * inv), to_tf32(out[3] * inv));
        float4 v1 = make_float4(to_tf32(out[4] * inv), to_tf32(out[5] * inv),
                                to_tf32(out[6] * inv), to_tf32(out[7] * inv));
        *(float4*)(ap)     = v0;
        *(float4*)(ap + 4) = v1;
    }
}

// ---------------------------------------------------------------------------
extern "C" void kernel_launch(void* const* d_in, const int* in_sizes, int n_in,
                              void* d_out, int out_size)
{
    const float* x      = (const float*)d_in[0];
    const float* w_qkv  = (const float*)d_in[1];
    const float* w_out  = (const float*)d_in[2];
    const float* b_out  = (const float*)d_in[3];
    const void*  layout = d_in[4];
    float* out = (float*)d_out;

    void* p;
    cudaGetSymbolAddress(&p, g_qkv);   float* qkv   = (float*)p;
    cudaGetSymbolAddress(&p, g_att);   float* att   = (float*)p;
    cudaGetSymbolAddress(&p, g_xr);    float* xr    = (float*)p;
    cudaGetSymbolAddress(&p, g_wqkvT); float* wqkvT = (float*)p;
    cudaGetSymbolAddress(&p, g_woutT); float* woutT = (float*)p;

    cudaFuncSetAttribute(gemm_sq<false>,
                         cudaFuncAttributeMaxDynamicSharedMemorySize, GEMM_SMEM);
    cudaFuncSetAttribute(gemm_sq<true>,
                         cudaFuncAttributeMaxDynamicSharedMemorySize, GEMM_SMEM);
    cudaFuncSetAttribute(attn_mma,
                         cudaFuncAttributeMaxDynamicSharedMemorySize, ATTN_SMEM);

    // 0) Preprocess: round x; transpose+round weights
    round_tf32<<<(MROWS * DIM / 4 + 255) / 256, 256>>>(x, xr, MROWS * DIM / 4);
    transpose_tf32<<<dim3(N3 / 32, DIM / 32), dim3(32, 8)>>>(w_qkv, wqkvT, DIM, N3);
    transpose_tf32<<<dim3(DIM / 32, DIM / 32), dim3(32, 8)>>>(w_out, woutT, DIM, DIM);

    // 1) QKV projection (output tf32-rounded)
    gemm_sq<false><<<dim3(N3 / 128, MROWS / 128), 128, GEMM_SMEM>>>(
        xr, wqkvT, nullptr, qkv, N3, DIM);

    // 2) Block-sparse flash attention (cp.async + ldmatrix, split chains)
    attn_mma<<<dim3(NB, HEADS, BATCH), 128, ATTN_SMEM>>>(qkv, layout, att);

    // 3) Output projection + bias
    gemm_sq<true><<<dim3(DIM / 128, MROWS / 128), 128, GEMM_SMEM>>>(
        att, woutT, b_out, out, DIM, DIM);
}

// round 14
// speedup vs baseline: 2.0963x; 1.0664x over previous
#include <cuda_runtime.h>
#include <math.h>
#include <stdint.h>

#define HEADS   16
#define DH      64
#define BLK     16
#define SEQ     2048
#define NB      128
#define BATCH   2
#define DIM     1024
#define N3      3072
#define MROWS   (BATCH * SEQ)   // 4096

// ---------------------------------------------------------------------------
// Scratch (device globals — no allocations anywhere)
// ---------------------------------------------------------------------------
__device__ float g_qkv[(size_t)MROWS * N3];    // 4096 x 3072 (tf32-rounded at write)
__device__ float g_att[(size_t)MROWS * DIM];   // 4096 x 1024 (tf32-rounded at write)
__device__ float g_xr[(size_t)MROWS * DIM];    // 4096 x 1024 (tf32-rounded x)
__device__ float g_wqkvT[(size_t)N3 * DIM];    // 3072 x 1024 (K-major, tf32-rounded)
__device__ float g_woutT[(size_t)DIM * DIM];   // 1024 x 1024

__device__ __forceinline__ float to_tf32(float x) {
    uint32_t u;
    asm("cvt.rna.tf32.f32 %0, %1;" : "=r"(u) : "f"(x));
    return __uint_as_float(u);
}

// mma.sync m16n8k8 tf32: D = A*B + D  (fp32 accum)
__device__ __forceinline__ void mma_tf32(float* c, const uint32_t* a, const uint32_t* b) {
    asm volatile(
        "mma.sync.aligned.m16n8k8.row.col.f32.tf32.tf32.f32 "
        "{%0,%1,%2,%3}, {%4,%5,%6,%7}, {%8,%9}, {%0,%1,%2,%3};"
        : "+f"(c[0]), "+f"(c[1]), "+f"(c[2]), "+f"(c[3])
        : "r"(a[0]), "r"(a[1]), "r"(a[2]), "r"(a[3]), "r"(b[0]), "r"(b[1]));
}

__device__ __forceinline__ uint32_t smem_u32(const void* p) {
    uint32_t a;
    asm("{ .reg .u64 t; cvta.to.shared.u64 t, %1; cvt.u32.u64 %0, t; }" : "=r"(a) : "l"(p));
    return a;
}
__device__ __forceinline__ void cpa16(uint32_t s, const void* g) {
    asm volatile("cp.async.cg.shared.global [%0], [%1], 16;" :: "r"(s), "l"(g));
}
#define CP_COMMIT() asm volatile("cp.async.commit_group;" ::: "memory")
#define CP_WAIT1()  asm volatile("cp.async.wait_group 1;" ::: "memory")
#define CP_WAIT2()  asm volatile("cp.async.wait_group 2;" ::: "memory")

__device__ __forceinline__ void ldsm_x4(uint32_t* r, uint32_t a) {
    asm volatile("ldmatrix.sync.aligned.m8n8.x4.shared.b16 {%0,%1,%2,%3}, [%4];"
                 : "=r"(r[0]), "=r"(r[1]), "=r"(r[2]), "=r"(r[3]) : "r"(a));
}

// ---------------------------------------------------------------------------
// Elementwise tf32 round (for x)
// ---------------------------------------------------------------------------
__global__ void __launch_bounds__(256)
round_tf32(const float* __restrict__ src, float* __restrict__ dst, int n4)
{
    int i = blockIdx.x * 256 + threadIdx.x;
    if (i < n4) {
        float4 v = ((const float4*)src)[i];
        v.x = to_tf32(v.x); v.y = to_tf32(v.y);
        v.z = to_tf32(v.z); v.w = to_tf32(v.w);
        ((float4*)dst)[i] = v;
    }
}

// ---------------------------------------------------------------------------
// Transpose + tf32 round: dst[C x R] = tf32(src[R x C])^T
// ---------------------------------------------------------------------------
__global__ void __launch_bounds__(256)
transpose_tf32(const float* __restrict__ src, float* __restrict__ dst, int R, int C)
{
    __shared__ float t[32][33];
    int c0 = blockIdx.x * 32, r0 = blockIdx.y * 32;
    int x = threadIdx.x, y = threadIdx.y;  // block (32, 8)
    #pragma unroll
    for (int i = 0; i < 32; i += 8)
        t[y + i][x] = to_tf32(src[(size_t)(r0 + y + i) * C + c0 + x]);
    __syncthreads();
    #pragma unroll
    for (int i = 0; i < 32; i += 8)
        dst[(size_t)(c0 + y + i) * R + r0 + x] = t[x][y + i];
}

// ---------------------------------------------------------------------------
// cp.async + ldmatrix tf32 GEMM (round-10 proven: 64x64 warp tiles).
// BIAS=false instance (QKV) tf32-rounds its output so attention needs no CVTs.
// ---------------------------------------------------------------------------
#define STAGES 3
#define GEMM_SMEM (STAGES * 32768)

template<bool BIAS>
__global__ void __launch_bounds__(128)
gemm_sq(const float* __restrict__ A, const float* __restrict__ Bt,
        const float* __restrict__ bias, float* __restrict__ C, int N, int K)
{
    extern __shared__ float sm[];
    const uint32_t smb = smem_u32(sm);

    const int tid = threadIdx.x;
    const int wid = tid >> 5;
    const int lid = tid & 31;
    const int wr  = wid >> 1;
    const int wc  = wid & 1;

    const int nchunk = K >> 5;

    const int r0c = tid >> 3;
    const int kqc = tid & 7;
    const uint32_t csw = (uint32_t)(r0c & 7);
    const uint32_t cq_off = (uint32_t)((kqc ^ csw) << 4);
    const float* Abase = A  + (size_t)(blockIdx.y * 128 + r0c) * K + kqc * 4;
    const float* Bbase = Bt + (size_t)(blockIdx.x * 128 + r0c) * K + kqc * 4;

    auto issue = [&](int c, int s) {
        const uint32_t ab = smb + s * 32768 + r0c * 128 + cq_off;
        #pragma unroll
        for (int i = 0; i < 8; i++) {
            cpa16(ab + i * 2048,         Abase + (size_t)(16 * i) * K + c * 32);
            cpa16(ab + 16384 + i * 2048, Bbase + (size_t)(16 * i) * K + c * 32);
        }
    };

    const uint32_t a_row = (uint32_t)(wr * 64 + (lid & 15));
    const uint32_t a_kqb = (uint32_t)(lid >> 4);
    const uint32_t b_row = (uint32_t)(wc * 64 + (lid & 7) + ((lid >> 4) << 3));
    const uint32_t b_kqb = (uint32_t)((lid >> 3) & 1);
    const uint32_t l_sw  = (uint32_t)(lid & 7);

    float acc[4][8][4];
    #pragma unroll
    for (int i = 0; i < 4; i++)
        #pragma unroll
        for (int j = 0; j < 8; j++)
            #pragma unroll
            for (int r = 0; r < 4; r++) acc[i][j][r] = 0.0f;

    issue(0, 0); CP_COMMIT();
    issue(1, 1); CP_COMMIT();

    uint32_t afr[2][4][4];
    uint32_t bfr[2][4][4];

    for (int c = 0; c < nchunk; c++) {
        const int s = c % STAGES;
        CP_WAIT1();
        __syncthreads();

        const int cn = c + STAGES - 1;
        if (cn < nchunk) issue(cn, cn % STAGES);
        CP_COMMIT();

        const uint32_t abase = smb + s * 32768 + a_row * 128;
        const uint32_t bbase = smb + s * 32768 + 16384 + b_row * 128;

        #pragma unroll
        for (int mt = 0; mt < 4; mt++)
            ldsm_x4(afr[0][mt], abase + mt * 2048 + ((a_kqb ^ l_sw) << 4));
        #pragma unroll
        for (int np = 0; np < 4; np++)
            ldsm_x4(bfr[0][np], bbase + np * 2048 + ((b_kqb ^ l_sw) << 4));

        #pragma unroll
        for (int ks = 0; ks < 4; ks++) {
            const int cur = ks & 1, nxt = cur ^ 1;
            if (ks < 3) {
                const uint32_t kq_a = (uint32_t)(2 * (ks + 1)) + a_kqb;
                const uint32_t kq_b = (uint32_t)(2 * (ks + 1)) + b_kqb;
                #pragma unroll
                for (int mt = 0; mt < 4; mt++)
                    ldsm_x4(afr[nxt][mt], abase + mt * 2048 + ((kq_a ^ l_sw) << 4));
                #pragma unroll
                for (int np = 0; np < 4; np++)
                    ldsm_x4(bfr[nxt][np], bbase + np * 2048 + ((kq_b ^ l_sw) << 4));
            }
            #pragma unroll
            for (int mt = 0; mt < 4; mt++)
                #pragma unroll
                for (int nt = 0; nt < 8; nt++)
                    mma_tf32(acc[mt][nt], afr[cur][mt], &bfr[cur][nt >> 1][(nt & 1) * 2]);
        }
    }

    const int r0 = blockIdx.y * 128 + wr * 64 + (lid >> 2);
    const int c0 = blockIdx.x * 128 + wc * 64 + (lid & 3) * 2;
    #pragma unroll
    for (int mt = 0; mt < 4; mt++) {
        #pragma unroll
        for (int nt = 0; nt < 8; nt++) {
            int row = r0 + mt * 16;
            int col = c0 + nt * 8;
            float2 v0, v1;
            if (BIAS) {
                float b0 = bias[col], b1 = bias[col + 1];
                v0 = make_float2(acc[mt][nt][0] + b0, acc[mt][nt][1] + b1);
                v1 = make_float2(acc[mt][nt][2] + b0, acc[mt][nt][3] + b1);
            } else {
                v0 = make_float2(to_tf32(acc[mt][nt][0]), to_tf32(acc[mt][nt][1]));
                v1 = make_float2(to_tf32(acc[mt][nt][2]), to_tf32(acc[mt][nt][3]));
            }
            *(float2*)(C + (size_t)row * N + col)       = v0;
            *(float2*)(C + (size_t)(row + 8) * N + col) = v1;
        }
    }
}

// ---------------------------------------------------------------------------
// mma.sync flash attention, warp-split-K. Compact smem for 4 CTAs/SM:
// per warp (3200 floats):
//   K stage s (s=0,1): +s*1024   (16 rows x 64, 16B XOR swizzle)
//   V (single stage):  +2048     (16 rows x stride 72; conflict-free reads)
//   P: reuses the just-consumed K stage (16 rows x stride 20)
//   Q staged through the V slot before V_0 is issued
//   epilogue reuse: O 16x66 @ +0, m @ +1056, l @ +1072
// list[NB] ints at float-offset 12800, wcnt[4] at 12928. Total 51728 bytes.
// cp.async groups per iter: [K_{i+1}] wait2 -> QK ; wait1 -> PV ; [V_{i+1}].
// ---------------------------------------------------------------------------
#define ATTN_SMEM 51728

__global__ void __launch_bounds__(128)
attn_mma(const float* __restrict__ qkv, const void* __restrict__ layout,
         float* __restrict__ att)
{
    extern __shared__ float asm_[];
    int* list = (int*)(asm_ + 12800);
    int* wcnt = (int*)(asm_ + 12928);

    const int qb = blockIdx.x, h = blockIdx.y, bz = blockIdx.z;
    const int tid = threadIdx.x;
    const int wid = tid >> 5;
    const int lid = tid & 31;
    const int r4  = lid >> 2;
    const int c4  = lid & 3;

    float* wbase = asm_ + wid * 3200;
    const uint32_t wbase_u = smem_u32(wbase);
    const uint32_t vbase_u = wbase_u + 2048u * 4;

    const float* qkv_bz = qkv + (size_t)(bz * SEQ) * N3 + h * 64;

    // ---- stage Q into the V slot (free until V_0 is issued) ----
    {
        const float* qg = qkv_bz + (size_t)(qb * 16) * N3;
        #pragma unroll
        for (int j = 0; j < 8; j++) {
            int f = lid + j * 32;
            int row = f >> 4, c16 = f & 15;
            uint32_t off = (uint32_t)row * 256 + ((uint32_t)(c16 ^ (row & 7)) << 4);
            cpa16(vbase_u + off, qg + (size_t)row * N3 + c16 * 4);
        }
    }
    CP_COMMIT();                       // group Q

    // ---- build allowed-block list (overlaps Q fetch) ----
    const int probe = __ldg(&((const int*)layout)[32]);
    const bool u8 = (probe == 257);
    const int kb0 = wid * 32 + lid;
    bool ok = (kb0 <= qb) &&
              (u8 ? (((const unsigned char*)layout)[qb * NB + kb0] != 0)
                  : (((const int*)layout)[qb * NB + kb0] != 0));
    unsigned bmask = __ballot_sync(0xffffffffu, ok);
    if (lid == 0) wcnt[wid] = __popc(bmask);
    __syncthreads();
    int pre = 0;
    #pragma unroll
    for (int w = 0; w < 4; w++) pre += (w < wid) ? wcnt[w] : 0;
    const int total = wcnt[0] + wcnt[1] + wcnt[2] + wcnt[3];
    if (ok) list[pre + __popc(bmask & ((1u << lid) - 1u))] = kb0;
    __syncthreads();

    // stage K of block list[it] into K stage s (swizzled stride-64)
    auto stage_k = [&](int it, int s) {
        if (it >= total) return;
        const float* kvb = qkv_bz + (size_t)(list[it] * 16) * N3 + 1024;
        const uint32_t base = wbase_u + (uint32_t)(s * 1024) * 4;
        #pragma unroll
        for (int j = 0; j < 8; j++) {
            int f = lid + j * 32;
            int row = f >> 4, c16 = f & 15;
            uint32_t off = (uint32_t)row * 256 + ((uint32_t)(c16 ^ (row & 7)) << 4);
            cpa16(base + off, kvb + (size_t)row * N3 + c16 * 4);
        }
    };
    // stage V of block list[it] (single buffer, stride 72 floats = 288 B)
    auto stage_v = [&](int it) {
        if (it >= total) return;
        const float* kvb = qkv_bz + (size_t)(list[it] * 16) * N3 + 2048;
        #pragma unroll
        for (int j = 0; j < 8; j++) {
            int f = lid + j * 32;
            int row = f >> 4, c16 = f & 15;
            cpa16(vbase_u + (uint32_t)(row * 288 + c16 * 16),
                  kvb + (size_t)row * N3 + c16 * 4);
        }
    };

    stage_k(wid, 0); CP_COMMIT();      // group K0
    CP_WAIT1();                        // Q complete (K0 may be pending)
    __syncwarp();

    // ---- Q A-fragments via ldmatrix (swizzled), scaled by exact 2^-3 ----
    uint32_t qa[8][4];
    {
        const uint32_t qrow = (uint32_t)(lid & 15);
        const uint32_t qb3  = (uint32_t)(lid >> 4);
        const uint32_t qro  = qrow * 256;
        const uint32_t qsw  = qrow & 7;
        #pragma unroll
        for (int ks = 0; ks < 8; ks++) {
            ldsm_x4(qa[ks], vbase_u + qro + ((((uint32_t)(2 * ks) + qb3) ^ qsw) << 4));
            #pragma unroll
            for (int r = 0; r < 4; r++)
                qa[ks][r] = __float_as_uint(__uint_as_float(qa[ks][r]) * 0.125f);
        }
    }
    __syncwarp();                      // all lanes done reading Q before V_0 lands
    stage_v(wid); CP_COMMIT();         // group V0

    float o[8][4];
    #pragma unroll
    for (int nt = 0; nt < 8; nt++)
        #pragma unroll
        for (int r = 0; r < 4; r++) o[nt][r] = 0.0f;
    float m_lo = -INFINITY, m_hi = -INFINITY, l_lo = 0.0f, l_hi = 0.0f;

    // ldmatrix address components
    const uint32_t krow_off = (uint32_t)((lid & 7) + ((lid >> 4) << 3)) * 256;
    const uint32_t k_qb     = (uint32_t)((lid >> 3) & 1);
    const uint32_t k_sw     = (uint32_t)(lid & 7);
    const uint32_t p_off    = (uint32_t)(lid & 15) * 80 + (uint32_t)(lid >> 4) * 16;

    float* Vs = wbase + 2048;
    int buf = 0;

    for (int it = wid; it < total; it += 4) {
        stage_k(it + 4, buf ^ 1); CP_COMMIT();   // K_{i+1}
        CP_WAIT2();                              // K_i ready (V_i, K_{i+1} pending)
        __syncwarp();

        const int kb = list[it];
        const uint32_t kst = wbase_u + (uint32_t)(buf * 1024) * 4;

        // S = Q @ K^T : even/odd split accumulators (dep depth 4)
        float s0e[4] = {0.f, 0.f, 0.f, 0.f};
        float s0o[4] = {0.f, 0.f, 0.f, 0.f};
        float s1e[4] = {0.f, 0.f, 0.f, 0.f};
        float s1o[4] = {0.f, 0.f, 0.f, 0.f};
        #pragma unroll
        for (int ks = 0; ks < 8; ks += 2) {
            uint32_t kfr0[4], kfr1[4];
            ldsm_x4(kfr0, kst + krow_off + ((((uint32_t)(2 * ks)     + k_qb) ^ k_sw) << 4));
            ldsm_x4(kfr1, kst + krow_off + ((((uint32_t)(2 * ks + 2) + k_qb) ^ k_sw) << 4));
            mma_tf32(s0e, qa[ks],     &kfr0[0]);
            mma_tf32(s1e, qa[ks],     &kfr0[2]);
            mma_tf32(s0o, qa[ks + 1], &kfr1[0]);
            mma_tf32(s1o, qa[ks + 1], &kfr1[2]);
        }
        float s0[4], s1[4];
        #pragma unroll
        for (int r = 0; r < 4; r++) {
            s0[r] = s0e[r] + s0o[r];
            s1[r] = s1e[r] + s1o[r];
        }

        if (kb == qb) {
            const int cA = 2 * c4, cB = 2 * c4 + 1;
            if (cA > r4)     s0[0] = -1e30f;
            if (cB > r4)     s0[1] = -1e30f;
            if (cA > r4 + 8) s0[2] = -1e30f;
            if (cB > r4 + 8) s0[3] = -1e30f;
            if (cA + 8 > r4)     s1[0] = -1e30f;
            if (cB + 8 > r4)     s1[1] = -1e30f;
            if (cA + 8 > r4 + 8) s1[2] = -1e30f;
            if (cB + 8 > r4 + 8) s1[3] = -1e30f;
        }

        float lo = fmaxf(fmaxf(s0[0], s0[1]), fmaxf(s1[0], s1[1]));
        float hi = fmaxf(fmaxf(s0[2], s0[3]), fmaxf(s1[2], s1[3]));
        lo = fmaxf(lo, __shfl_xor_sync(0xffffffffu, lo, 1));
        lo = fmaxf(lo, __shfl_xor_sync(0xffffffffu, lo, 2));
        hi = fmaxf(hi, __shfl_xor_sync(0xffffffffu, hi, 1));
        hi = fmaxf(hi, __shfl_xor_sync(0xffffffffu, hi, 2));

        const float mlo = fmaxf(m_lo, lo);
        const float mhi = fmaxf(m_hi, hi);
        const float alo = __expf(m_lo - mlo);
        const float ahi = __expf(m_hi - mhi);

        float p00 = __expf(s0[0] - mlo), p01 = __expf(s0[1] - mlo);
        float p10 = __expf(s1[0] - mlo), p11 = __expf(s1[1] - mlo);
        float p02 = __expf(s0[2] - mhi), p03 = __expf(s0[3] - mhi);
        float p12 = __expf(s1[2] - mhi), p13 = __expf(s1[3] - mhi);

        float slo = p00 + p01 + p10 + p11;
        float shi = p02 + p03 + p12 + p13;
        slo += __shfl_xor_sync(0xffffffffu, slo, 1);
        slo += __shfl_xor_sync(0xffffffffu, slo, 2);
        shi += __shfl_xor_sync(0xffffffffu, shi, 1);
        shi += __shfl_xor_sync(0xffffffffu, shi, 2);

        l_lo = l_lo * alo + slo;
        l_hi = l_hi * ahi + shi;
        m_lo = mlo; m_hi = mhi;

        #pragma unroll
        for (int nt = 0; nt < 8; nt++) {
            o[nt][0] *= alo; o[nt][1] *= alo;
            o[nt][2] *= ahi; o[nt][3] *= ahi;
        }

        // store P (tf32) into the just-consumed K stage (stride 20 floats)
        float* Ps = wbase + buf * 1024;
        *(float2*)&Ps[r4 * 20 + 2 * c4]           = make_float2(to_tf32(p00), to_tf32(p01));
        *(float2*)&Ps[r4 * 20 + 8 + 2 * c4]       = make_float2(to_tf32(p10), to_tf32(p11));
        *(float2*)&Ps[(r4 + 8) * 20 + 2 * c4]     = make_float2(to_tf32(p02), to_tf32(p03));
        *(float2*)&Ps[(r4 + 8) * 20 + 8 + 2 * c4] = make_float2(to_tf32(p12), to_tf32(p13));
        __syncwarp();

        uint32_t pa0[4], pa1[4];
        ldsm_x4(pa0, kst + p_off);
        ldsm_x4(pa1, kst + p_off + 32);

        CP_WAIT1();                              // V_i ready (K_{i+1} pending)
        __syncwarp();

        #pragma unroll
        for (int nt = 0; nt < 8; nt++) {
            uint32_t b0[2], b1[2];
            b0[0] = __float_as_uint(Vs[c4 * 72 + nt * 8 + r4]);
            b0[1] = __float_as_uint(Vs[(c4 + 4) * 72 + nt * 8 + r4]);
            mma_tf32(o[nt], pa0, b0);
            b1[0] = __float_as_uint(Vs[(8 + c4) * 72 + nt * 8 + r4]);
            b1[1] = __float_as_uint(Vs[(12 + c4) * 72 + nt * 8 + r4]);
            mma_tf32(o[nt], pa1, b1);
        }
        __syncwarp();
        stage_v(it + 4); CP_COMMIT();            // V_{i+1}
        buf ^= 1;
    }

    // ---- write per-warp partials (reuse warp area; trailing groups are empty) ----
    float* Os = wbase;
    #pragma unroll
    for (int nt = 0; nt < 8; nt++) {
        *(float2*)&Os[r4 * 66 + nt * 8 + 2 * c4]       = make_float2(o[nt][0], o[nt][1]);
        *(float2*)&Os[(r4 + 8) * 66 + nt * 8 + 2 * c4] = make_float2(o[nt][2], o[nt][3]);
    }
    if (c4 == 0) {
        Os[1056 + r4]     = m_lo;
        Os[1056 + 8 + r4] = m_hi;
        Os[1072 + r4]     = l_lo;
        Os[1072 + 8 + r4] = l_hi;
    }
    __syncthreads();

    // ---- split-K combine ----
    {
        const int row = tid >> 3;
        const int d0  = (tid & 7) * 8;
        float mw[4], lw[4];
        float M = -INFINITY;
        #pragma unroll
        for (int w = 0; w < 4; w++) {
            mw[w] = asm_[w * 3200 + 1056 + row];
            lw[w] = asm_[w * 3200 + 1072 + row];
            M = fmaxf(M, mw[w]);
        }
        float L = 0.0f, wgt[4];
        #pragma unroll
        for (int w = 0; w < 4; w++) {
            wgt[w] = __expf(mw[w] - M);
            L += wgt[w] * lw[w];
        }
        const float inv = 1.0f / L;
        float out[8];
        #pragma unroll
        for (int j = 0; j < 8; j++) out[j] = 0.0f;
        #pragma unroll
        for (int w = 0; w < 4; w++) {
            const float g = wgt[w];
            const float* op = asm_ + w * 3200 + row * 66 + d0;
            #pragma unroll
            for (int j = 0; j < 8; j++) out[j] += g * op[j];
        }
        float* ap = att + (size_t)(bz * SEQ + qb * 16 + row) * DIM + h * 64 + d0;
        float4 v0 = make_float4(to_tf32(out[0] * inv), to_tf32(out[1] * inv),
                                to_tf32(out[2] * inv), to_tf32(out[3] * inv));
        float4 v1 = make_float4(to_tf32(out[4] * inv), to_tf32(out[5] * inv),
                                to_tf32(out[6] * inv), to_tf32(out[7] * inv));
        *(float4*)(ap)     = v0;
        *(float4*)(ap + 4) = v1;
    }
}

// ---------------------------------------------------------------------------
extern "C" void kernel_launch(void* const* d_in, const int* in_sizes, int n_in,
                              void* d_out, int out_size)
{
    const float* x      = (const float*)d_in[0];
    const float* w_qkv  = (const float*)d_in[1];
    const float* w_out  = (const float*)d_in[2];
    const float* b_out  = (const float*)d_in[3];
    const void*  layout = d_in[4];
    float* out = (float*)d_out;

    void* p;
    cudaGetSymbolAddress(&p, g_qkv);   float* qkv   = (float*)p;
    cudaGetSymbolAddress(&p, g_att);   float* att   = (float*)p;
    cudaGetSymbolAddress(&p, g_xr);    float* xr    = (float*)p;
    cudaGetSymbolAddress(&p, g_wqkvT); float* wqkvT = (float*)p;
    cudaGetSymbolAddress(&p, g_woutT); float* woutT = (float*)p;

    cudaFuncSetAttribute(gemm_sq<false>,
                         cudaFuncAttributeMaxDynamicSharedMemorySize, GEMM_SMEM);
    cudaFuncSetAttribute(gemm_sq<true>,
                         cudaFuncAttributeMaxDynamicSharedMemorySize, GEMM_SMEM);
    cudaFuncSetAttribute(attn_mma,
                         cudaFuncAttributeMaxDynamicSharedMemorySize, ATTN_SMEM);

    // 0) Preprocess: round x; transpose+round weights
    round_tf32<<<(MROWS * DIM / 4 + 255) / 256, 256>>>(x, xr, MROWS * DIM / 4);
    transpose_tf32<<<dim3(N3 / 32, DIM / 32), dim3(32, 8)>>>(w_qkv, wqkvT, DIM, N3);
    transpose_tf32<<<dim3(DIM / 32, DIM / 32), dim3(32, 8)>>>(w_out, woutT, DIM, DIM);

    // 1) QKV projection (output tf32-rounded)
    gemm_sq<false><<<dim3(N3 / 128, MROWS / 128), 128, GEMM_SMEM>>>(
        xr, wqkvT, nullptr, qkv, N3, DIM);

    // 2) Block-sparse flash attention (compact smem, 4 CTAs/SM)
    attn_mma<<<dim3(NB, HEADS, BATCH), 128, ATTN_SMEM>>>(qkv, layout, att);

    // 3) Output projection + bias
    gemm_sq<true><<<dim3(DIM / 128, MROWS / 128), 128, GEMM_SMEM>>>(
        att, woutT, b_out, out, DIM, DIM);
}

// round 15
// speedup vs baseline: 2.9455x; 1.4051x over previous
#include <cuda_runtime.h>
#include <cuda_fp16.h>
#include <math.h>
#include <stdint.h>

#define HEADS   16
#define DH      64
#define BLK     16
#define SEQ     2048
#define NB      128
#define BATCH   2
#define DIM     1024
#define N3      3072
#define MROWS   (BATCH * SEQ)   // 4096

// ---------------------------------------------------------------------------
// Scratch (device globals — no allocations anywhere)
// ---------------------------------------------------------------------------
__device__ float  g_qkv[(size_t)MROWS * N3];    // fp32, tf32-rounded (attention)
__device__ __half g_att[(size_t)MROWS * DIM];   // attention out (proj A input)
__device__ __half g_xh[(size_t)MROWS * DIM];    // x rounded to fp16
__device__ __half g_wqkvT[(size_t)N3 * DIM];    // K-major fp16
__device__ __half g_woutT[(size_t)DIM * DIM];   // K-major fp16

__device__ __forceinline__ float to_tf32(float x) {
    uint32_t u;
    asm("cvt.rna.tf32.f32 %0, %1;" : "=r"(u) : "f"(x));
    return __uint_as_float(u);
}

// mma.sync m16n8k8 tf32 (attention)
__device__ __forceinline__ void mma_tf32(float* c, const uint32_t* a, const uint32_t* b) {
    asm volatile(
        "mma.sync.aligned.m16n8k8.row.col.f32.tf32.tf32.f32 "
        "{%0,%1,%2,%3}, {%4,%5,%6,%7}, {%8,%9}, {%0,%1,%2,%3};"
        : "+f"(c[0]), "+f"(c[1]), "+f"(c[2]), "+f"(c[3])
        : "r"(a[0]), "r"(a[1]), "r"(a[2]), "r"(a[3]), "r"(b[0]), "r"(b[1]));
}
// mma.sync m16n8k16 fp16, fp32 accumulate (GEMMs)
__device__ __forceinline__ void mma_f16(float* c, const uint32_t* a, const uint32_t* b) {
    asm volatile(
        "mma.sync.aligned.m16n8k16.row.col.f32.f16.f16.f32 "
        "{%0,%1,%2,%3}, {%4,%5,%6,%7}, {%8,%9}, {%0,%1,%2,%3};"
        : "+f"(c[0]), "+f"(c[1]), "+f"(c[2]), "+f"(c[3])
        : "r"(a[0]), "r"(a[1]), "r"(a[2]), "r"(a[3]), "r"(b[0]), "r"(b[1]));
}

__device__ __forceinline__ uint32_t smem_u32(const void* p) {
    uint32_t a;
    asm("{ .reg .u64 t; cvta.to.shared.u64 t, %1; cvt.u32.u64 %0, t; }" : "=r"(a) : "l"(p));
    return a;
}
__device__ __forceinline__ void cpa16(uint32_t s, const void* g) {
    asm volatile("cp.async.cg.shared.global [%0], [%1], 16;" :: "r"(s), "l"(g));
}
#define CP_COMMIT() asm volatile("cp.async.commit_group;" ::: "memory")
#define CP_WAIT1()  asm volatile("cp.async.wait_group 1;" ::: "memory")
#define CP_WAIT2()  asm volatile("cp.async.wait_group 2;" ::: "memory")

__device__ __forceinline__ void ldsm_x4(uint32_t* r, uint32_t a) {
    asm volatile("ldmatrix.sync.aligned.m8n8.x4.shared.b16 {%0,%1,%2,%3}, [%4];"
                 : "=r"(r[0]), "=r"(r[1]), "=r"(r[2]), "=r"(r[3]) : "r"(a));
}

// ---------------------------------------------------------------------------
// x -> fp16
// ---------------------------------------------------------------------------
__global__ void __launch_bounds__(256)
round_f16(const float* __restrict__ src, __half* __restrict__ dst, int n4)
{
    int i = blockIdx.x * 256 + threadIdx.x;
    if (i < n4) {
        float4 v = ((const float4*)src)[i];
        __half2 h0 = __floats2half2_rn(v.x, v.y);
        __half2 h1 = __floats2half2_rn(v.z, v.w);
        ((uint2*)dst)[i] = make_uint2(*(uint32_t*)&h0, *(uint32_t*)&h1);
    }
}

// ---------------------------------------------------------------------------
// Transpose + fp16 round: dst[C x R] = f16(src[R x C])^T
// ---------------------------------------------------------------------------
__global__ void __launch_bounds__(256)
transpose_f16(const float* __restrict__ src, __half* __restrict__ dst, int R, int C)
{
    __shared__ float t[32][33];
    int c0 = blockIdx.x * 32, r0 = blockIdx.y * 32;
    int x = threadIdx.x, y = threadIdx.y;  // block (32, 8)
    #pragma unroll
    for (int i = 0; i < 32; i += 8)
        t[y + i][x] = src[(size_t)(r0 + y + i) * C + c0 + x];
    __syncthreads();
    #pragma unroll
    for (int i = 0; i < 32; i += 8)
        dst[(size_t)(c0 + y + i) * R + r0 + x] = __float2half_rn(t[x][y + i]);
}

// ---------------------------------------------------------------------------
// fp16 GEMM (m16n8k16): C[f32] = A[f16] @ Bt[f16]^T (+bias | tf32-round).
// Same byte layout as the proven tf32 kernel: chunk = 128 B/row (64 halves),
// stage 32 KB, 3 stages, 64x64 warp tiles, ldmatrix fragments, identical
// swizzle.  MODE 0: tf32-round output (QKV). MODE 1: bias add (proj).
// ---------------------------------------------------------------------------
#define STAGES 3
#define GEMM_SMEM (STAGES * 32768)

template<int MODE>
__global__ void __launch_bounds__(128)
gemm_h(const __half* __restrict__ A, const __half* __restrict__ Bt,
       const float* __restrict__ bias, float* __restrict__ C, int N, int K)
{
    extern __shared__ float sm[];
    const uint32_t smb = smem_u32(sm);

    const int tid = threadIdx.x;
    const int wid = tid >> 5;
    const int lid = tid & 31;
    const int wr  = wid >> 1;
    const int wc  = wid & 1;

    const int nchunk = K >> 6;          // 64 halves per chunk

    const int r0c = tid >> 3;
    const int kqc = tid & 7;            // 16B quad = 8 halves
    const uint32_t csw = (uint32_t)(r0c & 7);
    const uint32_t cq_off = (uint32_t)((kqc ^ csw) << 4);
    const __half* Abase = A  + (size_t)(blockIdx.y * 128 + r0c) * K + kqc * 8;
    const __half* Bbase = Bt + (size_t)(blockIdx.x * 128 + r0c) * K + kqc * 8;

    auto issue = [&](int c, int s) {
        const uint32_t ab = smb + s * 32768 + r0c * 128 + cq_off;
        #pragma unroll
        for (int i = 0; i < 8; i++) {
            cpa16(ab + i * 2048,         Abase + (size_t)(16 * i) * K + c * 64);
            cpa16(ab + 16384 + i * 2048, Bbase + (size_t)(16 * i) * K + c * 64);
        }
    };

    const uint32_t a_row = (uint32_t)(wr * 64 + (lid & 15));
    const uint32_t a_kqb = (uint32_t)(lid >> 4);
    const uint32_t b_row = (uint32_t)(wc * 64 + (lid & 7) + ((lid >> 4) << 3));
    const uint32_t b_kqb = (uint32_t)((lid >> 3) & 1);
    const uint32_t l_sw  = (uint32_t)(lid & 7);

    float acc[4][8][4];
    #pragma unroll
    for (int i = 0; i < 4; i++)
        #pragma unroll
        for (int j = 0; j < 8; j++)
            #pragma unroll
            for (int r = 0; r < 4; r++) acc[i][j][r] = 0.0f;

    issue(0, 0); CP_COMMIT();
    issue(1, 1); CP_COMMIT();

    uint32_t afr[2][4][4];
    uint32_t bfr[2][4][4];

    for (int c = 0; c < nchunk; c++) {
        const int s = c % STAGES;
        CP_WAIT1();
        __syncthreads();

        const int cn = c + STAGES - 1;
        if (cn < nchunk) issue(cn, cn % STAGES);
        CP_COMMIT();

        const uint32_t abase = smb + s * 32768 + a_row * 128;
        const uint32_t bbase = smb + s * 32768 + 16384 + b_row * 128;

        #pragma unroll
        for (int mt = 0; mt < 4; mt++)
            ldsm_x4(afr[0][mt], abase + mt * 2048 + ((a_kqb ^ l_sw) << 4));
        #pragma unroll
        for (int np = 0; np < 4; np++)
            ldsm_x4(bfr[0][np], bbase + np * 2048 + ((b_kqb ^ l_sw) << 4));

        #pragma unroll
        for (int ks = 0; ks < 4; ks++) {        // k16 per step, 2 quads
            const int cur = ks & 1, nxt = cur ^ 1;
            if (ks < 3) {
                const uint32_t kq_a = (uint32_t)(2 * (ks + 1)) + a_kqb;
                const uint32_t kq_b = (uint32_t)(2 * (ks + 1)) + b_kqb;
                #pragma unroll
                for (int mt = 0; mt < 4; mt++)
                    ldsm_x4(afr[nxt][mt], abase + mt * 2048 + ((kq_a ^ l_sw) << 4));
                #pragma unroll
                for (int np = 0; np < 4; np++)
                    ldsm_x4(bfr[nxt][np], bbase + np * 2048 + ((kq_b ^ l_sw) << 4));
            }
            #pragma unroll
            for (int mt = 0; mt < 4; mt++)
                #pragma unroll
                for (int nt = 0; nt < 8; nt++)
                    mma_f16(acc[mt][nt], afr[cur][mt], &bfr[cur][nt >> 1][(nt & 1) * 2]);
        }
    }

    const int r0 = blockIdx.y * 128 + wr * 64 + (lid >> 2);
    const int c0 = blockIdx.x * 128 + wc * 64 + (lid & 3) * 2;
    #pragma unroll
    for (int mt = 0; mt < 4; mt++) {
        #pragma unroll
        for (int nt = 0; nt < 8; nt++) {
            int row = r0 + mt * 16;
            int col = c0 + nt * 8;
            float2 v0, v1;
            if (MODE == 1) {
                float b0 = bias[col], b1 = bias[col + 1];
                v0 = make_float2(acc[mt][nt][0] + b0, acc[mt][nt][1] + b1);
                v1 = make_float2(acc[mt][nt][2] + b0, acc[mt][nt][3] + b1);
            } else {
                v0 = make_float2(to_tf32(acc[mt][nt][0]), to_tf32(acc[mt][nt][1]));
                v1 = make_float2(to_tf32(acc[mt][nt][2]), to_tf32(acc[mt][nt][3]));
            }
            *(float2*)(C + (size_t)row * N + col)       = v0;
            *(float2*)(C + (size_t)(row + 8) * N + col) = v1;
        }
    }
}

// ---------------------------------------------------------------------------
// mma.sync flash attention (round-14 proven; epilogue now writes fp16)
// ---------------------------------------------------------------------------
#define ATTN_SMEM 51728

__global__ void __launch_bounds__(128)
attn_mma(const float* __restrict__ qkv, const void* __restrict__ layout,
         __half* __restrict__ att)
{
    extern __shared__ float asm_[];
    int* list = (int*)(asm_ + 12800);
    int* wcnt = (int*)(asm_ + 12928);

    const int qb = blockIdx.x, h = blockIdx.y, bz = blockIdx.z;
    const int tid = threadIdx.x;
    const int wid = tid >> 5;
    const int lid = tid & 31;
    const int r4  = lid >> 2;
    const int c4  = lid & 3;

    float* wbase = asm_ + wid * 3200;
    const uint32_t wbase_u = smem_u32(wbase);
    const uint32_t vbase_u = wbase_u + 2048u * 4;

    const float* qkv_bz = qkv + (size_t)(bz * SEQ) * N3 + h * 64;

    // stage Q into the V slot
    {
        const float* qg = qkv_bz + (size_t)(qb * 16) * N3;
        #pragma unroll
        for (int j = 0; j < 8; j++) {
            int f = lid + j * 32;
            int row = f >> 4, c16 = f & 15;
            uint32_t off = (uint32_t)row * 256 + ((uint32_t)(c16 ^ (row & 7)) << 4);
            cpa16(vbase_u + off, qg + (size_t)row * N3 + c16 * 4);
        }
    }
    CP_COMMIT();

    const int probe = __ldg(&((const int*)layout)[32]);
    const bool u8 = (probe == 257);
    const int kb0 = wid * 32 + lid;
    bool ok = (kb0 <= qb) &&
              (u8 ? (((const unsigned char*)layout)[qb * NB + kb0] != 0)
                  : (((const int*)layout)[qb * NB + kb0] != 0));
    unsigned bmask = __ballot_sync(0xffffffffu, ok);
    if (lid == 0) wcnt[wid] = __popc(bmask);
    __syncthreads();
    int pre = 0;
    #pragma unroll
    for (int w = 0; w < 4; w++) pre += (w < wid) ? wcnt[w] : 0;
    const int total = wcnt[0] + wcnt[1] + wcnt[2] + wcnt[3];
    if (ok) list[pre + __popc(bmask & ((1u << lid) - 1u))] = kb0;
    __syncthreads();

    auto stage_k = [&](int it, int s) {
        if (it >= total) return;
        const float* kvb = qkv_bz + (size_t)(list[it] * 16) * N3 + 1024;
        const uint32_t base = wbase_u + (uint32_t)(s * 1024) * 4;
        #pragma unroll
        for (int j = 0; j < 8; j++) {
            int f = lid + j * 32;
            int row = f >> 4, c16 = f & 15;
            uint32_t off = (uint32_t)row * 256 + ((uint32_t)(c16 ^ (row & 7)) << 4);
            cpa16(base + off, kvb + (size_t)row * N3 + c16 * 4);
        }
    };
    auto stage_v = [&](int it) {
        if (it >= total) return;
        const float* kvb = qkv_bz + (size_t)(list[it] * 16) * N3 + 2048;
        #pragma unroll
        for (int j = 0; j < 8; j++) {
            int f = lid + j * 32;
            int row = f >> 4, c16 = f & 15;
            cpa16(vbase_u + (uint32_t)(row * 288 + c16 * 16),
                  kvb + (size_t)row * N3 + c16 * 4);
        }
    };

    stage_k(wid, 0); CP_COMMIT();
    CP_WAIT1();
    __syncwarp();

    uint32_t qa[8][4];
    {
        const uint32_t qrow = (uint32_t)(lid & 15);
        const uint32_t qb3  = (uint32_t)(lid >> 4);
        const uint32_t qro  = qrow * 256;
        const uint32_t qsw  = qrow & 7;
        #pragma unroll
        for (int ks = 0; ks < 8; ks++) {
            ldsm_x4(qa[ks], vbase_u + qro + ((((uint32_t)(2 * ks) + qb3) ^ qsw) << 4));
            #pragma unroll
            for (int r = 0; r < 4; r++)
                qa[ks][r] = __float_as_uint(__uint_as_float(qa[ks][r]) * 0.125f);
        }
    }
    __syncwarp();
    stage_v(wid); CP_COMMIT();

    float o[8][4];
    #pragma unroll
    for (int nt = 0; nt < 8; nt++)
        #pragma unroll
        for (int r = 0; r < 4; r++) o[nt][r] = 0.0f;
    float m_lo = -INFINITY, m_hi = -INFINITY, l_lo = 0.0f, l_hi = 0.0f;

    const uint32_t krow_off = (uint32_t)((lid & 7) + ((lid >> 4) << 3)) * 256;
    const uint32_t k_qb     = (uint32_t)((lid >> 3) & 1);
    const uint32_t k_sw     = (uint32_t)(lid & 7);
    const uint32_t p_off    = (uint32_t)(lid & 15) * 80 + (uint32_t)(lid >> 4) * 16;

    float* Vs = wbase + 2048;
    int buf = 0;

    for (int it = wid; it < total; it += 4) {
        stage_k(it + 4, buf ^ 1); CP_COMMIT();
        CP_WAIT2();
        __syncwarp();

        const int kb = list[it];
        const uint32_t kst = wbase_u + (uint32_t)(buf * 1024) * 4;

        float s0e[4] = {0.f, 0.f, 0.f, 0.f};
        float s0o[4] = {0.f, 0.f, 0.f, 0.f};
        float s1e[4] = {0.f, 0.f, 0.f, 0.f};
        float s1o[4] = {0.f, 0.f, 0.f, 0.f};
        #pragma unroll
        for (int ks = 0; ks < 8; ks += 2) {
            uint32_t kfr0[4], kfr1[4];
            ldsm_x4(kfr0, kst + krow_off + ((((uint32_t)(2 * ks)     + k_qb) ^ k_sw) << 4));
            ldsm_x4(kfr1, kst + krow_off + ((((uint32_t)(2 * ks + 2) + k_qb) ^ k_sw) << 4));
            mma_tf32(s0e, qa[ks],     &kfr0[0]);
            mma_tf32(s1e, qa[ks],     &kfr0[2]);
            mma_tf32(s0o, qa[ks + 1], &kfr1[0]);
            mma_tf32(s1o, qa[ks + 1], &kfr1[2]);
        }
        float s0[4], s1[4];
        #pragma unroll
        for (int r = 0; r < 4; r++) {
            s0[r] = s0e[r] + s0o[r];
            s1[r] = s1e[r] + s1o[r];
        }

        if (kb == qb) {
            const int cA = 2 * c4, cB = 2 * c4 + 1;
            if (cA > r4)     s0[0] = -1e30f;
            if (cB > r4)     s0[1] = -1e30f;
            if (cA > r4 + 8) s0[2] = -1e30f;
            if (cB > r4 + 8) s0[3] = -1e30f;
            if (cA + 8 > r4)     s1[0] = -1e30f;
            if (cB + 8 > r4)     s1[1] = -1e30f;
            if (cA + 8 > r4 + 8) s1[2] = -1e30f;
            if (cB + 8 > r4 + 8) s1[3] = -1e30f;
        }

        float lo = fmaxf(fmaxf(s0[0], s0[1]), fmaxf(s1[0], s1[1]));
        float hi = fmaxf(fmaxf(s0[2], s0[3]), fmaxf(s1[2], s1[3]));
        lo = fmaxf(lo, __shfl_xor_sync(0xffffffffu, lo, 1));
        lo = fmaxf(lo, __shfl_xor_sync(0xffffffffu, lo, 2));
        hi = fmaxf(hi, __shfl_xor_sync(0xffffffffu, hi, 1));
        hi = fmaxf(hi, __shfl_xor_sync(0xffffffffu, hi, 2));

        const float mlo = fmaxf(m_lo, lo);
        const float mhi = fmaxf(m_hi, hi);
        const float alo = __expf(m_lo - mlo);
        const float ahi = __expf(m_hi - mhi);

        float p00 = __expf(s0[0] - mlo), p01 = __expf(s0[1] - mlo);
        float p10 = __expf(s1[0] - mlo), p11 = __expf(s1[1] - mlo);
        float p02 = __expf(s0[2] - mhi), p03 = __expf(s0[3] - mhi);
        float p12 = __expf(s1[2] - mhi), p13 = __expf(s1[3] - mhi);

        float slo = p00 + p01 + p10 + p11;
        float shi = p02 + p03 + p12 + p13;
        slo += __shfl_xor_sync(0xffffffffu, slo, 1);
        slo += __shfl_xor_sync(0xffffffffu, slo, 2);
        shi += __shfl_xor_sync(0xffffffffu, shi, 1);
        shi += __shfl_xor_sync(0xffffffffu, shi, 2);

        l_lo = l_lo * alo + slo;
        l_hi = l_hi * ahi + shi;
        m_lo = mlo; m_hi = mhi;

        #pragma unroll
        for (int nt = 0; nt < 8; nt++) {
            o[nt][0] *= alo; o[nt][1] *= alo;
            o[nt][2] *= ahi; o[nt][3] *= ahi;
        }

        float* Ps = wbase + buf * 1024;
        *(float2*)&Ps[r4 * 20 + 2 * c4]           = make_float2(to_tf32(p00), to_tf32(p01));
        *(float2*)&Ps[r4 * 20 + 8 + 2 * c4]       = make_float2(to_tf32(p10), to_tf32(p11));
        *(float2*)&Ps[(r4 + 8) * 20 + 2 * c4]     = make_float2(to_tf32(p02), to_tf32(p03));
        *(float2*)&Ps[(r4 + 8) * 20 + 8 + 2 * c4] = make_float2(to_tf32(p12), to_tf32(p13));
        __syncwarp();

        uint32_t pa0[4], pa1[4];
        ldsm_x4(pa0, kst + p_off);
        ldsm_x4(pa1, kst + p_off + 32);

        CP_WAIT1();
        __syncwarp();

        #pragma unroll
        for (int nt = 0; nt < 8; nt++) {
            uint32_t b0[2], b1[2];
            b0[0] = __float_as_uint(Vs[c4 * 72 + nt * 8 + r4]);
            b0[1] = __float_as_uint(Vs[(c4 + 4) * 72 + nt * 8 + r4]);
            mma_tf32(o[nt], pa0, b0);
            b1[0] = __float_as_uint(Vs[(8 + c4) * 72 + nt * 8 + r4]);
            b1[1] = __float_as_uint(Vs[(12 + c4) * 72 + nt * 8 + r4]);
            mma_tf32(o[nt], pa1, b1);
        }
        __syncwarp();
        stage_v(it + 4); CP_COMMIT();
        buf ^= 1;
    }

    float* Os = wbase;
    #pragma unroll
    for (int nt = 0; nt < 8; nt++) {
        *(float2*)&Os[r4 * 66 + nt * 8 + 2 * c4]       = make_float2(o[nt][0], o[nt][1]);
        *(float2*)&Os[(r4 + 8) * 66 + nt * 8 + 2 * c4] = make_float2(o[nt][2], o[nt][3]);
    }
    if (c4 == 0) {
        Os[1056 + r4]     = m_lo;
        Os[1056 + 8 + r4] = m_hi;
        Os[1072 + r4]     = l_lo;
        Os[1072 + 8 + r4] = l_hi;
    }
    __syncthreads();

    {
        const int row = tid >> 3;
        const int d0  = (tid & 7) * 8;
        float mw[4], lw[4];
        float M = -INFINITY;
        #pragma unroll
        for (int w = 0; w < 4; w++) {
            mw[w] = asm_[w * 3200 + 1056 + row];
            lw[w] = asm_[w * 3200 + 1072 + row];
            M = fmaxf(M, mw[w]);
        }
        float L = 0.0f, wgt[4];
        #pragma unroll
        for (int w = 0; w < 4; w++) {
            wgt[w] = __expf(mw[w] - M);
            L += wgt[w] * lw[w];
        }
        const float inv = 1.0f / L;
        float out[8];
        #pragma unroll
        for (int j = 0; j < 8; j++) out[j] = 0.0f;
        #pragma unroll
        for (int w = 0; w < 4; w++) {
            const float g = wgt[w];
            const float* op = asm_ + w * 3200 + row * 66 + d0;
            #pragma unroll
            for (int j = 0; j < 8; j++) out[j] += g * op[j];
        }
        __half* ap = att + (size_t)(bz * SEQ + qb * 16 + row) * DIM + h * 64 + d0;
        __half2 h0 = __floats2half2_rn(out[0] * inv, out[1] * inv);
        __half2 h1 = __floats2half2_rn(out[2] * inv, out[3] * inv);
        __half2 h2 = __floats2half2_rn(out[4] * inv, out[5] * inv);
        __half2 h3 = __floats2half2_rn(out[6] * inv, out[7] * inv);
        uint4 pk = make_uint4(*(uint32_t*)&h0, *(uint32_t*)&h1,
                              *(uint32_t*)&h2, *(uint32_t*)&h3);
        *(uint4*)ap = pk;
    }
}

// ---------------------------------------------------------------------------
extern "C" void kernel_launch(void* const* d_in, const int* in_sizes, int n_in,
                              void* d_out, int out_size)
{
    const float* x      = (const float*)d_in[0];
    const float* w_qkv  = (const float*)d_in[1];
    const float* w_out  = (const float*)d_in[2];
    const float* b_out  = (const float*)d_in[3];
    const void*  layout = d_in[4];
    float* out = (float*)d_out;

    void* p;
    cudaGetSymbolAddress(&p, g_qkv);   float*  qkv   = (float*)p;
    cudaGetSymbolAddress(&p, g_att);   __half* att   = (__half*)p;
    cudaGetSymbolAddress(&p, g_xh);    __half* xh    = (__half*)p;
    cudaGetSymbolAddress(&p, g_wqkvT); __half* wqkvT = (__half*)p;
    cudaGetSymbolAddress(&p, g_woutT); __half* woutT = (__half*)p;

    cudaFuncSetAttribute(gemm_h<0>,
                         cudaFuncAttributeMaxDynamicSharedMemorySize, GEMM_SMEM);
    cudaFuncSetAttribute(gemm_h<1>,
                         cudaFuncAttributeMaxDynamicSharedMemorySize, GEMM_SMEM);
    cudaFuncSetAttribute(attn_mma,
                         cudaFuncAttributeMaxDynamicSharedMemorySize, ATTN_SMEM);

    // 0) Preprocess: x -> fp16; weights -> K-major fp16
    round_f16<<<(MROWS * DIM / 4 + 255) / 256, 256>>>(x, xh, MROWS * DIM / 4);
    transpose_f16<<<dim3(N3 / 32, DIM / 32), dim3(32, 8)>>>(w_qkv, wqkvT, DIM, N3);
    transpose_f16<<<dim3(DIM / 32, DIM / 32), dim3(32, 8)>>>(w_out, woutT, DIM, DIM);

    // 1) QKV projection (fp16 MMA, fp32 accum, tf32-rounded output)
    gemm_h<0><<<dim3(N3 / 128, MROWS / 128), 128, GEMM_SMEM>>>(
        xh, wqkvT, nullptr, qkv, N3, DIM);

    // 2) Block-sparse flash attention (tf32; epilogue writes fp16)
    attn_mma<<<dim3(NB, HEADS, BATCH), 128, ATTN_SMEM>>>(qkv, layout, att);

    // 3) Output projection + bias (fp16 MMA, fp32 accum)
    gemm_h<1><<<dim3(DIM / 128, MROWS / 128), 128, GEMM_SMEM>>>(
        att, woutT, b_out, out, DIM, DIM);
}

// round 16
// speedup vs baseline: 3.3881x; 1.1503x over previous
#include <cuda_runtime.h>
#include <cuda_fp16.h>
#include <math.h>
#include <stdint.h>

#define HEADS   16
#define DH      64
#define BLK     16
#define SEQ     2048
#define NB      128
#define BATCH   2
#define DIM     1024
#define N3      3072
#define MROWS   (BATCH * SEQ)   // 4096

// ---------------------------------------------------------------------------
// Scratch (device globals — no allocations anywhere)
// ---------------------------------------------------------------------------
__device__ __half g_qkv[(size_t)MROWS * N3];    // fp16 qkv
__device__ __half g_att[(size_t)MROWS * DIM];   // attention out (proj A input)
__device__ __half g_xh[(size_t)MROWS * DIM];    // x rounded to fp16
__device__ __half g_wqkvT[(size_t)N3 * DIM];    // K-major fp16
__device__ __half g_woutT[(size_t)DIM * DIM];   // K-major fp16

// mma.sync m16n8k16 fp16, fp32 accumulate
__device__ __forceinline__ void mma_f16(float* c, const uint32_t* a, const uint32_t* b) {
    asm volatile(
        "mma.sync.aligned.m16n8k16.row.col.f32.f16.f16.f32 "
        "{%0,%1,%2,%3}, {%4,%5,%6,%7}, {%8,%9}, {%0,%1,%2,%3};"
        : "+f"(c[0]), "+f"(c[1]), "+f"(c[2]), "+f"(c[3])
        : "r"(a[0]), "r"(a[1]), "r"(a[2]), "r"(a[3]), "r"(b[0]), "r"(b[1]));
}

__device__ __forceinline__ uint32_t smem_u32(const void* p) {
    uint32_t a;
    asm("{ .reg .u64 t; cvta.to.shared.u64 t, %1; cvt.u32.u64 %0, t; }" : "=r"(a) : "l"(p));
    return a;
}
__device__ __forceinline__ void cpa16(uint32_t s, const void* g) {
    asm volatile("cp.async.cg.shared.global [%0], [%1], 16;" :: "r"(s), "l"(g));
}
#define CP_COMMIT() asm volatile("cp.async.commit_group;" ::: "memory")
#define CP_WAIT1()  asm volatile("cp.async.wait_group 1;" ::: "memory")
#define CP_WAIT2()  asm volatile("cp.async.wait_group 2;" ::: "memory")

__device__ __forceinline__ void ldsm_x4(uint32_t* r, uint32_t a) {
    asm volatile("ldmatrix.sync.aligned.m8n8.x4.shared.b16 {%0,%1,%2,%3}, [%4];"
                 : "=r"(r[0]), "=r"(r[1]), "=r"(r[2]), "=r"(r[3]) : "r"(a));
}
__device__ __forceinline__ void ldsm_x4_t(uint32_t* r, uint32_t a) {
    asm volatile("ldmatrix.sync.aligned.m8n8.x4.trans.shared.b16 {%0,%1,%2,%3}, [%4];"
                 : "=r"(r[0]), "=r"(r[1]), "=r"(r[2]), "=r"(r[3]) : "r"(a));
}

// ---------------------------------------------------------------------------
// x -> fp16
// ---------------------------------------------------------------------------
__global__ void __launch_bounds__(256)
round_f16(const float* __restrict__ src, __half* __restrict__ dst, int n4)
{
    int i = blockIdx.x * 256 + threadIdx.x;
    if (i < n4) {
        float4 v = ((const float4*)src)[i];
        __half2 h0 = __floats2half2_rn(v.x, v.y);
        __half2 h1 = __floats2half2_rn(v.z, v.w);
        ((uint2*)dst)[i] = make_uint2(*(uint32_t*)&h0, *(uint32_t*)&h1);
    }
}

// ---------------------------------------------------------------------------
// Transpose + fp16 round: dst[C x R] = f16(src[R x C])^T
// ---------------------------------------------------------------------------
__global__ void __launch_bounds__(256)
transpose_f16(const float* __restrict__ src, __half* __restrict__ dst, int R, int C)
{
    __shared__ float t[32][33];
    int c0 = blockIdx.x * 32, r0 = blockIdx.y * 32;
    int x = threadIdx.x, y = threadIdx.y;
    #pragma unroll
    for (int i = 0; i < 32; i += 8)
        t[y + i][x] = src[(size_t)(r0 + y + i) * C + c0 + x];
    __syncthreads();
    #pragma unroll
    for (int i = 0; i < 32; i += 8)
        dst[(size_t)(c0 + y + i) * R + r0 + x] = __float2half_rn(t[x][y + i]);
}

// ---------------------------------------------------------------------------
// fp16 GEMM (m16n8k16), round-15 proven. MODE 0: fp16 output (QKV).
// MODE 1: fp32 output + bias (projection).
// ---------------------------------------------------------------------------
#define STAGES 3
#define GEMM_SMEM (STAGES * 32768)

template<int MODE>
__global__ void __launch_bounds__(128)
gemm_h(const __half* __restrict__ A, const __half* __restrict__ Bt,
       const float* __restrict__ bias, float* __restrict__ Cf,
       __half* __restrict__ Ch, int N, int K)
{
    extern __shared__ float sm[];
    const uint32_t smb = smem_u32(sm);

    const int tid = threadIdx.x;
    const int wid = tid >> 5;
    const int lid = tid & 31;
    const int wr  = wid >> 1;
    const int wc  = wid & 1;

    const int nchunk = K >> 6;

    const int r0c = tid >> 3;
    const int kqc = tid & 7;
    const uint32_t csw = (uint32_t)(r0c & 7);
    const uint32_t cq_off = (uint32_t)((kqc ^ csw) << 4);
    const __half* Abase = A  + (size_t)(blockIdx.y * 128 + r0c) * K + kqc * 8;
    const __half* Bbase = Bt + (size_t)(blockIdx.x * 128 + r0c) * K + kqc * 8;

    auto issue = [&](int c, int s) {
        const uint32_t ab = smb + s * 32768 + r0c * 128 + cq_off;
        #pragma unroll
        for (int i = 0; i < 8; i++) {
            cpa16(ab + i * 2048,         Abase + (size_t)(16 * i) * K + c * 64);
            cpa16(ab + 16384 + i * 2048, Bbase + (size_t)(16 * i) * K + c * 64);
        }
    };

    const uint32_t a_row = (uint32_t)(wr * 64 + (lid & 15));
    const uint32_t a_kqb = (uint32_t)(lid >> 4);
    const uint32_t b_row = (uint32_t)(wc * 64 + (lid & 7) + ((lid >> 4) << 3));
    const uint32_t b_kqb = (uint32_t)((lid >> 3) & 1);
    const uint32_t l_sw  = (uint32_t)(lid & 7);

    float acc[4][8][4];
    #pragma unroll
    for (int i = 0; i < 4; i++)
        #pragma unroll
        for (int j = 0; j < 8; j++)
            #pragma unroll
            for (int r = 0; r < 4; r++) acc[i][j][r] = 0.0f;

    issue(0, 0); CP_COMMIT();
    issue(1, 1); CP_COMMIT();

    uint32_t afr[2][4][4];
    uint32_t bfr[2][4][4];

    for (int c = 0; c < nchunk; c++) {
        const int s = c % STAGES;
        CP_WAIT1();
        __syncthreads();

        const int cn = c + STAGES - 1;
        if (cn < nchunk) issue(cn, cn % STAGES);
        CP_COMMIT();

        const uint32_t abase = smb + s * 32768 + a_row * 128;
        const uint32_t bbase = smb + s * 32768 + 16384 + b_row * 128;

        #pragma unroll
        for (int mt = 0; mt < 4; mt++)
            ldsm_x4(afr[0][mt], abase + mt * 2048 + ((a_kqb ^ l_sw) << 4));
        #pragma unroll
        for (int np = 0; np < 4; np++)
            ldsm_x4(bfr[0][np], bbase + np * 2048 + ((b_kqb ^ l_sw) << 4));

        #pragma unroll
        for (int ks = 0; ks < 4; ks++) {
            const int cur = ks & 1, nxt = cur ^ 1;
            if (ks < 3) {
                const uint32_t kq_a = (uint32_t)(2 * (ks + 1)) + a_kqb;
                const uint32_t kq_b = (uint32_t)(2 * (ks + 1)) + b_kqb;
                #pragma unroll
                for (int mt = 0; mt < 4; mt++)
                    ldsm_x4(afr[nxt][mt], abase + mt * 2048 + ((kq_a ^ l_sw) << 4));
                #pragma unroll
                for (int np = 0; np < 4; np++)
                    ldsm_x4(bfr[nxt][np], bbase + np * 2048 + ((kq_b ^ l_sw) << 4));
            }
            #pragma unroll
            for (int mt = 0; mt < 4; mt++)
                #pragma unroll
                for (int nt = 0; nt < 8; nt++)
                    mma_f16(acc[mt][nt], afr[cur][mt], &bfr[cur][nt >> 1][(nt & 1) * 2]);
        }
    }

    const int r0 = blockIdx.y * 128 + wr * 64 + (lid >> 2);
    const int c0 = blockIdx.x * 128 + wc * 64 + (lid & 3) * 2;
    #pragma unroll
    for (int mt = 0; mt < 4; mt++) {
        #pragma unroll
        for (int nt = 0; nt < 8; nt++) {
            int row = r0 + mt * 16;
            int col = c0 + nt * 8;
            if (MODE == 1) {
                float b0 = bias[col], b1 = bias[col + 1];
                *(float2*)(Cf + (size_t)row * N + col) =
                    make_float2(acc[mt][nt][0] + b0, acc[mt][nt][1] + b1);
                *(float2*)(Cf + (size_t)(row + 8) * N + col) =
                    make_float2(acc[mt][nt][2] + b0, acc[mt][nt][3] + b1);
            } else {
                __half2 h0 = __floats2half2_rn(acc[mt][nt][0], acc[mt][nt][1]);
                __half2 h1 = __floats2half2_rn(acc[mt][nt][2], acc[mt][nt][3]);
                *(uint32_t*)(Ch + (size_t)row * N + col)       = *(uint32_t*)&h0;
                *(uint32_t*)(Ch + (size_t)(row + 8) * N + col) = *(uint32_t*)&h1;
            }
        }
    }
}

// ---------------------------------------------------------------------------
// fp16 flash attention, warp-split-K, cp.async K double-buffer + single V.
// Per-warp smem (bytes, base = wid*6912):
//   K0 @ +0 (2048), K1 @ +2048, V @ +4096 (2048, swizzled), P @ +6144 (16x48)
//   Q staged through V slot; epilogue: O 16x66 f32 @ +0, m @ +4224, l @ +4288
// list[NB] @ 27648, wcnt[4] @ 28160. Total 28176 bytes.
// ---------------------------------------------------------------------------
#define WARP_B    6912
#define ATTN_SMEM 28176

__global__ void __launch_bounds__(128)
attn_mma(const __half* __restrict__ qkv, const void* __restrict__ layout,
         __half* __restrict__ att)
{
    extern __shared__ char asmc[];
    int* list = (int*)(asmc + 27648);
    int* wcnt = (int*)(asmc + 28160);

    const int qb = blockIdx.x, h = blockIdx.y, bz = blockIdx.z;
    const int tid = threadIdx.x;
    const int wid = tid >> 5;
    const int lid = tid & 31;
    const int r4  = lid >> 2;
    const int c4  = lid & 3;

    char* wbase = asmc + wid * WARP_B;
    const uint32_t wb = smem_u32(wbase);
    const uint32_t vb = wb + 4096;
    const uint32_t pb = wb + 6144;

    const __half* qkv_bz = qkv + (size_t)(bz * SEQ) * N3 + h * 64;

    // ---- stage Q (fp16) into the V slot ----
    {
        const __half* qg = qkv_bz + (size_t)(qb * 16) * N3;
        #pragma unroll
        for (int j = 0; j < 4; j++) {
            int idx = lid + j * 32;
            int row = idx >> 3, q = idx & 7;
            cpa16(vb + row * 128 + ((uint32_t)(q ^ (row & 7)) << 4),
                  qg + (size_t)row * N3 + q * 8);
        }
    }
    CP_COMMIT();                        // group Q

    // ---- allowed-block list ----
    const int probe = __ldg(&((const int*)layout)[32]);
    const bool u8 = (probe == 257);
    const int kb0 = wid * 32 + lid;
    bool ok = (kb0 <= qb) &&
              (u8 ? (((const unsigned char*)layout)[qb * NB + kb0] != 0)
                  : (((const int*)layout)[qb * NB + kb0] != 0));
    unsigned bmask = __ballot_sync(0xffffffffu, ok);
    if (lid == 0) wcnt[wid] = __popc(bmask);
    __syncthreads();
    int pre = 0;
    #pragma unroll
    for (int w = 0; w < 4; w++) pre += (w < wid) ? wcnt[w] : 0;
    const int total = wcnt[0] + wcnt[1] + wcnt[2] + wcnt[3];
    if (ok) list[pre + __popc(bmask & ((1u << lid) - 1u))] = kb0;
    __syncthreads();

    auto stage_k = [&](int it, int s) {
        if (it >= total) return;
        const __half* kg = qkv_bz + (size_t)(list[it] * 16) * N3 + 1024;
        const uint32_t base = wb + (uint32_t)s * 2048;
        #pragma unroll
        for (int j = 0; j < 4; j++) {
            int idx = lid + j * 32;
            int row = idx >> 3, q = idx & 7;
            cpa16(base + row * 128 + ((uint32_t)(q ^ (row & 7)) << 4),
                  kg + (size_t)row * N3 + q * 8);
        }
    };
    auto stage_v = [&](int it) {
        if (it >= total) return;
        const __half* vg = qkv_bz + (size_t)(list[it] * 16) * N3 + 2048;
        #pragma unroll
        for (int j = 0; j < 4; j++) {
            int idx = lid + j * 32;
            int row = idx >> 3, q = idx & 7;
            cpa16(vb + row * 128 + ((uint32_t)(q ^ (row & 7)) << 4),
                  vg + (size_t)row * N3 + q * 8);
        }
    };

    stage_k(wid, 0); CP_COMMIT();       // group K0
    CP_WAIT1();                         // Q done
    __syncwarp();

    // ---- Q A-fragments (4 k16 steps), scale by exact 2^-3 ----
    uint32_t qa[4][4];
    {
        const uint32_t qrow = (uint32_t)(lid & 15);
        const uint32_t qq   = (uint32_t)(lid >> 4);
        const uint32_t qsw  = qrow & 7;
        const __half2 s8 = __float2half2_rn(0.125f);
        #pragma unroll
        for (int ks = 0; ks < 4; ks++) {
            ldsm_x4(qa[ks], vb + qrow * 128 + ((((uint32_t)(2 * ks) + qq) ^ qsw) << 4));
            #pragma unroll
            for (int r = 0; r < 4; r++) {
                __half2 v = *(__half2*)&qa[ks][r];
                v = __hmul2(v, s8);
                qa[ks][r] = *(uint32_t*)&v;
            }
        }
    }
    __syncwarp();
    stage_v(wid); CP_COMMIT();          // group V0

    float o[8][4];
    #pragma unroll
    for (int nt = 0; nt < 8; nt++)
        #pragma unroll
        for (int r = 0; r < 4; r++) o[nt][r] = 0.0f;
    float m_lo = -INFINITY, m_hi = -INFINITY, l_lo = 0.0f, l_hi = 0.0f;

    const uint32_t krow = (uint32_t)((lid & 7) + ((lid >> 4) << 3));
    const uint32_t kqb  = (uint32_t)((lid >> 3) & 1);
    const uint32_t ksw  = krow & 7;
    const uint32_t poff = (uint32_t)(lid & 15) * 48 + (uint32_t)(lid >> 4) * 16;
    const uint32_t vrow = (uint32_t)(lid & 15);
    const uint32_t vq   = (uint32_t)(lid >> 4);
    const uint32_t vsw  = vrow & 7;

    int buf = 0;

    for (int it = wid; it < total; it += 4) {
        stage_k(it + 4, buf ^ 1); CP_COMMIT();     // K_{i+1}
        CP_WAIT2();                                // K_i ready
        __syncwarp();

        const int kb = list[it];
        const uint32_t kst = wb + (uint32_t)buf * 2048;

        // S = Q @ K^T (even/odd chains)
        float s0e[4] = {0.f, 0.f, 0.f, 0.f};
        float s0o[4] = {0.f, 0.f, 0.f, 0.f};
        float s1e[4] = {0.f, 0.f, 0.f, 0.f};
        float s1o[4] = {0.f, 0.f, 0.f, 0.f};
        #pragma unroll
        for (int ks = 0; ks < 4; ks += 2) {
            uint32_t kfr0[4], kfr1[4];
            ldsm_x4(kfr0, kst + krow * 128 + ((((uint32_t)(2 * ks)     + kqb) ^ ksw) << 4));
            ldsm_x4(kfr1, kst + krow * 128 + ((((uint32_t)(2 * ks + 2) + kqb) ^ ksw) << 4));
            mma_f16(s0e, qa[ks],     &kfr0[0]);
            mma_f16(s1e, qa[ks],     &kfr0[2]);
            mma_f16(s0o, qa[ks + 1], &kfr1[0]);
            mma_f16(s1o, qa[ks + 1], &kfr1[2]);
        }
        float s0[4], s1[4];
        #pragma unroll
        for (int r = 0; r < 4; r++) {
            s0[r] = s0e[r] + s0o[r];
            s1[r] = s1e[r] + s1o[r];
        }

        if (kb == qb) {
            const int cA = 2 * c4, cB = 2 * c4 + 1;
            if (cA > r4)     s0[0] = -1e30f;
            if (cB > r4)     s0[1] = -1e30f;
            if (cA > r4 + 8) s0[2] = -1e30f;
            if (cB > r4 + 8) s0[3] = -1e30f;
            if (cA + 8 > r4)     s1[0] = -1e30f;
            if (cB + 8 > r4)     s1[1] = -1e30f;
            if (cA + 8 > r4 + 8) s1[2] = -1e30f;
            if (cB + 8 > r4 + 8) s1[3] = -1e30f;
        }

        float lo = fmaxf(fmaxf(s0[0], s0[1]), fmaxf(s1[0], s1[1]));
        float hi = fmaxf(fmaxf(s0[2], s0[3]), fmaxf(s1[2], s1[3]));
        lo = fmaxf(lo, __shfl_xor_sync(0xffffffffu, lo, 1));
        lo = fmaxf(lo, __shfl_xor_sync(0xffffffffu, lo, 2));
        hi = fmaxf(hi, __shfl_xor_sync(0xffffffffu, hi, 1));
        hi = fmaxf(hi, __shfl_xor_sync(0xffffffffu, hi, 2));

        const float mlo = fmaxf(m_lo, lo);
        const float mhi = fmaxf(m_hi, hi);
        const float alo = __expf(m_lo - mlo);
        const float ahi = __expf(m_hi - mhi);

        float p00 = __expf(s0[0] - mlo), p01 = __expf(s0[1] - mlo);
        float p10 = __expf(s1[0] - mlo), p11 = __expf(s1[1] - mlo);
        float p02 = __expf(s0[2] - mhi), p03 = __expf(s0[3] - mhi);
        float p12 = __expf(s1[2] - mhi), p13 = __expf(s1[3] - mhi);

        float slo = p00 + p01 + p10 + p11;
        float shi = p02 + p03 + p12 + p13;
        slo += __shfl_xor_sync(0xffffffffu, slo, 1);
        slo += __shfl_xor_sync(0xffffffffu, slo, 2);
        shi += __shfl_xor_sync(0xffffffffu, shi, 1);
        shi += __shfl_xor_sync(0xffffffffu, shi, 2);

        l_lo = l_lo * alo + slo;
        l_hi = l_hi * ahi + shi;
        m_lo = mlo; m_hi = mhi;

        #pragma unroll
        for (int nt = 0; nt < 8; nt++) {
            o[nt][0] *= alo; o[nt][1] *= alo;
            o[nt][2] *= ahi; o[nt][3] *= ahi;
        }

        // store P as fp16 (16 x 16, stride 48 B)
        {
            __half2 q0 = __floats2half2_rn(p00, p01);
            __half2 q1 = __floats2half2_rn(p10, p11);
            __half2 q2 = __floats2half2_rn(p02, p03);
            __half2 q3 = __floats2half2_rn(p12, p13);
            *(uint32_t*)(asmc + (pb - smem_u32(asmc)) + 0) = 0; // (no-op to keep layout obvious)
            uint32_t pbl = pb;
            *(uint32_t*)((char*)asmc + (pbl - smem_u32(asmc)) + r4 * 48 + c4 * 4)            = *(uint32_t*)&q0;
            *(uint32_t*)((char*)asmc + (pbl - smem_u32(asmc)) + r4 * 48 + 16 + c4 * 4)       = *(uint32_t*)&q1;
            *(uint32_t*)((char*)asmc + (pbl - smem_u32(asmc)) + (r4 + 8) * 48 + c4 * 4)      = *(uint32_t*)&q2;
            *(uint32_t*)((char*)asmc + (pbl - smem_u32(asmc)) + (r4 + 8) * 48 + 16 + c4 * 4) = *(uint32_t*)&q3;
        }
        __syncwarp();

        uint32_t pa[4];
        ldsm_x4(pa, pb + poff);

        CP_WAIT1();                                // V_i ready
        __syncwarp();

        #pragma unroll
        for (int np = 0; np < 4; np++) {
            uint32_t vfr[4];
            ldsm_x4_t(vfr, vb + vrow * 128 + (((vq + (uint32_t)(2 * np)) ^ vsw) << 4));
            mma_f16(o[2 * np],     pa, &vfr[0]);
            mma_f16(o[2 * np + 1], pa, &vfr[2]);
        }
        __syncwarp();
        stage_v(it + 4); CP_COMMIT();              // V_{i+1}
        buf ^= 1;
    }

    // ---- per-warp partials (fp32, reuse warp area) ----
    float* Os = (float*)wbase;
    #pragma unroll
    for (int nt = 0; nt < 8; nt++) {
        *(float2*)&Os[r4 * 66 + nt * 8 + 2 * c4]       = make_float2(o[nt][0], o[nt][1]);
        *(float2*)&Os[(r4 + 8) * 66 + nt * 8 + 2 * c4] = make_float2(o[nt][2], o[nt][3]);
    }
    if (c4 == 0) {
        Os[1056 + r4]     = m_lo;
        Os[1056 + 8 + r4] = m_hi;
        Os[1072 + r4]     = l_lo;
        Os[1072 + 8 + r4] = l_hi;
    }
    __syncthreads();

    // ---- split-K combine ----
    {
        const int row = tid >> 3;
        const int d0  = (tid & 7) * 8;
        float mw[4], lw[4];
        float M = -INFINITY;
        #pragma unroll
        for (int w = 0; w < 4; w++) {
            const float* wp = (const float*)(asmc + w * WARP_B);
            mw[w] = wp[1056 + row];
            lw[w] = wp[1072 + row];
            M = fmaxf(M, mw[w]);
        }
        float L = 0.0f, wgt[4];
        #pragma unroll
        for (int w = 0; w < 4; w++) {
            wgt[w] = __expf(mw[w] - M);
            L += wgt[w] * lw[w];
        }
        const float inv = 1.0f / L;
        float out[8];
        #pragma unroll
        for (int j = 0; j < 8; j++) out[j] = 0.0f;
        #pragma unroll
        for (int w = 0; w < 4; w++) {
            const float g = wgt[w];
            const float* op = (const float*)(asmc + w * WARP_B) + row * 66 + d0;
            #pragma unroll
            for (int j = 0; j < 8; j++) out[j] += g * op[j];
        }
        __half* ap = att + (size_t)(bz * SEQ + qb * 16 + row) * DIM + h * 64 + d0;
        __half2 h0 = __floats2half2_rn(out[0] * inv, out[1] * inv);
        __half2 h1 = __floats2half2_rn(out[2] * inv, out[3] * inv);
        __half2 h2 = __floats2half2_rn(out[4] * inv, out[5] * inv);
        __half2 h3 = __floats2half2_rn(out[6] * inv, out[7] * inv);
        *(uint4*)ap = make_uint4(*(uint32_t*)&h0, *(uint32_t*)&h1,
                                 *(uint32_t*)&h2, *(uint32_t*)&h3);
    }
}

// ---------------------------------------------------------------------------
extern "C" void kernel_launch(void* const* d_in, const int* in_sizes, int n_in,
                              void* d_out, int out_size)
{
    const float* x      = (const float*)d_in[0];
    const float* w_qkv  = (const float*)d_in[1];
    const float* w_out  = (const float*)d_in[2];
    const float* b_out  = (const float*)d_in[3];
    const void*  layout = d_in[4];
    float* out = (float*)d_out;

    void* p;
    cudaGetSymbolAddress(&p, g_qkv);   __half* qkv   = (__half*)p;
    cudaGetSymbolAddress(&p, g_att);   __half* att   = (__half*)p;
    cudaGetSymbolAddress(&p, g_xh);    __half* xh    = (__half*)p;
    cudaGetSymbolAddress(&p, g_wqkvT); __half* wqkvT = (__half*)p;
    cudaGetSymbolAddress(&p, g_woutT); __half* woutT = (__half*)p;

    cudaFuncSetAttribute(gemm_h<0>,
                         cudaFuncAttributeMaxDynamicSharedMemorySize, GEMM_SMEM);
    cudaFuncSetAttribute(gemm_h<1>,
                         cudaFuncAttributeMaxDynamicSharedMemorySize, GEMM_SMEM);
    cudaFuncSetAttribute(attn_mma,
                         cudaFuncAttributeMaxDynamicSharedMemorySize, ATTN_SMEM);

    // 0) Preprocess: x -> fp16; weights -> K-major fp16
    round_f16<<<(MROWS * DIM / 4 + 255) / 256, 256>>>(x, xh, MROWS * DIM / 4);
    transpose_f16<<<dim3(N3 / 32, DIM / 32), dim3(32, 8)>>>(w_qkv, wqkvT, DIM, N3);
    transpose_f16<<<dim3(DIM / 32, DIM / 32), dim3(32, 8)>>>(w_out, woutT, DIM, DIM);

    // 1) QKV projection (fp16 in/out, fp32 accum)
    gemm_h<0><<<dim3(N3 / 128, MROWS / 128), 128, GEMM_SMEM>>>(
        xh, wqkvT, nullptr, nullptr, qkv, N3, DIM);

    // 2) Block-sparse flash attention (fp16 MMA end-to-end)
    attn_mma<<<dim3(NB, HEADS, BATCH), 128, ATTN_SMEM>>>(qkv, layout, att);

    // 3) Output projection + bias (fp32 out)
    gemm_h<1><<<dim3(DIM / 128, MROWS / 128), 128, GEMM_SMEM>>>(
        att, woutT, b_out, out, nullptr, DIM, DIM);
}

// round 17
// speedup vs baseline: 3.5142x; 1.0372x over previous
#include <cuda_runtime.h>
#include <cuda_fp16.h>
#include <math.h>
#include <stdint.h>

#define HEADS   16
#define DH      64
#define BLK     16
#define SEQ     2048
#define NB      128
#define BATCH   2
#define DIM     1024
#define N3      3072
#define MROWS   (BATCH * SEQ)   // 4096

// ---------------------------------------------------------------------------
// Scratch (device globals — no allocations anywhere)
// ---------------------------------------------------------------------------
__device__ __half g_qkv[(size_t)MROWS * N3];    // fp16 qkv
__device__ __half g_att[(size_t)MROWS * DIM];   // attention out (proj A input)
__device__ __half g_xh[(size_t)MROWS * DIM];    // x rounded to fp16
__device__ __half g_wqkvT[(size_t)N3 * DIM];    // K-major fp16
__device__ __half g_woutT[(size_t)DIM * DIM];   // K-major fp16

// mma.sync m16n8k16 fp16, fp32 accumulate
__device__ __forceinline__ void mma_f16(float* c, const uint32_t* a, const uint32_t* b) {
    asm volatile(
        "mma.sync.aligned.m16n8k16.row.col.f32.f16.f16.f32 "
        "{%0,%1,%2,%3}, {%4,%5,%6,%7}, {%8,%9}, {%0,%1,%2,%3};"
        : "+f"(c[0]), "+f"(c[1]), "+f"(c[2]), "+f"(c[3])
        : "r"(a[0]), "r"(a[1]), "r"(a[2]), "r"(a[3]), "r"(b[0]), "r"(b[1]));
}

__device__ __forceinline__ uint32_t smem_u32(const void* p) {
    uint32_t a;
    asm("{ .reg .u64 t; cvta.to.shared.u64 t, %1; cvt.u32.u64 %0, t; }" : "=r"(a) : "l"(p));
    return a;
}
__device__ __forceinline__ void cpa16(uint32_t s, const void* g) {
    asm volatile("cp.async.cg.shared.global [%0], [%1], 16;" :: "r"(s), "l"(g));
}
#define CP_COMMIT() asm volatile("cp.async.commit_group;" ::: "memory")
#define CP_WAIT1()  asm volatile("cp.async.wait_group 1;" ::: "memory")
#define CP_WAIT2()  asm volatile("cp.async.wait_group 2;" ::: "memory")

__device__ __forceinline__ void ldsm_x4(uint32_t* r, uint32_t a) {
    asm volatile("ldmatrix.sync.aligned.m8n8.x4.shared.b16 {%0,%1,%2,%3}, [%4];"
                 : "=r"(r[0]), "=r"(r[1]), "=r"(r[2]), "=r"(r[3]) : "r"(a));
}
__device__ __forceinline__ void ldsm_x4_t(uint32_t* r, uint32_t a) {
    asm volatile("ldmatrix.sync.aligned.m8n8.x4.trans.shared.b16 {%0,%1,%2,%3}, [%4];"
                 : "=r"(r[0]), "=r"(r[1]), "=r"(r[2]), "=r"(r[3]) : "r"(a));
}

// ---------------------------------------------------------------------------
// x -> fp16
// ---------------------------------------------------------------------------
__global__ void __launch_bounds__(256)
round_f16(const float* __restrict__ src, __half* __restrict__ dst, int n4)
{
    int i = blockIdx.x * 256 + threadIdx.x;
    if (i < n4) {
        float4 v = ((const float4*)src)[i];
        __half2 h0 = __floats2half2_rn(v.x, v.y);
        __half2 h1 = __floats2half2_rn(v.z, v.w);
        ((uint2*)dst)[i] = make_uint2(*(uint32_t*)&h0, *(uint32_t*)&h1);
    }
}

// ---------------------------------------------------------------------------
// Transpose + fp16 round: dst[C x R] = f16(src[R x C])^T
// ---------------------------------------------------------------------------
__global__ void __launch_bounds__(256)
transpose_f16(const float* __restrict__ src, __half* __restrict__ dst, int R, int C)
{
    __shared__ float t[32][33];
    int c0 = blockIdx.x * 32, r0 = blockIdx.y * 32;
    int x = threadIdx.x, y = threadIdx.y;
    #pragma unroll
    for (int i = 0; i < 32; i += 8)
        t[y + i][x] = src[(size_t)(r0 + y + i) * C + c0 + x];
    __syncthreads();
    #pragma unroll
    for (int i = 0; i < 32; i += 8)
        dst[(size_t)(c0 + y + i) * R + r0 + x] = __float2half_rn(t[x][y + i]);
}

// ---------------------------------------------------------------------------
// fp16 GEMM (m16n8k16), round-15/16 proven. MODE 0: fp16 out (QKV).
// MODE 1: fp32 out + bias (projection).
// ---------------------------------------------------------------------------
#define STAGES 3
#define GEMM_SMEM (STAGES * 32768)

template<int MODE>
__global__ void __launch_bounds__(128)
gemm_h(const __half* __restrict__ A, const __half* __restrict__ Bt,
       const float* __restrict__ bias, float* __restrict__ Cf,
       __half* __restrict__ Ch, int N, int K)
{
    extern __shared__ float sm[];
    const uint32_t smb = smem_u32(sm);

    const int tid = threadIdx.x;
    const int wid = tid >> 5;
    const int lid = tid & 31;
    const int wr  = wid >> 1;
    const int wc  = wid & 1;

    const int nchunk = K >> 6;

    const int r0c = tid >> 3;
    const int kqc = tid & 7;
    const uint32_t csw = (uint32_t)(r0c & 7);
    const uint32_t cq_off = (uint32_t)((kqc ^ csw) << 4);
    const __half* Abase = A  + (size_t)(blockIdx.y * 128 + r0c) * K + kqc * 8;
    const __half* Bbase = Bt + (size_t)(blockIdx.x * 128 + r0c) * K + kqc * 8;

    auto issue = [&](int c, int s) {
        const uint32_t ab = smb + s * 32768 + r0c * 128 + cq_off;
        #pragma unroll
        for (int i = 0; i < 8; i++) {
            cpa16(ab + i * 2048,         Abase + (size_t)(16 * i) * K + c * 64);
            cpa16(ab + 16384 + i * 2048, Bbase + (size_t)(16 * i) * K + c * 64);
        }
    };

    const uint32_t a_row = (uint32_t)(wr * 64 + (lid & 15));
    const uint32_t a_kqb = (uint32_t)(lid >> 4);
    const uint32_t b_row = (uint32_t)(wc * 64 + (lid & 7) + ((lid >> 4) << 3));
    const uint32_t b_kqb = (uint32_t)((lid >> 3) & 1);
    const uint32_t l_sw  = (uint32_t)(lid & 7);

    float acc[4][8][4];
    #pragma unroll
    for (int i = 0; i < 4; i++)
        #pragma unroll
        for (int j = 0; j < 8; j++)
            #pragma unroll
            for (int r = 0; r < 4; r++) acc[i][j][r] = 0.0f;

    issue(0, 0); CP_COMMIT();
    issue(1, 1); CP_COMMIT();

    uint32_t afr[2][4][4];
    uint32_t bfr[2][4][4];

    for (int c = 0; c < nchunk; c++) {
        const int s = c % STAGES;
        CP_WAIT1();
        __syncthreads();

        const int cn = c + STAGES - 1;
        if (cn < nchunk) issue(cn, cn % STAGES);
        CP_COMMIT();

        const uint32_t abase = smb + s * 32768 + a_row * 128;
        const uint32_t bbase = smb + s * 32768 + 16384 + b_row * 128;

        #pragma unroll
        for (int mt = 0; mt < 4; mt++)
            ldsm_x4(afr[0][mt], abase + mt * 2048 + ((a_kqb ^ l_sw) << 4));
        #pragma unroll
        for (int np = 0; np < 4; np++)
            ldsm_x4(bfr[0][np], bbase + np * 2048 + ((b_kqb ^ l_sw) << 4));

        #pragma unroll
        for (int ks = 0; ks < 4; ks++) {
            const int cur = ks & 1, nxt = cur ^ 1;
            if (ks < 3) {
                const uint32_t kq_a = (uint32_t)(2 * (ks + 1)) + a_kqb;
                const uint32_t kq_b = (uint32_t)(2 * (ks + 1)) + b_kqb;
                #pragma unroll
                for (int mt = 0; mt < 4; mt++)
                    ldsm_x4(afr[nxt][mt], abase + mt * 2048 + ((kq_a ^ l_sw) << 4));
                #pragma unroll
                for (int np = 0; np < 4; np++)
                    ldsm_x4(bfr[nxt][np], bbase + np * 2048 + ((kq_b ^ l_sw) << 4));
            }
            #pragma unroll
            for (int mt = 0; mt < 4; mt++)
                #pragma unroll
                for (int nt = 0; nt < 8; nt++)
                    mma_f16(acc[mt][nt], afr[cur][mt], &bfr[cur][nt >> 1][(nt & 1) * 2]);
        }
    }

    const int r0 = blockIdx.y * 128 + wr * 64 + (lid >> 2);
    const int c0 = blockIdx.x * 128 + wc * 64 + (lid & 3) * 2;
    #pragma unroll
    for (int mt = 0; mt < 4; mt++) {
        #pragma unroll
        for (int nt = 0; nt < 8; nt++) {
            int row = r0 + mt * 16;
            int col = c0 + nt * 8;
            if (MODE == 1) {
                float b0 = bias[col], b1 = bias[col + 1];
                *(float2*)(Cf + (size_t)row * N + col) =
                    make_float2(acc[mt][nt][0] + b0, acc[mt][nt][1] + b1);
                *(float2*)(Cf + (size_t)(row + 8) * N + col) =
                    make_float2(acc[mt][nt][2] + b0, acc[mt][nt][3] + b1);
            } else {
                __half2 h0 = __floats2half2_rn(acc[mt][nt][0], acc[mt][nt][1]);
                __half2 h1 = __floats2half2_rn(acc[mt][nt][2], acc[mt][nt][3]);
                *(uint32_t*)(Ch + (size_t)row * N + col)       = *(uint32_t*)&h0;
                *(uint32_t*)(Ch + (size_t)(row + 8) * N + col) = *(uint32_t*)&h1;
            }
        }
    }
}

// ---------------------------------------------------------------------------
// fp16 flash attention, warp-split-K, PAIRED key blocks (32-key softmax).
// Per-warp smem (bytes, base = wid*13568):
//   K stage s (s=0,1): +s*4096  (pair: b0 @ +0, b1 @ +2048; swizzled rows)
//   V pair:            +8192    (4096; b0/b1 like K)   [Q staged here first]
//   P:                 +12288   (16 rows x 32 halves, stride 80 B)
//   epilogue reuse: O 16x66 f32 @ +0, m @ f32[1056], l @ f32[1072]
// list[NB] @ 54272, wcnt[4] @ 54784. Total 54800 bytes -> 4 CTAs/SM.
// cp.async groups/iter: [Kpair_{i+1}] wait2 -> QK ; wait1 -> PV ; [Vpair_{i+1}]
// ---------------------------------------------------------------------------
#define WARP_B    13568
#define ATTN_SMEM 54800

__global__ void __launch_bounds__(128)
attn_mma(const __half* __restrict__ qkv, const void* __restrict__ layout,
         __half* __restrict__ att)
{
    extern __shared__ char asmc[];
    int* list = (int*)(asmc + 54272);
    int* wcnt = (int*)(asmc + 54784);

    const int qb = blockIdx.x, h = blockIdx.y, bz = blockIdx.z;
    const int tid = threadIdx.x;
    const int wid = tid >> 5;
    const int lid = tid & 31;
    const int r4  = lid >> 2;
    const int c4  = lid & 3;

    char* wbase = asmc + wid * WARP_B;
    const uint32_t wb = smem_u32(wbase);
    const uint32_t vb = wb + 8192;
    const uint32_t pbs = wb + 12288;

    const __half* qkv_bz = qkv + (size_t)(bz * SEQ) * N3 + h * 64;

    // ---- stage Q (fp16) into the V slot ----
    {
        const __half* qg = qkv_bz + (size_t)(qb * 16) * N3;
        #pragma unroll
        for (int j = 0; j < 4; j++) {
            int idx = lid + j * 32;
            int row = idx >> 3, q = idx & 7;
            cpa16(vb + row * 128 + ((uint32_t)(q ^ (row & 7)) << 4),
                  qg + (size_t)row * N3 + q * 8);
        }
    }
    CP_COMMIT();                        // group Q

    // ---- allowed-block list ----
    const int probe = __ldg(&((const int*)layout)[32]);
    const bool u8 = (probe == 257);
    const int kb0i = wid * 32 + lid;
    bool ok = (kb0i <= qb) &&
              (u8 ? (((const unsigned char*)layout)[qb * NB + kb0i] != 0)
                  : (((const int*)layout)[qb * NB + kb0i] != 0));
    unsigned bmask = __ballot_sync(0xffffffffu, ok);
    if (lid == 0) wcnt[wid] = __popc(bmask);
    __syncthreads();
    int pre = 0;
    #pragma unroll
    for (int w = 0; w < 4; w++) pre += (w < wid) ? wcnt[w] : 0;
    const int total = wcnt[0] + wcnt[1] + wcnt[2] + wcnt[3];
    if (ok) list[pre + __popc(bmask & ((1u << lid) - 1u))] = kb0i;
    __syncthreads();

    // stage K pair of (list[it], list[it+1 clamped]) into stage s
    auto stage_kpair = [&](int it, int s) {
        if (it >= total) return;
        const int i1 = (it + 1 < total) ? it + 1 : it;
        const __half* g0 = qkv_bz + (size_t)(list[it] * 16) * N3 + 1024;
        const __half* g1 = qkv_bz + (size_t)(list[i1] * 16) * N3 + 1024;
        const uint32_t base = wb + (uint32_t)s * 4096;
        #pragma unroll
        for (int j = 0; j < 4; j++) {
            int idx = lid + j * 32;
            int row = idx >> 3, q = idx & 7;
            uint32_t off = row * 128 + ((uint32_t)(q ^ (row & 7)) << 4);
            cpa16(base + off,        g0 + (size_t)row * N3 + q * 8);
            cpa16(base + 2048 + off, g1 + (size_t)row * N3 + q * 8);
        }
    };
    auto stage_vpair = [&](int it) {
        if (it >= total) return;
        const int i1 = (it + 1 < total) ? it + 1 : it;
        const __half* g0 = qkv_bz + (size_t)(list[it] * 16) * N3 + 2048;
        const __half* g1 = qkv_bz + (size_t)(list[i1] * 16) * N3 + 2048;
        #pragma unroll
        for (int j = 0; j < 4; j++) {
            int idx = lid + j * 32;
            int row = idx >> 3, q = idx & 7;
            uint32_t off = row * 128 + ((uint32_t)(q ^ (row & 7)) << 4);
            cpa16(vb + off,        g0 + (size_t)row * N3 + q * 8);
            cpa16(vb + 2048 + off, g1 + (size_t)row * N3 + q * 8);
        }
    };

    const int it0 = wid * 2;
    stage_kpair(it0, 0); CP_COMMIT();   // group K0
    CP_WAIT1();                         // Q done
    __syncwarp();

    // ---- Q A-fragments (4 k16 steps), scale by exact 2^-3 ----
    uint32_t qa[4][4];
    {
        const uint32_t qrow = (uint32_t)(lid & 15);
        const uint32_t qq   = (uint32_t)(lid >> 4);
        const uint32_t qsw  = qrow & 7;
        const __half2 s8 = __float2half2_rn(0.125f);
        #pragma unroll
        for (int ks = 0; ks < 4; ks++) {
            ldsm_x4(qa[ks], vb + qrow * 128 + ((((uint32_t)(2 * ks) + qq) ^ qsw) << 4));
            #pragma unroll
            for (int r = 0; r < 4; r++) {
                __half2 v = *(__half2*)&qa[ks][r];
                v = __hmul2(v, s8);
                qa[ks][r] = *(uint32_t*)&v;
            }
        }
    }
    __syncwarp();
    stage_vpair(it0); CP_COMMIT();      // group V0

    float o[8][4];
    #pragma unroll
    for (int nt = 0; nt < 8; nt++)
        #pragma unroll
        for (int r = 0; r < 4; r++) o[nt][r] = 0.0f;
    float m_lo = -INFINITY, m_hi = -INFINITY, l_lo = 0.0f, l_hi = 0.0f;

    const uint32_t krow = (uint32_t)((lid & 7) + ((lid >> 4) << 3));
    const uint32_t kqb  = (uint32_t)((lid >> 3) & 1);
    const uint32_t ksw  = krow & 7;
    const uint32_t poff = (uint32_t)(lid & 15) * 80 + (uint32_t)(lid >> 4) * 16;
    const uint32_t vrow = (uint32_t)(lid & 15);
    const uint32_t vq   = (uint32_t)(lid >> 4);
    const uint32_t vsw  = vrow & 7;

    int buf = 0;

    for (int it = it0; it < total; it += 8) {
        stage_kpair(it + 8, buf ^ 1); CP_COMMIT();   // Kpair_{i+1}
        CP_WAIT2();                                  // Kpair_i ready
        __syncwarp();

        const int b0 = list[it];
        const bool v1 = (it + 1 < total);
        const int b1 = v1 ? list[it + 1] : -1;
        const uint32_t kst = wb + (uint32_t)buf * 4096;

        // S = Q @ [K0 K1]^T : four independent accumulator chains
        float s00[4] = {0.f, 0.f, 0.f, 0.f};   // b0, keys 0-7
        float s01[4] = {0.f, 0.f, 0.f, 0.f};   // b0, keys 8-15
        float s10[4] = {0.f, 0.f, 0.f, 0.f};   // b1, keys 0-7
        float s11[4] = {0.f, 0.f, 0.f, 0.f};   // b1, keys 8-15
        #pragma unroll
        for (int ks = 0; ks < 4; ks++) {
            uint32_t kf0[4], kf1[4];
            uint32_t qoff = ((((uint32_t)(2 * ks) + kqb) ^ ksw) << 4);
            ldsm_x4(kf0, kst + krow * 128 + qoff);
            ldsm_x4(kf1, kst + 2048 + krow * 128 + qoff);
            mma_f16(s00, qa[ks], &kf0[0]);
            mma_f16(s01, qa[ks], &kf0[2]);
            mma_f16(s10, qa[ks], &kf1[0]);
            mma_f16(s11, qa[ks], &kf1[2]);
        }

        // causal mask per block; invalid b1 fully masked
        {
            const int cA = 2 * c4, cB = 2 * c4 + 1;
            if (b0 == qb) {
                if (cA > r4)     s00[0] = -1e30f;
                if (cB > r4)     s00[1] = -1e30f;
                if (cA > r4 + 8) s00[2] = -1e30f;
                if (cB > r4 + 8) s00[3] = -1e30f;
                if (cA + 8 > r4)     s01[0] = -1e30f;
                if (cB + 8 > r4)     s01[1] = -1e30f;
                if (cA + 8 > r4 + 8) s01[2] = -1e30f;
                if (cB + 8 > r4 + 8) s01[3] = -1e30f;
            }
            if (!v1) {
                #pragma unroll
                for (int r = 0; r < 4; r++) { s10[r] = -1e30f; s11[r] = -1e30f; }
            } else if (b1 == qb) {
                if (cA > r4)     s10[0] = -1e30f;
                if (cB > r4)     s10[1] = -1e30f;
                if (cA > r4 + 8) s10[2] = -1e30f;
                if (cB > r4 + 8) s10[3] = -1e30f;
                if (cA + 8 > r4)     s11[0] = -1e30f;
                if (cB + 8 > r4)     s11[1] = -1e30f;
                if (cA + 8 > r4 + 8) s11[2] = -1e30f;
                if (cB + 8 > r4 + 8) s11[3] = -1e30f;
            }
        }

        // row max over 32 keys
        float lo = fmaxf(fmaxf(fmaxf(s00[0], s00[1]), fmaxf(s01[0], s01[1])),
                         fmaxf(fmaxf(s10[0], s10[1]), fmaxf(s11[0], s11[1])));
        float hi = fmaxf(fmaxf(fmaxf(s00[2], s00[3]), fmaxf(s01[2], s01[3])),
                         fmaxf(fmaxf(s10[2], s10[3]), fmaxf(s11[2], s11[3])));
        lo = fmaxf(lo, __shfl_xor_sync(0xffffffffu, lo, 1));
        lo = fmaxf(lo, __shfl_xor_sync(0xffffffffu, lo, 2));
        hi = fmaxf(hi, __shfl_xor_sync(0xffffffffu, hi, 1));
        hi = fmaxf(hi, __shfl_xor_sync(0xffffffffu, hi, 2));

        const float mlo = fmaxf(m_lo, lo);
        const float mhi = fmaxf(m_hi, hi);
        const float alo = __expf(m_lo - mlo);
        const float ahi = __expf(m_hi - mhi);

        float p000 = __expf(s00[0] - mlo), p001 = __expf(s00[1] - mlo);
        float p010 = __expf(s01[0] - mlo), p011 = __expf(s01[1] - mlo);
        float p100 = __expf(s10[0] - mlo), p101 = __expf(s10[1] - mlo);
        float p110 = __expf(s11[0] - mlo), p111 = __expf(s11[1] - mlo);
        float p002 = __expf(s00[2] - mhi), p003 = __expf(s00[3] - mhi);
        float p012 = __expf(s01[2] - mhi), p013 = __expf(s01[3] - mhi);
        float p102 = __expf(s10[2] - mhi), p103 = __expf(s10[3] - mhi);
        float p112 = __expf(s11[2] - mhi), p113 = __expf(s11[3] - mhi);

        float slo = (p000 + p001) + (p010 + p011) + (p100 + p101) + (p110 + p111);
        float shi = (p002 + p003) + (p012 + p013) + (p102 + p103) + (p112 + p113);
        slo += __shfl_xor_sync(0xffffffffu, slo, 1);
        slo += __shfl_xor_sync(0xffffffffu, slo, 2);
        shi += __shfl_xor_sync(0xffffffffu, shi, 1);
        shi += __shfl_xor_sync(0xffffffffu, shi, 2);

        l_lo = l_lo * alo + slo;
        l_hi = l_hi * ahi + shi;
        m_lo = mlo; m_hi = mhi;

        #pragma unroll
        for (int nt = 0; nt < 8; nt++) {
            o[nt][0] *= alo; o[nt][1] *= alo;
            o[nt][2] *= ahi; o[nt][3] *= ahi;
        }

        // store P (16 x 32 fp16, stride 80 B): b0 cols 0-15, b1 cols 16-31
        {
            __half2 q00 = __floats2half2_rn(p000, p001);
            __half2 q01 = __floats2half2_rn(p010, p011);
            __half2 q10 = __floats2half2_rn(p100, p101);
            __half2 q11 = __floats2half2_rn(p110, p111);
            __half2 q02 = __floats2half2_rn(p002, p003);
            __half2 q03 = __floats2half2_rn(p012, p013);
            __half2 q12 = __floats2half2_rn(p102, p103);
            __half2 q13 = __floats2half2_rn(p112, p113);
            char* pp = (char*)wbase + 12288;
            *(uint32_t*)(pp + r4 * 80 + c4 * 4)            = *(uint32_t*)&q00;
            *(uint32_t*)(pp + r4 * 80 + 16 + c4 * 4)       = *(uint32_t*)&q01;
            *(uint32_t*)(pp + r4 * 80 + 32 + c4 * 4)       = *(uint32_t*)&q10;
            *(uint32_t*)(pp + r4 * 80 + 48 + c4 * 4)       = *(uint32_t*)&q11;
            *(uint32_t*)(pp + (r4 + 8) * 80 + c4 * 4)      = *(uint32_t*)&q02;
            *(uint32_t*)(pp + (r4 + 8) * 80 + 16 + c4 * 4) = *(uint32_t*)&q03;
            *(uint32_t*)(pp + (r4 + 8) * 80 + 32 + c4 * 4) = *(uint32_t*)&q12;
            *(uint32_t*)(pp + (r4 + 8) * 80 + 48 + c4 * 4) = *(uint32_t*)&q13;
        }
        __syncwarp();

        uint32_t pa0[4], pa1[4];                      // P_b0, P_b1 A-frags
        ldsm_x4(pa0, pbs + poff);
        ldsm_x4(pa1, pbs + poff + 32);

        CP_WAIT1();                                   // Vpair_i ready
        __syncwarp();

        #pragma unroll
        for (int np = 0; np < 4; np++) {
            uint32_t vf0[4], vf1[4];
            uint32_t voff = (((vq + (uint32_t)(2 * np)) ^ vsw) << 4);
            ldsm_x4_t(vf0, vb + vrow * 128 + voff);
            ldsm_x4_t(vf1, vb + 2048 + vrow * 128 + voff);
            mma_f16(o[2 * np],     pa0, &vf0[0]);
            mma_f16(o[2 * np],     pa1, &vf1[0]);
            mma_f16(o[2 * np + 1], pa0, &vf0[2]);
            mma_f16(o[2 * np + 1], pa1, &vf1[2]);
        }
        __syncwarp();
        stage_vpair(it + 8); CP_COMMIT();             // Vpair_{i+1}
        buf ^= 1;
    }

    // ---- per-warp partials (fp32, reuse warp area) ----
    float* Os = (float*)wbase;
    #pragma unroll
    for (int nt = 0; nt < 8; nt++) {
        *(float2*)&Os[r4 * 66 + nt * 8 + 2 * c4]       = make_float2(o[nt][0], o[nt][1]);
        *(float2*)&Os[(r4 + 8) * 66 + nt * 8 + 2 * c4] = make_float2(o[nt][2], o[nt][3]);
    }
    if (c4 == 0) {
        Os[1056 + r4]     = m_lo;
        Os[1056 + 8 + r4] = m_hi;
        Os[1072 + r4]     = l_lo;
        Os[1072 + 8 + r4] = l_hi;
    }
    __syncthreads();

    // ---- split-K combine ----
    {
        const int row = tid >> 3;
        const int d0  = (tid & 7) * 8;
        float mw[4], lw[4];
        float M = -INFINITY;
        #pragma unroll
        for (int w = 0; w < 4; w++) {
            const float* wp = (const float*)(asmc + w * WARP_B);
            mw[w] = wp[1056 + row];
            lw[w] = wp[1072 + row];
            M = fmaxf(M, mw[w]);
        }
        float L = 0.0f, wgt[4];
        #pragma unroll
        for (int w = 0; w < 4; w++) {
            wgt[w] = __expf(mw[w] - M);
            L += wgt[w] * lw[w];
        }
        const float inv = 1.0f / L;
        float out[8];
        #pragma unroll
        for (int j = 0; j < 8; j++) out[j] = 0.0f;
        #pragma unroll
        for (int w = 0; w < 4; w++) {
            const float g = wgt[w];
            const float* op = (const float*)(asmc + w * WARP_B) + row * 66 + d0;
            #pragma unroll
            for (int j = 0; j < 8; j++) out[j] += g * op[j];
        }
        __half* ap = att + (size_t)(bz * SEQ + qb * 16 + row) * DIM + h * 64 + d0;
        __half2 h0 = __floats2half2_rn(out[0] * inv, out[1] * inv);
        __half2 h1 = __floats2half2_rn(out[2] * inv, out[3] * inv);
        __half2 h2 = __floats2half2_rn(out[4] * inv, out[5] * inv);
        __half2 h3 = __floats2half2_rn(out[6] * inv, out[7] * inv);
        *(uint4*)ap = make_uint4(*(uint32_t*)&h0, *(uint32_t*)&h1,
                                 *(uint32_t*)&h2, *(uint32_t*)&h3);
    }
}

// ---------------------------------------------------------------------------
extern "C" void kernel_launch(void* const* d_in, const int* in_sizes, int n_in,
                              void* d_out, int out_size)
{
    const float* x      = (const float*)d_in[0];
    const float* w_qkv  = (const float*)d_in[1];
    const float* w_out  = (const float*)d_in[2];
    const float* b_out  = (const float*)d_in[3];
    const void*  layout = d_in[4];
    float* out = (float*)d_out;

    void* p;
    cudaGetSymbolAddress(&p, g_qkv);   __half* qkv   = (__half*)p;
    cudaGetSymbolAddress(&p, g_att);   __half* att   = (__half*)p;
    cudaGetSymbolAddress(&p, g_xh);    __half* xh    = (__half*)p;
    cudaGetSymbolAddress(&p, g_wqkvT); __half* wqkvT = (__half*)p;
    cudaGetSymbolAddress(&p, g_woutT); __half* woutT = (__half*)p;

    cudaFuncSetAttribute(gemm_h<0>,
                         cudaFuncAttributeMaxDynamicSharedMemorySize, GEMM_SMEM);
    cudaFuncSetAttribute(gemm_h<1>,
                         cudaFuncAttributeMaxDynamicSharedMemorySize, GEMM_SMEM);
    cudaFuncSetAttribute(attn_mma,
                         cudaFuncAttributeMaxDynamicSharedMemorySize, ATTN_SMEM);

    // 0) Preprocess: x -> fp16; weights -> K-major fp16
    round_f16<<<(MROWS * DIM / 4 + 255) / 256, 256>>>(x, xh, MROWS * DIM / 4);
    transpose_f16<<<dim3(N3 / 32, DIM / 32), dim3(32, 8)>>>(w_qkv, wqkvT, DIM, N3);
    transpose_f16<<<dim3(DIM / 32, DIM / 32), dim3(32, 8)>>>(w_out, woutT, DIM, DIM);

    // 1) QKV projection (fp16 in/out, fp32 accum)
    gemm_h<0><<<dim3(N3 / 128, MROWS / 128), 128, GEMM_SMEM>>>(
        xh, wqkvT, nullptr, nullptr, qkv, N3, DIM);

    // 2) Block-sparse flash attention (fp16, paired key blocks)
    attn_mma<<<dim3(NB, HEADS, BATCH), 128, ATTN_SMEM>>>(qkv, layout, att);

    // 3) Output projection + bias (fp32 out)
    gemm_h<1><<<dim3(DIM / 128, MROWS / 128), 128, GEMM_SMEM>>>(
        att, woutT, b_out, out, nullptr, DIM, DIM);
}